// round 1
// baseline (speedup 1.0000x reference)
#include <cuda_runtime.h>
#include <math.h>

#define BSZ   2
#define SEQ   2048
#define DM    1024
#define NH    16
#define DK    64
#define RELN  (2*SEQ-1)   // 4095

// ---------------- scratch (device globals: no allocation allowed) ----------
__device__ float g_q[BSZ*NH*SEQ*DK];     // [b][h][s][d]
__device__ float g_k[BSZ*NH*SEQ*DK];
__device__ float g_v[BSZ*NH*SEQ*DK];
__device__ float g_attn[BSZ*SEQ*DM];     // [b*S+s][h*64+d]
__device__ float g_bias[NH*RELN];        // [h][rel + S-1]

// ---------------- relative-position bias precompute -------------------------
__global__ void bias_kernel(const float* __restrict__ table) {
    int idx = blockIdx.x * blockDim.x + threadIdx.x;
    if (idx >= RELN) return;
    int rel = idx - (SEQ - 1);            // mem - ctx
    int bucket = (rel > 0) ? 16 : 0;
    int rabs = rel < 0 ? -rel : rel;
    int add;
    if (rabs < 8) {
        add = rabs;
    } else {
        double lf = log((double)rabs / 8.0) / log(16.0) * 8.0;
        add = 8 + (int)lf;                // truncation toward zero, lf >= 0
        if (add > 15) add = 15;
    }
    bucket += add;
#pragma unroll
    for (int h = 0; h < NH; h++)
        g_bias[h * RELN + idx] = table[bucket * NH + h];
}

// ---------------- shared SGEMM body: 128x128 tile, 8x8 per thread ----------
__device__ __forceinline__ void sgemm_body(
    const float* __restrict__ A, const float* __restrict__ W,
    float (*As)[128], float (*Bs)[128],
    float acc[8][8], int m0, int n0)
{
    int tid = threadIdx.x;
    int arow = tid >> 1, ac = tid & 1;      // A tile load: 128 rows x 8 k
    int brow = tid >> 5, bc = tid & 31;     // B tile load: 8 k x 128 n
    int tx = tid & 15, ty = tid >> 4;

    const float* Aptr = A + (size_t)(m0 + arow) * DM + ac * 4;
    const float* Wptr = W + (size_t)brow * DM + n0 + bc * 4;

    for (int k0 = 0; k0 < DM; k0 += 8) {
        float4 a4 = *(const float4*)(Aptr + k0);
        float4 b4 = *(const float4*)(Wptr + (size_t)k0 * DM);
        __syncthreads();                     // previous iter compute done
        As[ac * 4 + 0][arow] = a4.x;
        As[ac * 4 + 1][arow] = a4.y;
        As[ac * 4 + 2][arow] = a4.z;
        As[ac * 4 + 3][arow] = a4.w;
        *(float4*)&Bs[brow][bc * 4] = b4;
        __syncthreads();
#pragma unroll
        for (int kk = 0; kk < 8; kk++) {
            float ra[8], rb[8];
            *(float4*)&ra[0] = *(float4*)&As[kk][ty * 8];
            *(float4*)&ra[4] = *(float4*)&As[kk][ty * 8 + 4];
            *(float4*)&rb[0] = *(float4*)&Bs[kk][tx * 4];
            *(float4*)&rb[4] = *(float4*)&Bs[kk][tx * 4 + 64];
#pragma unroll
            for (int i = 0; i < 8; i++)
#pragma unroll
                for (int j = 0; j < 8; j++)
                    acc[i][j] += ra[i] * rb[j];
        }
    }
}

// ---------------- QKV projection: X @ {Wq,Wk,Wv} -> [B,H,S,D] --------------
__global__ __launch_bounds__(256) void sgemm_qkv(
    const float* __restrict__ X,
    const float* __restrict__ Wq,
    const float* __restrict__ Wk,
    const float* __restrict__ Wv)
{
    __shared__ float As[8][128];
    __shared__ float Bs[8][128];
    int z = blockIdx.z;
    const float* W = (z == 0) ? Wq : (z == 1) ? Wk : Wv;
    float* out = (z == 0) ? g_q : (z == 1) ? g_k : g_v;

    int m0 = blockIdx.y * 128;
    int n0 = blockIdx.x * 128;
    float acc[8][8];
#pragma unroll
    for (int i = 0; i < 8; i++)
#pragma unroll
        for (int j = 0; j < 8; j++) acc[i][j] = 0.f;

    sgemm_body(X, W, As, Bs, acc, m0, n0);

    int tx = threadIdx.x & 15, ty = threadIdx.x >> 4;
    int h0 = n0 >> 6;   // two heads per 128-col tile
#pragma unroll
    for (int i = 0; i < 8; i++) {
        int m = m0 + ty * 8 + i;
        int b = m >> 11, s = m & (SEQ - 1);
        float4 q0 = make_float4(acc[i][0], acc[i][1], acc[i][2], acc[i][3]);
        float4 q1 = make_float4(acc[i][4], acc[i][5], acc[i][6], acc[i][7]);
        size_t base0 = (((size_t)(b * NH + h0)     * SEQ + s) * DK) + tx * 4;
        size_t base1 = (((size_t)(b * NH + h0 + 1) * SEQ + s) * DK) + tx * 4;
        *(float4*)&out[base0] = q0;
        *(float4*)&out[base1] = q1;
    }
}

// ---------------- output projection: g_attn @ Wo -> d_out ------------------
__global__ __launch_bounds__(256) void sgemm_out(
    const float* __restrict__ Wo, float* __restrict__ C)
{
    __shared__ float As[8][128];
    __shared__ float Bs[8][128];
    int m0 = blockIdx.y * 128;
    int n0 = blockIdx.x * 128;
    float acc[8][8];
#pragma unroll
    for (int i = 0; i < 8; i++)
#pragma unroll
        for (int j = 0; j < 8; j++) acc[i][j] = 0.f;

    sgemm_body(g_attn, Wo, As, Bs, acc, m0, n0);

    int tx = threadIdx.x & 15, ty = threadIdx.x >> 4;
#pragma unroll
    for (int i = 0; i < 8; i++) {
        int row = m0 + ty * 8 + i;
        float4 q0 = make_float4(acc[i][0], acc[i][1], acc[i][2], acc[i][3]);
        float4 q1 = make_float4(acc[i][4], acc[i][5], acc[i][6], acc[i][7]);
        *(float4*)&C[(size_t)row * DM + n0 + tx * 4]      = q0;
        *(float4*)&C[(size_t)row * DM + n0 + 64 + tx * 4] = q1;
    }
}

// ---------------- flash attention with T5 relative bias --------------------
// Block: 256 threads = 64 q-rows x 4 threads. Q row cached in registers.
// K/V tiles of 64 rows in smem (stride 68 floats -> conflict-free patterns).
// P tile overlays the Ks buffer between the two phases.
__global__ __launch_bounds__(256) void attn_kernel() {
    __shared__ float Ks[64][68];
    __shared__ float Vs[64][68];

    int bh = blockIdx.y;            // b*NH + h
    int h = bh & (NH - 1);
    int b = bh >> 4;
    int q0 = blockIdx.x * 64;
    const float* Qg = g_q + (size_t)bh * SEQ * DK;
    const float* Kg = g_k + (size_t)bh * SEQ * DK;
    const float* Vg = g_v + (size_t)bh * SEQ * DK;

    int tid = threadIdx.x;
    int r = tid >> 2;               // q-row within tile
    int t = tid & 3;                // quarter owner

    // stage Q tile through smem (coalesced), then grab own row into registers
    for (int i = tid; i < 64 * 16; i += 256) {
        int rr = i >> 4, c4 = i & 15;
        *(float4*)&Ks[rr][c4 * 4] = *(const float4*)(Qg + (size_t)(q0 + rr) * DK + c4 * 4);
    }
    __syncthreads();
    float4 qreg[16];
#pragma unroll
    for (int i = 0; i < 16; i++) qreg[i] = *(float4*)&Ks[r][i * 4];
    __syncthreads();

    float4 acc[4];
#pragma unroll
    for (int j = 0; j < 4; j++) acc[j] = make_float4(0.f, 0.f, 0.f, 0.f);
    float m_i = -1e30f, l_i = 0.f;

    const float* biasrow = g_bias + h * RELN + (SEQ - 1) - q0 - r;

    for (int k0 = 0; k0 < SEQ; k0 += 64) {
        // load K/V tiles (coalesced float4)
        for (int i = tid; i < 64 * 16; i += 256) {
            int rr = i >> 4, c4 = i & 15;
            *(float4*)&Ks[rr][c4 * 4] = *(const float4*)(Kg + (size_t)(k0 + rr) * DK + c4 * 4);
            *(float4*)&Vs[rr][c4 * 4] = *(const float4*)(Vg + (size_t)(k0 + rr) * DK + c4 * 4);
        }
        __syncthreads();

        // phase 1: scores for 16 interleaved columns c = t + 4*cc
        float sc[16];
#pragma unroll
        for (int cc = 0; cc < 16; cc++) {
            int c = t + cc * 4;
            float4 s4 = make_float4(0.f, 0.f, 0.f, 0.f);
#pragma unroll
            for (int i = 0; i < 16; i++) {
                float4 kv = *(float4*)&Ks[c][i * 4];
                s4.x += qreg[i].x * kv.x;
                s4.y += qreg[i].y * kv.y;
                s4.z += qreg[i].z * kv.z;
                s4.w += qreg[i].w * kv.w;
            }
            sc[cc] = (s4.x + s4.y) + (s4.z + s4.w) + __ldg(biasrow + k0 + c);
        }

        // online softmax: row reduce across the 4 threads of this row
        float mx = sc[0];
#pragma unroll
        for (int cc = 1; cc < 16; cc++) mx = fmaxf(mx, sc[cc]);
        mx = fmaxf(mx, __shfl_xor_sync(0xffffffffu, mx, 1));
        mx = fmaxf(mx, __shfl_xor_sync(0xffffffffu, mx, 2));
        float m_new = fmaxf(m_i, mx);
        float corr = __expf(m_i - m_new);
        float lsum = 0.f;
#pragma unroll
        for (int cc = 0; cc < 16; cc++) {
            float p = __expf(sc[cc] - m_new);
            sc[cc] = p;
            lsum += p;
        }
        lsum += __shfl_xor_sync(0xffffffffu, lsum, 1);
        lsum += __shfl_xor_sync(0xffffffffu, lsum, 2);
        l_i = l_i * corr + lsum;
        m_i = m_new;

        __syncthreads();              // all warps done reading Ks
        // stage P into the Ks buffer (row-local, same warp)
#pragma unroll
        for (int cc = 0; cc < 16; cc++) Ks[r][t + cc * 4] = sc[cc];
        __syncwarp();

        // phase 2: acc[d] = acc[d]*corr + sum_c P[r][c] * V[c][d]
#pragma unroll
        for (int j = 0; j < 4; j++) {
            acc[j].x *= corr; acc[j].y *= corr; acc[j].z *= corr; acc[j].w *= corr;
        }
#pragma unroll 4
        for (int c = 0; c < 64; c++) {
            float p = Ks[r][c];
#pragma unroll
            for (int j = 0; j < 4; j++) {
                float4 v4 = *(float4*)&Vs[c][t * 4 + 16 * j];
                acc[j].x += p * v4.x;
                acc[j].y += p * v4.y;
                acc[j].z += p * v4.z;
                acc[j].w += p * v4.w;
            }
        }
        __syncthreads();              // done with Vs/P before next tile load
    }

    float inv = 1.0f / l_i;
    float* orow = g_attn + ((size_t)(b * SEQ + q0 + r)) * DM + h * DK + t * 4;
#pragma unroll
    for (int j = 0; j < 4; j++) {
        float4 o = make_float4(acc[j].x * inv, acc[j].y * inv,
                               acc[j].z * inv, acc[j].w * inv);
        *(float4*)(orow + 16 * j) = o;
    }
}

// ---------------- launch ----------------------------------------------------
extern "C" void kernel_launch(void* const* d_in, const int* in_sizes, int n_in,
                              void* d_out, int out_size) {
    const float* X   = (const float*)d_in[0];
    const float* Wq  = (const float*)d_in[1];
    const float* Wk  = (const float*)d_in[2];
    const float* Wv  = (const float*)d_in[3];
    const float* Wo  = (const float*)d_in[4];
    const float* tbl = (const float*)d_in[5];
    float* out = (float*)d_out;

    bias_kernel<<<(RELN + 255) / 256, 256>>>(tbl);

    dim3 g1(DM / 128, (BSZ * SEQ) / 128, 3);
    sgemm_qkv<<<g1, 256>>>(X, Wq, Wk, Wv);

    dim3 g2(SEQ / 64, BSZ * NH);
    attn_kernel<<<g2, 256>>>();

    dim3 g3(DM / 128, (BSZ * SEQ) / 128);
    sgemm_out<<<g3, 256>>>(Wo, out);
}

// round 2
// speedup vs baseline: 1.5305x; 1.5305x over previous
#include <cuda_runtime.h>
#include <math.h>

#define BSZ   2
#define SEQ   2048
#define DM    1024
#define NH    16
#define DK    64
#define RELN  (2*SEQ-1)   // 4095

// ---------------- scratch (device globals: no allocation allowed) ----------
__device__ float g_q[BSZ*NH*SEQ*DK];     // [b][h][s][d]
__device__ float g_k[BSZ*NH*SEQ*DK];
__device__ float g_v[BSZ*NH*SEQ*DK];
__device__ float g_attn[BSZ*SEQ*DM];     // [b*S+s][h*64+d]
__device__ float g_bias[NH*RELN];        // [h][rel + S-1]

// ---------------- relative-position bias precompute -------------------------
__global__ void bias_kernel(const float* __restrict__ table) {
    int idx = blockIdx.x * blockDim.x + threadIdx.x;
    if (idx >= RELN) return;
    int rel = idx - (SEQ - 1);            // mem - ctx
    int bucket = (rel > 0) ? 16 : 0;
    int rabs = rel < 0 ? -rel : rel;
    int add;
    if (rabs < 8) {
        add = rabs;
    } else {
        double lf = log((double)rabs / 8.0) / log(16.0) * 8.0;
        add = 8 + (int)lf;                // truncation toward zero, lf >= 0
        if (add > 15) add = 15;
    }
    bucket += add;
#pragma unroll
    for (int h = 0; h < NH; h++)
        g_bias[h * RELN + idx] = table[bucket * NH + h];
}

// ---------------- shared SGEMM body: 128x128 tile, 8x8 per thread ----------
__device__ __forceinline__ void sgemm_body(
    const float* __restrict__ A, const float* __restrict__ W,
    float (*As)[128], float (*Bs)[128],
    float acc[8][8], int m0, int n0)
{
    int tid = threadIdx.x;
    int arow = tid >> 1, ac = tid & 1;      // A tile load: 128 rows x 8 k
    int brow = tid >> 5, bc = tid & 31;     // B tile load: 8 k x 128 n
    int tx = tid & 15, ty = tid >> 4;

    const float* Aptr = A + (size_t)(m0 + arow) * DM + ac * 4;
    const float* Wptr = W + (size_t)brow * DM + n0 + bc * 4;

    for (int k0 = 0; k0 < DM; k0 += 8) {
        float4 a4 = *(const float4*)(Aptr + k0);
        float4 b4 = *(const float4*)(Wptr + (size_t)k0 * DM);
        __syncthreads();                     // previous iter compute done
        As[ac * 4 + 0][arow] = a4.x;
        As[ac * 4 + 1][arow] = a4.y;
        As[ac * 4 + 2][arow] = a4.z;
        As[ac * 4 + 3][arow] = a4.w;
        *(float4*)&Bs[brow][bc * 4] = b4;
        __syncthreads();
#pragma unroll
        for (int kk = 0; kk < 8; kk++) {
            float ra[8], rb[8];
            *(float4*)&ra[0] = *(float4*)&As[kk][ty * 8];
            *(float4*)&ra[4] = *(float4*)&As[kk][ty * 8 + 4];
            *(float4*)&rb[0] = *(float4*)&Bs[kk][tx * 4];
            *(float4*)&rb[4] = *(float4*)&Bs[kk][tx * 4 + 64];
#pragma unroll
            for (int i = 0; i < 8; i++)
#pragma unroll
                for (int j = 0; j < 8; j++)
                    acc[i][j] += ra[i] * rb[j];
        }
    }
}

// ---------------- QKV projection: X @ {Wq,Wk,Wv} -> [B,H,S,D] --------------
__global__ __launch_bounds__(256) void sgemm_qkv(
    const float* __restrict__ X,
    const float* __restrict__ Wq,
    const float* __restrict__ Wk,
    const float* __restrict__ Wv)
{
    __shared__ float As[8][128];
    __shared__ float Bs[8][128];
    int z = blockIdx.z;
    const float* W = (z == 0) ? Wq : (z == 1) ? Wk : Wv;
    float* out = (z == 0) ? g_q : (z == 1) ? g_k : g_v;

    int m0 = blockIdx.y * 128;
    int n0 = blockIdx.x * 128;
    float acc[8][8];
#pragma unroll
    for (int i = 0; i < 8; i++)
#pragma unroll
        for (int j = 0; j < 8; j++) acc[i][j] = 0.f;

    sgemm_body(X, W, As, Bs, acc, m0, n0);

    int tx = threadIdx.x & 15, ty = threadIdx.x >> 4;
    int h0 = n0 >> 6;   // two heads per 128-col tile
#pragma unroll
    for (int i = 0; i < 8; i++) {
        int m = m0 + ty * 8 + i;
        int b = m >> 11, s = m & (SEQ - 1);
        float4 q0 = make_float4(acc[i][0], acc[i][1], acc[i][2], acc[i][3]);
        float4 q1 = make_float4(acc[i][4], acc[i][5], acc[i][6], acc[i][7]);
        size_t base0 = (((size_t)(b * NH + h0)     * SEQ + s) * DK) + tx * 4;
        size_t base1 = (((size_t)(b * NH + h0 + 1) * SEQ + s) * DK) + tx * 4;
        *(float4*)&out[base0] = q0;
        *(float4*)&out[base1] = q1;
    }
}

// ---------------- output projection: g_attn @ Wo -> d_out ------------------
__global__ __launch_bounds__(256) void sgemm_out(
    const float* __restrict__ Wo, float* __restrict__ C)
{
    __shared__ float As[8][128];
    __shared__ float Bs[8][128];
    int m0 = blockIdx.y * 128;
    int n0 = blockIdx.x * 128;
    float acc[8][8];
#pragma unroll
    for (int i = 0; i < 8; i++)
#pragma unroll
        for (int j = 0; j < 8; j++) acc[i][j] = 0.f;

    sgemm_body(g_attn, Wo, As, Bs, acc, m0, n0);

    int tx = threadIdx.x & 15, ty = threadIdx.x >> 4;
#pragma unroll
    for (int i = 0; i < 8; i++) {
        int row = m0 + ty * 8 + i;
        float4 q0 = make_float4(acc[i][0], acc[i][1], acc[i][2], acc[i][3]);
        float4 q1 = make_float4(acc[i][4], acc[i][5], acc[i][6], acc[i][7]);
        *(float4*)&C[(size_t)row * DM + n0 + tx * 4]      = q0;
        *(float4*)&C[(size_t)row * DM + n0 + 64 + tx * 4] = q1;
    }
}

// ---------------- flash attention v2: register-tiled GEMM pair -------------
// Block 256 thr (16 ty x 16 tx). Br=128 q-rows, Bc=128 k-cols per iter.
// Phase1: S = Q*K^T via 8x8 microtile, Q/K d-major in smem (broadcast reads).
// Softmax per row via shfl over the 16 tx lanes. P staged fp32 in smem.
// Phase2: O += P*V, 8 rows x 4 d per thread, broadcast P reads.
#define BR 128
#define BC 128
#define VS_STRIDE 68
#define PS_STRIDE 132
// float offsets into dynamic smem
#define QS_OFF 0
#define KS_OFF (64*BR)                    // 8192
#define VS_OFF (KS_OFF + 64*BC)           // 16384
#define PS_OFF (VS_OFF + BC*VS_STRIDE)    // 25088
#define ATTN_SMEM_BYTES ((PS_OFF + BR*PS_STRIDE) * 4)   // 167936

__global__ __launch_bounds__(256, 1) void attn_kernel_v2() {
    extern __shared__ float sm[];
    float* Qs = sm + QS_OFF;   // [d][row]  64 x 128
    float* Ks = sm + KS_OFF;   // [d][col]  64 x 128
    float* Vs = sm + VS_OFF;   // [c][d]   128 x 68
    float* Ps = sm + PS_OFF;   // [row][c] 128 x 132

    const int bh = blockIdx.y;
    const int h = bh & (NH - 1);
    const int b = bh >> 4;
    const int q0 = blockIdx.x * BR;
    const float* __restrict__ Qg = g_q + (size_t)bh * SEQ * DK;
    const float* __restrict__ Kg = g_k + (size_t)bh * SEQ * DK;
    const float* __restrict__ Vg = g_v + (size_t)bh * SEQ * DK;

    const int tid = threadIdx.x;
    const int tx = tid & 15, ty = tid >> 4;

    // load Q transposed (scattered gmem reads once; conflict-free STS)
    for (int jb = tid; jb < BR * 16; jb += 256) {
        int row = jb & (BR - 1);
        int c4 = jb >> 7;
        float4 v = *(const float4*)(Qg + (size_t)(q0 + row) * DK + c4 * 4);
        Qs[(c4 * 4 + 0) * BR + row] = v.x;
        Qs[(c4 * 4 + 1) * BR + row] = v.y;
        Qs[(c4 * 4 + 2) * BR + row] = v.z;
        Qs[(c4 * 4 + 3) * BR + row] = v.w;
    }

    float4 acc[8];
#pragma unroll
    for (int i = 0; i < 8; i++) acc[i] = make_float4(0.f, 0.f, 0.f, 0.f);
    float mrow[8], lrow[8];
#pragma unroll
    for (int i = 0; i < 8; i++) { mrow[i] = -1e30f; lrow[i] = 0.f; }

    // per-thread bias window base: index = 2047 + (k0+8tx+j) - (q0+8ty+i)
    const float* __restrict__ bias0 =
        g_bias + h * RELN + (SEQ - 1) - q0 + 8 * (tx - ty) - 7;

    for (int k0 = 0; k0 < SEQ; k0 += BC) {
        __syncthreads();   // prev phase2 finished with Vs/Ps, phase1 with Ks

        // K transposed into Ks[d][col]
        for (int jb = tid; jb < BC * 16; jb += 256) {
            int row = jb & (BC - 1);
            int c4 = jb >> 7;
            float4 v = *(const float4*)(Kg + (size_t)(k0 + row) * DK + c4 * 4);
            Ks[(c4 * 4 + 0) * BC + row] = v.x;
            Ks[(c4 * 4 + 1) * BC + row] = v.y;
            Ks[(c4 * 4 + 2) * BC + row] = v.z;
            Ks[(c4 * 4 + 3) * BC + row] = v.w;
        }
        // V natural into Vs[c][d]
        for (int jb = tid; jb < BC * 16; jb += 256) {
            int c = jb >> 4, d4 = jb & 15;
            *(float4*)&Vs[c * VS_STRIDE + d4 * 4] =
                *(const float4*)(Vg + (size_t)(k0 + c) * DK + d4 * 4);
        }
        // bias window for this k-tile (15 values cover all j-i)
        float br[15];
#pragma unroll
        for (int m = 0; m < 15; m++) br[m] = __ldg(bias0 + k0 + m);
        __syncthreads();

        // ---------------- phase 1: S = Q K^T (8x8 microtile) -------------
        float sc[8][8];
#pragma unroll
        for (int i = 0; i < 8; i++)
#pragma unroll
            for (int j = 0; j < 8; j++) sc[i][j] = 0.f;

#pragma unroll 4
        for (int d = 0; d < DK; d++) {
            float qv[8], kv[8];
            *(float4*)&qv[0] = *(float4*)&Qs[d * BR + ty * 8];
            *(float4*)&qv[4] = *(float4*)&Qs[d * BR + ty * 8 + 4];
            *(float4*)&kv[0] = *(float4*)&Ks[d * BC + tx * 8];
            *(float4*)&kv[4] = *(float4*)&Ks[d * BC + tx * 8 + 4];
#pragma unroll
            for (int i = 0; i < 8; i++)
#pragma unroll
                for (int j = 0; j < 8; j++)
                    sc[i][j] += qv[i] * kv[j];
        }

        // ---------------- softmax (rows owned by 16 tx lanes) ------------
        float cr[8];
#pragma unroll
        for (int i = 0; i < 8; i++) {
#pragma unroll
            for (int j = 0; j < 8; j++) sc[i][j] += br[j - i + 7];
            float mx = sc[i][0];
#pragma unroll
            for (int j = 1; j < 8; j++) mx = fmaxf(mx, sc[i][j]);
            mx = fmaxf(mx, __shfl_xor_sync(0xffffffffu, mx, 1));
            mx = fmaxf(mx, __shfl_xor_sync(0xffffffffu, mx, 2));
            mx = fmaxf(mx, __shfl_xor_sync(0xffffffffu, mx, 4));
            mx = fmaxf(mx, __shfl_xor_sync(0xffffffffu, mx, 8));
            float mn = fmaxf(mrow[i], mx);
            float corr = __expf(mrow[i] - mn);
            float ls = 0.f;
#pragma unroll
            for (int j = 0; j < 8; j++) {
                float p = __expf(sc[i][j] - mn);
                sc[i][j] = p;
                ls += p;
            }
            ls += __shfl_xor_sync(0xffffffffu, ls, 1);
            ls += __shfl_xor_sync(0xffffffffu, ls, 2);
            ls += __shfl_xor_sync(0xffffffffu, ls, 4);
            ls += __shfl_xor_sync(0xffffffffu, ls, 8);
            lrow[i] = lrow[i] * corr + ls;
            mrow[i] = mn;
            cr[i] = corr;
        }

        // stage P (row-major) and rescale accumulators
#pragma unroll
        for (int i = 0; i < 8; i++) {
            float* pr = &Ps[(ty * 8 + i) * PS_STRIDE + tx * 8];
            *(float4*)pr       = make_float4(sc[i][0], sc[i][1], sc[i][2], sc[i][3]);
            *(float4*)(pr + 4) = make_float4(sc[i][4], sc[i][5], sc[i][6], sc[i][7]);
        }
#pragma unroll
        for (int i = 0; i < 8; i++) {
            acc[i].x *= cr[i]; acc[i].y *= cr[i];
            acc[i].z *= cr[i]; acc[i].w *= cr[i];
        }
        __syncthreads();

        // ---------------- phase 2: O += P V (8 rows x 4 d) ---------------
#pragma unroll 2
        for (int c0 = 0; c0 < BC; c0 += 4) {
            float pv[8][4];
#pragma unroll
            for (int i = 0; i < 8; i++)
                *(float4*)&pv[i][0] = *(float4*)&Ps[(ty * 8 + i) * PS_STRIDE + c0];
            float4 vv[4];
#pragma unroll
            for (int cc = 0; cc < 4; cc++)
                vv[cc] = *(float4*)&Vs[(c0 + cc) * VS_STRIDE + tx * 4];
#pragma unroll
            for (int i = 0; i < 8; i++)
#pragma unroll
                for (int cc = 0; cc < 4; cc++) {
                    acc[i].x += pv[i][cc] * vv[cc].x;
                    acc[i].y += pv[i][cc] * vv[cc].y;
                    acc[i].z += pv[i][cc] * vv[cc].z;
                    acc[i].w += pv[i][cc] * vv[cc].w;
                }
        }
    }

    // epilogue
#pragma unroll
    for (int i = 0; i < 8; i++) {
        float inv = 1.0f / lrow[i];
        int row = q0 + ty * 8 + i;
        float4 o = make_float4(acc[i].x * inv, acc[i].y * inv,
                               acc[i].z * inv, acc[i].w * inv);
        *(float4*)&g_attn[(size_t)(b * SEQ + row) * DM + h * DK + tx * 4] = o;
    }
}

// ---------------- launch ----------------------------------------------------
extern "C" void kernel_launch(void* const* d_in, const int* in_sizes, int n_in,
                              void* d_out, int out_size) {
    const float* X   = (const float*)d_in[0];
    const float* Wq  = (const float*)d_in[1];
    const float* Wk  = (const float*)d_in[2];
    const float* Wv  = (const float*)d_in[3];
    const float* Wo  = (const float*)d_in[4];
    const float* tbl = (const float*)d_in[5];
    float* out = (float*)d_out;

    cudaFuncSetAttribute(attn_kernel_v2,
                         cudaFuncAttributeMaxDynamicSharedMemorySize,
                         ATTN_SMEM_BYTES);

    bias_kernel<<<(RELN + 255) / 256, 256>>>(tbl);

    dim3 g1(DM / 128, (BSZ * SEQ) / 128, 3);
    sgemm_qkv<<<g1, 256>>>(X, Wq, Wk, Wv);

    dim3 g2(SEQ / BR, BSZ * NH);
    attn_kernel_v2<<<g2, 256, ATTN_SMEM_BYTES>>>();

    dim3 g3(DM / 128, (BSZ * SEQ) / 128);
    sgemm_out<<<g3, 256>>>(Wo, out);
}

// round 6
// speedup vs baseline: 1.9570x; 1.2787x over previous
#include <cuda_runtime.h>
#include <cuda_bf16.h>
#include <math.h>
#include <stdint.h>

#define BSZ   2
#define SEQ   2048
#define DM    1024
#define NH    16
#define DK    64
#define RELN  (2*SEQ-1)   // 4095
#define MROWS (BSZ*SEQ)   // 4096

// ---------------- scratch (device globals: no allocation allowed) ----------
// NOTE: these are referenced ONLY from device code (host-side decay of a
// __device__ symbol yields the host shadow address -> fault).
__device__ float g_q[BSZ*NH*SEQ*DK];     // [b][h][s][d]
__device__ float g_k[BSZ*NH*SEQ*DK];
__device__ float g_v[BSZ*NH*SEQ*DK];
__device__ float g_attn[BSZ*SEQ*DM];     // [b*S+s][h*64+d]
__device__ float g_bias[NH*RELN];        // [h][rel + S-1]

__device__ __nv_bfloat16 g_xhi[MROWS*DM];   // activation hi/lo (X, then attn)
__device__ __nv_bfloat16 g_xlo[MROWS*DM];
__device__ __nv_bfloat16 g_wth[4*DM*DM];    // W^T hi: [w][n][k]
__device__ __nv_bfloat16 g_wtl[4*DM*DM];    // W^T lo

// ======================= mma.sync helper =====================================
__device__ __forceinline__ void mma_bf16(float acc[4], const uint32_t a[4],
                                         const uint32_t b[2]) {
    asm volatile(
        "mma.sync.aligned.m16n8k16.row.col.f32.bf16.bf16.f32 "
        "{%0,%1,%2,%3}, {%4,%5,%6,%7}, {%8,%9}, {%0,%1,%2,%3};"
        : "+f"(acc[0]), "+f"(acc[1]), "+f"(acc[2]), "+f"(acc[3])
        : "r"(a[0]), "r"(a[1]), "r"(a[2]), "r"(a[3]), "r"(b[0]), "r"(b[1]));
}

// ---------------- relative-position bias precompute -------------------------
__global__ void bias_kernel(const float* __restrict__ table) {
    int idx = blockIdx.x * blockDim.x + threadIdx.x;
    if (idx >= RELN) return;
    int rel = idx - (SEQ - 1);
    int bucket = (rel > 0) ? 16 : 0;
    int rabs = rel < 0 ? -rel : rel;
    int add;
    if (rabs < 8) {
        add = rabs;
    } else {
        double lf = log((double)rabs / 8.0) / log(16.0) * 8.0;
        add = 8 + (int)lf;
        if (add > 15) add = 15;
    }
    bucket += add;
#pragma unroll
    for (int h = 0; h < NH; h++)
        g_bias[h * RELN + idx] = table[bucket * NH + h];
}

// ---------------- fp32 -> (hi,lo) bf16 split --------------------------------
// use_attn=0: read from harness pointer `in`; use_attn=1: read g_attn.
__global__ __launch_bounds__(256) void xcvt(const float* __restrict__ in,
                                            int use_attn, int n4) {
    int i = blockIdx.x * blockDim.x + threadIdx.x;
    if (i >= n4) return;
    const float* src = use_attn ? (const float*)g_attn : in;
    float4 x = ((const float4*)src)[i];
    float xs[4] = {x.x, x.y, x.z, x.w};
    __nv_bfloat16 hb[4], lb[4];
#pragma unroll
    for (int j = 0; j < 4; j++) {
        hb[j] = __float2bfloat16_rn(xs[j]);
        lb[j] = __float2bfloat16_rn(xs[j] - __bfloat162float(hb[j]));
    }
    *(uint2*)&g_xhi[i * 4] = *(uint2*)hb;
    *(uint2*)&g_xlo[i * 4] = *(uint2*)lb;
}

// ---------------- W [K][N] -> W^T (hi,lo) bf16 [N][K] -----------------------
__global__ __launch_bounds__(256) void wt_cvt(const float* __restrict__ Wq,
                                              const float* __restrict__ Wk,
                                              const float* __restrict__ Wv,
                                              const float* __restrict__ Wo) {
    __shared__ float tile[32][33];
    int w = blockIdx.z;
    const float* W = (w == 0) ? Wq : (w == 1) ? Wk : (w == 2) ? Wv : Wo;
    int kb = blockIdx.y * 32, nb = blockIdx.x * 32;
    int tx = threadIdx.x, ty = threadIdx.y;
    for (int r = ty; r < 32; r += 8)
        tile[r][tx] = W[(size_t)(kb + r) * DM + nb + tx];
    __syncthreads();
    __nv_bfloat16* oh = g_wth + (size_t)w * DM * DM;
    __nv_bfloat16* ol = g_wtl + (size_t)w * DM * DM;
    for (int r = ty; r < 32; r += 8) {
        float x = tile[tx][r];                    // = W[kb+tx][nb+r]
        __nv_bfloat16 h = __float2bfloat16_rn(x);
        __nv_bfloat16 l = __float2bfloat16_rn(x - __bfloat162float(h));
        size_t o = (size_t)(nb + r) * DM + kb + tx;
        oh[o] = h;
        ol[o] = l;
    }
}

// ---------------- split-bf16 GEMM via mma.sync (direct-LDS fragments) -------
// C[128 x 128] per block, K=1024 in 32 chunks of 32. 8 warps = 2(m) x 4(n),
// warp tile 64x32. Smem [row][k] stride 40 bf16 = 20 words (conflict-free).
// mode 0: epilogue permutes into g_q/g_k/g_v ([B,H,S,D]); mode 1: row-major.
#define A_ELEMS (128*40)     // 5120 bf16 per tensor half (= 2560 words)
#define AW      2560         // words per region
#define RSTRIDE 20           // words per row

__global__ __launch_bounds__(256) void gemm_mma(
    int wbase, int mode, float* __restrict__ outp)
{
    __shared__ __align__(16) __nv_bfloat16 smem[4 * A_ELEMS];   // 40 KB
    const uint32_t* SW = (const uint32_t*)smem;

    const int tid = threadIdx.x;
    const int wid = tid >> 5, lane = tid & 31;
    const int wm = wid & 1;        // 0..1  (64 rows each)
    const int wn = wid >> 1;       // 0..3  (32 cols each)
    const int fr = lane >> 2;      // 0..7
    const int fc = lane & 3;       // 0..3

    const int w  = wbase + blockIdx.z;
    const int m0 = blockIdx.y * 128;
    const int n0 = blockIdx.x * 128;
    const __nv_bfloat16* __restrict__ ah = g_xhi;
    const __nv_bfloat16* __restrict__ al = g_xlo;
    const __nv_bfloat16* __restrict__ bh = g_wth + (size_t)w * DM * DM;
    const __nv_bfloat16* __restrict__ bl = g_wtl + (size_t)w * DM * DM;

    float acc[4][4][4];
#pragma unroll
    for (int i = 0; i < 4; i++)
#pragma unroll
        for (int j = 0; j < 4; j++)
#pragma unroll
            for (int q = 0; q < 4; q++) acc[i][j][q] = 0.f;

    for (int c = 0; c < 32; c++) {
        const int k0 = c * 32;
        __syncthreads();
        // ---- load A hi/lo (1024 uint4) and B hi/lo (1024 uint4) ----
#pragma unroll
        for (int i = 0; i < 4; i++) {
            int idx = tid + i * 256;
            int sel = idx >> 9, r = (idx >> 2) & 127, j = idx & 3;
            const __nv_bfloat16* src =
                (sel ? al : ah) + (size_t)(m0 + r) * DM + k0 + j * 8;
            *(uint4*)(smem + sel * A_ELEMS + r * 40 + j * 8) =
                *(const uint4*)src;
        }
#pragma unroll
        for (int i = 0; i < 4; i++) {
            int idx = tid + i * 256;
            int sel = idx >> 9, r = (idx >> 2) & 127, j = idx & 3;
            const __nv_bfloat16* src =
                (sel ? bl : bh) + (size_t)(n0 + r) * DM + k0 + j * 8;
            *(uint4*)(smem + 2 * A_ELEMS + sel * A_ELEMS + r * 40 + j * 8) =
                *(const uint4*)src;
        }
        __syncthreads();

        // ---- compute: 2 k-steps of 16 ----
#pragma unroll
        for (int ks = 0; ks < 2; ks++) {
            const int kw = ks * 8;   // k offset in words
            uint32_t Ahf[4][4], Alf[4][4], Bf[4][2];
            // A hi fragments
#pragma unroll
            for (int mf = 0; mf < 4; mf++) {
                int base = (wm * 64 + mf * 16 + fr) * RSTRIDE + kw + fc;
                Ahf[mf][0] = SW[base];
                Ahf[mf][1] = SW[base + 8 * RSTRIDE];
                Ahf[mf][2] = SW[base + 4];
                Ahf[mf][3] = SW[base + 8 * RSTRIDE + 4];
            }
            // B hi fragments
#pragma unroll
            for (int nf = 0; nf < 4; nf++) {
                int nb = (wn * 32 + nf * 8 + fr) * RSTRIDE + kw + fc;
                Bf[nf][0] = SW[2 * AW + nb];
                Bf[nf][1] = SW[2 * AW + nb + 4];
            }
#pragma unroll
            for (int mf = 0; mf < 4; mf++)
#pragma unroll
                for (int nf = 0; nf < 4; nf++)
                    mma_bf16(acc[mf][nf], Ahf[mf], Bf[nf]);   // hi*hi
            // A lo fragments
#pragma unroll
            for (int mf = 0; mf < 4; mf++) {
                int base = AW + (wm * 64 + mf * 16 + fr) * RSTRIDE + kw + fc;
                Alf[mf][0] = SW[base];
                Alf[mf][1] = SW[base + 8 * RSTRIDE];
                Alf[mf][2] = SW[base + 4];
                Alf[mf][3] = SW[base + 8 * RSTRIDE + 4];
            }
#pragma unroll
            for (int mf = 0; mf < 4; mf++)
#pragma unroll
                for (int nf = 0; nf < 4; nf++)
                    mma_bf16(acc[mf][nf], Alf[mf], Bf[nf]);   // lo*hi
            // B lo fragments (overwrite Bf)
#pragma unroll
            for (int nf = 0; nf < 4; nf++) {
                int nb = (wn * 32 + nf * 8 + fr) * RSTRIDE + kw + fc;
                Bf[nf][0] = SW[3 * AW + nb];
                Bf[nf][1] = SW[3 * AW + nb + 4];
            }
#pragma unroll
            for (int mf = 0; mf < 4; mf++)
#pragma unroll
                for (int nf = 0; nf < 4; nf++)
                    mma_bf16(acc[mf][nf], Ahf[mf], Bf[nf]);   // hi*lo
        }
    }

    // ---- epilogue: c0,c1 -> (row, n..n+1); c2,c3 -> (row+8, n..n+1) ----
#pragma unroll
    for (int mf = 0; mf < 4; mf++) {
        int row = m0 + wm * 64 + mf * 16 + fr;
#pragma unroll
        for (int nf = 0; nf < 4; nf++) {
            int n = n0 + wn * 32 + nf * 8 + fc * 2;
            float2 v0 = make_float2(acc[mf][nf][0], acc[mf][nf][1]);
            float2 v1 = make_float2(acc[mf][nf][2], acc[mf][nf][3]);
            if (mode == 0) {
                float* dst = (w == 0) ? g_q : (w == 1) ? g_k : g_v;
                int h = n >> 6, d = n & 63;
                int b = row >> 11, s = row & (SEQ - 1);
                size_t base = (((size_t)(b * NH + h) * SEQ + s) * DK) + d;
                *(float2*)(dst + base) = v0;
                *(float2*)(dst + base + 8 * DK) = v1;   // row+8 -> s+8
            } else {
                *(float2*)(outp + (size_t)row * DM + n) = v0;
                *(float2*)(outp + (size_t)(row + 8) * DM + n) = v1;
            }
        }
    }
}

// ---------------- flash attention (register-tiled GEMM pair) ---------------
#define BR 128
#define BC 128
#define VS_STRIDE 68
#define PS_STRIDE 132
#define QS_OFF 0
#define KS_OFF (64*BR)
#define VS_OFF (KS_OFF + 64*BC)
#define PS_OFF (VS_OFF + BC*VS_STRIDE)
#define ATTN_SMEM_BYTES ((PS_OFF + BR*PS_STRIDE) * 4)

__global__ __launch_bounds__(256, 1) void attn_kernel_v2() {
    extern __shared__ float smf[];
    float* Qs = smf + QS_OFF;
    float* Ks = smf + KS_OFF;
    float* Vs = smf + VS_OFF;
    float* Ps = smf + PS_OFF;

    const int bh = blockIdx.y;
    const int h = bh & (NH - 1);
    const int b = bh >> 4;
    const int q0 = blockIdx.x * BR;
    const float* __restrict__ Qg = g_q + (size_t)bh * SEQ * DK;
    const float* __restrict__ Kg = g_k + (size_t)bh * SEQ * DK;
    const float* __restrict__ Vg = g_v + (size_t)bh * SEQ * DK;

    const int tid = threadIdx.x;
    const int tx = tid & 15, ty = tid >> 4;

    for (int jb = tid; jb < BR * 16; jb += 256) {
        int row = jb & (BR - 1);
        int c4 = jb >> 7;
        float4 v = *(const float4*)(Qg + (size_t)(q0 + row) * DK + c4 * 4);
        Qs[(c4 * 4 + 0) * BR + row] = v.x;
        Qs[(c4 * 4 + 1) * BR + row] = v.y;
        Qs[(c4 * 4 + 2) * BR + row] = v.z;
        Qs[(c4 * 4 + 3) * BR + row] = v.w;
    }

    float4 acc[8];
#pragma unroll
    for (int i = 0; i < 8; i++) acc[i] = make_float4(0.f, 0.f, 0.f, 0.f);
    float mrow[8], lrow[8];
#pragma unroll
    for (int i = 0; i < 8; i++) { mrow[i] = -1e30f; lrow[i] = 0.f; }

    const float* __restrict__ bias0 =
        g_bias + h * RELN + (SEQ - 1) - q0 + 8 * (tx - ty) - 7;

    for (int k0 = 0; k0 < SEQ; k0 += BC) {
        __syncthreads();
        for (int jb = tid; jb < BC * 16; jb += 256) {
            int row = jb & (BC - 1);
            int c4 = jb >> 7;
            float4 v = *(const float4*)(Kg + (size_t)(k0 + row) * DK + c4 * 4);
            Ks[(c4 * 4 + 0) * BC + row] = v.x;
            Ks[(c4 * 4 + 1) * BC + row] = v.y;
            Ks[(c4 * 4 + 2) * BC + row] = v.z;
            Ks[(c4 * 4 + 3) * BC + row] = v.w;
        }
        for (int jb = tid; jb < BC * 16; jb += 256) {
            int c = jb >> 4, d4 = jb & 15;
            *(float4*)&Vs[c * VS_STRIDE + d4 * 4] =
                *(const float4*)(Vg + (size_t)(k0 + c) * DK + d4 * 4);
        }
        float br[15];
#pragma unroll
        for (int mm = 0; mm < 15; mm++) br[mm] = __ldg(bias0 + k0 + mm);
        __syncthreads();

        float sc[8][8];
#pragma unroll
        for (int i = 0; i < 8; i++)
#pragma unroll
            for (int j = 0; j < 8; j++) sc[i][j] = 0.f;

#pragma unroll 4
        for (int d = 0; d < DK; d++) {
            float qv[8], kv[8];
            *(float4*)&qv[0] = *(float4*)&Qs[d * BR + ty * 8];
            *(float4*)&qv[4] = *(float4*)&Qs[d * BR + ty * 8 + 4];
            *(float4*)&kv[0] = *(float4*)&Ks[d * BC + tx * 8];
            *(float4*)&kv[4] = *(float4*)&Ks[d * BC + tx * 8 + 4];
#pragma unroll
            for (int i = 0; i < 8; i++)
#pragma unroll
                for (int j = 0; j < 8; j++)
                    sc[i][j] += qv[i] * kv[j];
        }

        float cr[8];
#pragma unroll
        for (int i = 0; i < 8; i++) {
#pragma unroll
            for (int j = 0; j < 8; j++) sc[i][j] += br[j - i + 7];
            float mx = sc[i][0];
#pragma unroll
            for (int j = 1; j < 8; j++) mx = fmaxf(mx, sc[i][j]);
            mx = fmaxf(mx, __shfl_xor_sync(0xffffffffu, mx, 1));
            mx = fmaxf(mx, __shfl_xor_sync(0xffffffffu, mx, 2));
            mx = fmaxf(mx, __shfl_xor_sync(0xffffffffu, mx, 4));
            mx = fmaxf(mx, __shfl_xor_sync(0xffffffffu, mx, 8));
            float mn = fmaxf(mrow[i], mx);
            float corr = __expf(mrow[i] - mn);
            float ls = 0.f;
#pragma unroll
            for (int j = 0; j < 8; j++) {
                float p = __expf(sc[i][j] - mn);
                sc[i][j] = p;
                ls += p;
            }
            ls += __shfl_xor_sync(0xffffffffu, ls, 1);
            ls += __shfl_xor_sync(0xffffffffu, ls, 2);
            ls += __shfl_xor_sync(0xffffffffu, ls, 4);
            ls += __shfl_xor_sync(0xffffffffu, ls, 8);
            lrow[i] = lrow[i] * corr + ls;
            mrow[i] = mn;
            cr[i] = corr;
        }

#pragma unroll
        for (int i = 0; i < 8; i++) {
            float* pr = &Ps[(ty * 8 + i) * PS_STRIDE + tx * 8];
            *(float4*)pr       = make_float4(sc[i][0], sc[i][1], sc[i][2], sc[i][3]);
            *(float4*)(pr + 4) = make_float4(sc[i][4], sc[i][5], sc[i][6], sc[i][7]);
        }
#pragma unroll
        for (int i = 0; i < 8; i++) {
            acc[i].x *= cr[i]; acc[i].y *= cr[i];
            acc[i].z *= cr[i]; acc[i].w *= cr[i];
        }
        __syncthreads();

#pragma unroll 2
        for (int c0 = 0; c0 < BC; c0 += 4) {
            float pv[8][4];
#pragma unroll
            for (int i = 0; i < 8; i++)
                *(float4*)&pv[i][0] = *(float4*)&Ps[(ty * 8 + i) * PS_STRIDE + c0];
            float4 vv[4];
#pragma unroll
            for (int cc = 0; cc < 4; cc++)
                vv[cc] = *(float4*)&Vs[(c0 + cc) * VS_STRIDE + tx * 4];
#pragma unroll
            for (int i = 0; i < 8; i++)
#pragma unroll
                for (int cc = 0; cc < 4; cc++) {
                    acc[i].x += pv[i][cc] * vv[cc].x;
                    acc[i].y += pv[i][cc] * vv[cc].y;
                    acc[i].z += pv[i][cc] * vv[cc].z;
                    acc[i].w += pv[i][cc] * vv[cc].w;
                }
        }
    }

#pragma unroll
    for (int i = 0; i < 8; i++) {
        float inv = 1.0f / lrow[i];
        int row = q0 + ty * 8 + i;
        float4 o = make_float4(acc[i].x * inv, acc[i].y * inv,
                               acc[i].z * inv, acc[i].w * inv);
        *(float4*)&g_attn[(size_t)(b * SEQ + row) * DM + h * DK + tx * 4] = o;
    }
}

// ---------------- launch ----------------------------------------------------
extern "C" void kernel_launch(void* const* d_in, const int* in_sizes, int n_in,
                              void* d_out, int out_size) {
    const float* X   = (const float*)d_in[0];
    const float* Wq  = (const float*)d_in[1];
    const float* Wk  = (const float*)d_in[2];
    const float* Wv  = (const float*)d_in[3];
    const float* Wo  = (const float*)d_in[4];
    const float* tbl = (const float*)d_in[5];
    float* out = (float*)d_out;

    cudaFuncSetAttribute(attn_kernel_v2,
                         cudaFuncAttributeMaxDynamicSharedMemorySize,
                         ATTN_SMEM_BYTES);

    bias_kernel<<<(RELN + 255) / 256, 256>>>(tbl);

    // split conversions (only harness pointers cross host/device boundary)
    xcvt<<<(MROWS * DM / 4 + 255) / 256, 256>>>(X, 0, MROWS * DM / 4);
    dim3 gw(DM / 32, DM / 32, 4);
    wt_cvt<<<gw, dim3(32, 8)>>>(Wq, Wk, Wv, Wo);

    // QKV projections on tensor cores (mma.sync)
    dim3 g1(DM / 128, MROWS / 128, 3);
    gemm_mma<<<g1, 256>>>(0, 0, nullptr);

    // attention
    dim3 g2(SEQ / BR, BSZ * NH);
    attn_kernel_v2<<<g2, 256, ATTN_SMEM_BYTES>>>();

    // convert attn output, then output projection on tensor cores
    xcvt<<<(MROWS * DM / 4 + 255) / 256, 256>>>(nullptr, 1, MROWS * DM / 4);
    dim3 g3(DM / 128, MROWS / 128, 1);
    gemm_mma<<<g3, 256>>>(3, 1, out);
}

// round 7
// speedup vs baseline: 3.1913x; 1.6307x over previous
#include <cuda_runtime.h>
#include <cuda_bf16.h>
#include <math.h>
#include <stdint.h>

#define BSZ   2
#define SEQ   2048
#define DM    1024
#define NH    16
#define DK    64
#define RELN  (2*SEQ-1)   // 4095
#define MROWS (BSZ*SEQ)   // 4096

// ---------------- scratch (device globals; device-code access only) --------
__device__ float g_q[BSZ*NH*SEQ*DK];     // [b][h][s][d]
__device__ float g_k[BSZ*NH*SEQ*DK];
__device__ float g_v[BSZ*NH*SEQ*DK];
__device__ float g_attn[BSZ*SEQ*DM];     // [b*S+s][h*64+d]
__device__ float g_bias[NH*RELN];        // [h][rel + S-1]

__device__ __nv_bfloat16 g_xhi[MROWS*DM];
__device__ __nv_bfloat16 g_xlo[MROWS*DM];
__device__ __nv_bfloat16 g_wth[4*DM*DM];    // W^T hi: [w][n][k]
__device__ __nv_bfloat16 g_wtl[4*DM*DM];    // W^T lo

// ======================= mma.sync helpers ====================================
__device__ __forceinline__ void mma_bf16(float acc[4], const uint32_t a[4],
                                         const uint32_t b[2]) {
    asm volatile(
        "mma.sync.aligned.m16n8k16.row.col.f32.bf16.bf16.f32 "
        "{%0,%1,%2,%3}, {%4,%5,%6,%7}, {%8,%9}, {%0,%1,%2,%3};"
        : "+f"(acc[0]), "+f"(acc[1]), "+f"(acc[2]), "+f"(acc[3])
        : "r"(a[0]), "r"(a[1]), "r"(a[2]), "r"(a[3]), "r"(b[0]), "r"(b[1]));
}
__device__ __forceinline__ uint32_t packbf(float a, float b) {
    __nv_bfloat162 t;
    t.x = __float2bfloat16_rn(a);
    t.y = __float2bfloat16_rn(b);
    return *(uint32_t*)&t;
}
__device__ __forceinline__ void pack_hilo(float a, float b,
                                          uint32_t& hi, uint32_t& lo) {
    __nv_bfloat16 ha = __float2bfloat16_rn(a);
    __nv_bfloat16 hb = __float2bfloat16_rn(b);
    __nv_bfloat162 th; th.x = ha; th.y = hb;
    hi = *(uint32_t*)&th;
    lo = packbf(a - __bfloat162float(ha), b - __bfloat162float(hb));
}

// ---------------- relative-position bias precompute -------------------------
__global__ void bias_kernel(const float* __restrict__ table) {
    int idx = blockIdx.x * blockDim.x + threadIdx.x;
    if (idx >= RELN) return;
    int rel = idx - (SEQ - 1);
    int bucket = (rel > 0) ? 16 : 0;
    int rabs = rel < 0 ? -rel : rel;
    int add;
    if (rabs < 8) {
        add = rabs;
    } else {
        double lf = log((double)rabs / 8.0) / log(16.0) * 8.0;
        add = 8 + (int)lf;
        if (add > 15) add = 15;
    }
    bucket += add;
#pragma unroll
    for (int h = 0; h < NH; h++)
        g_bias[h * RELN + idx] = table[bucket * NH + h];
}

// ---------------- fp32 -> (hi,lo) bf16 split --------------------------------
__global__ __launch_bounds__(256) void xcvt(const float* __restrict__ in,
                                            int use_attn, int n4) {
    int i = blockIdx.x * blockDim.x + threadIdx.x;
    if (i >= n4) return;
    const float* src = use_attn ? (const float*)g_attn : in;
    float4 x = ((const float4*)src)[i];
    float xs[4] = {x.x, x.y, x.z, x.w};
    __nv_bfloat16 hb[4], lb[4];
#pragma unroll
    for (int j = 0; j < 4; j++) {
        hb[j] = __float2bfloat16_rn(xs[j]);
        lb[j] = __float2bfloat16_rn(xs[j] - __bfloat162float(hb[j]));
    }
    *(uint2*)&g_xhi[i * 4] = *(uint2*)hb;
    *(uint2*)&g_xlo[i * 4] = *(uint2*)lb;
}

// ---------------- W [K][N] -> W^T (hi,lo) bf16 [N][K] -----------------------
__global__ __launch_bounds__(256) void wt_cvt(const float* __restrict__ Wq,
                                              const float* __restrict__ Wk,
                                              const float* __restrict__ Wv,
                                              const float* __restrict__ Wo) {
    __shared__ float tile[32][33];
    int w = blockIdx.z;
    const float* W = (w == 0) ? Wq : (w == 1) ? Wk : (w == 2) ? Wv : Wo;
    int kb = blockIdx.y * 32, nb = blockIdx.x * 32;
    int tx = threadIdx.x, ty = threadIdx.y;
    for (int r = ty; r < 32; r += 8)
        tile[r][tx] = W[(size_t)(kb + r) * DM + nb + tx];
    __syncthreads();
    __nv_bfloat16* oh = g_wth + (size_t)w * DM * DM;
    __nv_bfloat16* ol = g_wtl + (size_t)w * DM * DM;
    for (int r = ty; r < 32; r += 8) {
        float x = tile[tx][r];
        __nv_bfloat16 h = __float2bfloat16_rn(x);
        __nv_bfloat16 l = __float2bfloat16_rn(x - __bfloat162float(h));
        size_t o = (size_t)(nb + r) * DM + kb + tx;
        oh[o] = h;
        ol[o] = l;
    }
}

// ---------------- split-bf16 GEMM via mma.sync (proven) ---------------------
#define A_ELEMS (128*40)
#define AW      2560
#define RSTRIDE 20

__global__ __launch_bounds__(256) void gemm_mma(
    int wbase, int mode, float* __restrict__ outp)
{
    __shared__ __align__(16) __nv_bfloat16 smem[4 * A_ELEMS];
    const uint32_t* SW = (const uint32_t*)smem;

    const int tid = threadIdx.x;
    const int wid = tid >> 5, lane = tid & 31;
    const int wm = wid & 1;
    const int wn = wid >> 1;
    const int fr = lane >> 2;
    const int fc = lane & 3;

    const int w  = wbase + blockIdx.z;
    const int m0 = blockIdx.y * 128;
    const int n0 = blockIdx.x * 128;
    const __nv_bfloat16* __restrict__ ah = g_xhi;
    const __nv_bfloat16* __restrict__ al = g_xlo;
    const __nv_bfloat16* __restrict__ bh = g_wth + (size_t)w * DM * DM;
    const __nv_bfloat16* __restrict__ bl = g_wtl + (size_t)w * DM * DM;

    float acc[4][4][4];
#pragma unroll
    for (int i = 0; i < 4; i++)
#pragma unroll
        for (int j = 0; j < 4; j++)
#pragma unroll
            for (int q = 0; q < 4; q++) acc[i][j][q] = 0.f;

    for (int c = 0; c < 32; c++) {
        const int k0 = c * 32;
        __syncthreads();
#pragma unroll
        for (int i = 0; i < 4; i++) {
            int idx = tid + i * 256;
            int sel = idx >> 9, r = (idx >> 2) & 127, j = idx & 3;
            const __nv_bfloat16* src =
                (sel ? al : ah) + (size_t)(m0 + r) * DM + k0 + j * 8;
            *(uint4*)(smem + sel * A_ELEMS + r * 40 + j * 8) =
                *(const uint4*)src;
        }
#pragma unroll
        for (int i = 0; i < 4; i++) {
            int idx = tid + i * 256;
            int sel = idx >> 9, r = (idx >> 2) & 127, j = idx & 3;
            const __nv_bfloat16* src =
                (sel ? bl : bh) + (size_t)(n0 + r) * DM + k0 + j * 8;
            *(uint4*)(smem + 2 * A_ELEMS + sel * A_ELEMS + r * 40 + j * 8) =
                *(const uint4*)src;
        }
        __syncthreads();

#pragma unroll
        for (int ks = 0; ks < 2; ks++) {
            const int kw = ks * 8;
            uint32_t Ahf[4][4], Alf[4][4], Bf[4][2];
#pragma unroll
            for (int mf = 0; mf < 4; mf++) {
                int base = (wm * 64 + mf * 16 + fr) * RSTRIDE + kw + fc;
                Ahf[mf][0] = SW[base];
                Ahf[mf][1] = SW[base + 8 * RSTRIDE];
                Ahf[mf][2] = SW[base + 4];
                Ahf[mf][3] = SW[base + 8 * RSTRIDE + 4];
            }
#pragma unroll
            for (int nf = 0; nf < 4; nf++) {
                int nb = (wn * 32 + nf * 8 + fr) * RSTRIDE + kw + fc;
                Bf[nf][0] = SW[2 * AW + nb];
                Bf[nf][1] = SW[2 * AW + nb + 4];
            }
#pragma unroll
            for (int mf = 0; mf < 4; mf++)
#pragma unroll
                for (int nf = 0; nf < 4; nf++)
                    mma_bf16(acc[mf][nf], Ahf[mf], Bf[nf]);
#pragma unroll
            for (int mf = 0; mf < 4; mf++) {
                int base = AW + (wm * 64 + mf * 16 + fr) * RSTRIDE + kw + fc;
                Alf[mf][0] = SW[base];
                Alf[mf][1] = SW[base + 8 * RSTRIDE];
                Alf[mf][2] = SW[base + 4];
                Alf[mf][3] = SW[base + 8 * RSTRIDE + 4];
            }
#pragma unroll
            for (int mf = 0; mf < 4; mf++)
#pragma unroll
                for (int nf = 0; nf < 4; nf++)
                    mma_bf16(acc[mf][nf], Alf[mf], Bf[nf]);
#pragma unroll
            for (int nf = 0; nf < 4; nf++) {
                int nb = (wn * 32 + nf * 8 + fr) * RSTRIDE + kw + fc;
                Bf[nf][0] = SW[3 * AW + nb];
                Bf[nf][1] = SW[3 * AW + nb + 4];
            }
#pragma unroll
            for (int mf = 0; mf < 4; mf++)
#pragma unroll
                for (int nf = 0; nf < 4; nf++)
                    mma_bf16(acc[mf][nf], Ahf[mf], Bf[nf]);
        }
    }

#pragma unroll
    for (int mf = 0; mf < 4; mf++) {
        int row = m0 + wm * 64 + mf * 16 + fr;
#pragma unroll
        for (int nf = 0; nf < 4; nf++) {
            int n = n0 + wn * 32 + nf * 8 + fc * 2;
            float2 v0 = make_float2(acc[mf][nf][0], acc[mf][nf][1]);
            float2 v1 = make_float2(acc[mf][nf][2], acc[mf][nf][3]);
            if (mode == 0) {
                float* dst = (w == 0) ? g_q : (w == 1) ? g_k : g_v;
                int h = n >> 6, d = n & 63;
                int b = row >> 11, s = row & (SEQ - 1);
                size_t base = (((size_t)(b * NH + h) * SEQ + s) * DK) + d;
                *(float2*)(dst + base) = v0;
                *(float2*)(dst + base + 8 * DK) = v1;
            } else {
                *(float2*)(outp + (size_t)row * DM + n) = v0;
                *(float2*)(outp + (size_t)(row + 8) * DM + n) = v1;
            }
        }
    }
}

// ---------------- flash attention via mma.sync ------------------------------
// Block: 256 thr = 8 warps; warp w owns q-rows [16w,16w+16), full 128-col tile.
// Smem word layout: K hi [128][36], K lo [128][36], Vt hi [64][68],
// Vt lo [64][68], bias window [256].
#define KSTR 36
#define VSTR 68
#define KWH_OFF 0
#define KWL_OFF (128*KSTR)             // 4608
#define VTH_OFF (2*128*KSTR)           // 9216
#define VTL_OFF (VTH_OFF + 64*VSTR)    // 13568
#define SB_OFF  (VTH_OFF + 2*64*VSTR)  // 17920
#define ATTN3_BYTES ((SB_OFF + 256) * 4)   // 72704

__global__ __launch_bounds__(256, 1) void attn_mma() {
    extern __shared__ __align__(16) uint32_t SW3[];
    float* Sb = (float*)(SW3 + SB_OFF);

    const int bh = blockIdx.y;
    const int h = bh & (NH - 1);
    const int b = bh >> 4;
    const int q0 = blockIdx.x * 128;
    const float* __restrict__ Qg = g_q + (size_t)bh * SEQ * DK;
    const float* __restrict__ Kg = g_k + (size_t)bh * SEQ * DK;
    const float* __restrict__ Vg = g_v + (size_t)bh * SEQ * DK;

    const int tid = threadIdx.x;
    const int wid = tid >> 5, lane = tid & 31;
    const int fr = lane >> 2, fc = lane & 3;

    // ---- stage Q into K buffer, extract register fragments ----
#pragma unroll
    for (int i = 0; i < 8; i++) {
        int idx = tid + i * 256;
        int r = idx >> 4, j = idx & 15;
        float4 v = *(const float4*)(Qg + (size_t)(q0 + r) * DK + j * 4);
        uint32_t h0, l0, h1, l1;
        pack_hilo(v.x, v.y, h0, l0);
        pack_hilo(v.z, v.w, h1, l1);
        SW3[KWH_OFF + r * KSTR + 2 * j]     = h0;
        SW3[KWH_OFF + r * KSTR + 2 * j + 1] = h1;
        SW3[KWL_OFF + r * KSTR + 2 * j]     = l0;
        SW3[KWL_OFF + r * KSTR + 2 * j + 1] = l1;
    }
    __syncthreads();
    uint32_t Qh[4][4], Ql[4][4];
#pragma unroll
    for (int ks = 0; ks < 4; ks++) {
        int base = (16 * wid + fr) * KSTR + ks * 8 + fc;
        Qh[ks][0] = SW3[KWH_OFF + base];
        Qh[ks][1] = SW3[KWH_OFF + base + 8 * KSTR];
        Qh[ks][2] = SW3[KWH_OFF + base + 4];
        Qh[ks][3] = SW3[KWH_OFF + base + 8 * KSTR + 4];
        Ql[ks][0] = SW3[KWL_OFF + base];
        Ql[ks][1] = SW3[KWL_OFF + base + 8 * KSTR];
        Ql[ks][2] = SW3[KWL_OFF + base + 4];
        Ql[ks][3] = SW3[KWL_OFF + base + 8 * KSTR + 4];
    }

    float Oa[8][4];
#pragma unroll
    for (int i = 0; i < 8; i++)
#pragma unroll
        for (int q = 0; q < 4; q++) Oa[i][q] = 0.f;
    float m_a = -1e30f, m_b = -1e30f, l_a = 0.f, l_b = 0.f;

    const int sboff = 2 * fc - 16 * wid - fr + 128;   // Sb idx for (row a, col0)

    for (int k0 = 0; k0 < SEQ; k0 += 128) {
        __syncthreads();   // Q-frag extraction done / prev tile consumed

        // ---- K tile -> [row][kword] hi/lo ----
#pragma unroll
        for (int i = 0; i < 8; i++) {
            int idx = tid + i * 256;
            int r = idx >> 4, j = idx & 15;
            float4 v = *(const float4*)(Kg + (size_t)(k0 + r) * DK + j * 4);
            uint32_t h0, l0, h1, l1;
            pack_hilo(v.x, v.y, h0, l0);
            pack_hilo(v.z, v.w, h1, l1);
            SW3[KWH_OFF + r * KSTR + 2 * j]     = h0;
            SW3[KWH_OFF + r * KSTR + 2 * j + 1] = h1;
            SW3[KWL_OFF + r * KSTR + 2 * j]     = l0;
            SW3[KWL_OFF + r * KSTR + 2 * j + 1] = l1;
        }
        // ---- V tile -> transposed [d][cword] hi/lo ----
#pragma unroll
        for (int i = 0; i < 4; i++) {
            int t = tid + i * 256;
            int u = t & 63, jg = t >> 6;
            float4 v0 = *(const float4*)(Vg + (size_t)(k0 + 2 * u) * DK + jg * 4);
            float4 v1 = *(const float4*)(Vg + (size_t)(k0 + 2 * u + 1) * DK + jg * 4);
            float a0[4] = {v0.x, v0.y, v0.z, v0.w};
            float a1[4] = {v1.x, v1.y, v1.z, v1.w};
#pragma unroll
            for (int dd = 0; dd < 4; dd++) {
                uint32_t hw, lw;
                pack_hilo(a0[dd], a1[dd], hw, lw);
                int d = jg * 4 + dd;
                SW3[VTH_OFF + d * VSTR + u] = hw;
                SW3[VTL_OFF + d * VSTR + u] = lw;
            }
        }
        // ---- bias window ----
        if (tid < 256) {
            int gi = 2047 + k0 - q0 + tid - 128;
            gi = gi < 0 ? 0 : gi;
            Sb[tid] = g_bias[h * RELN + gi];
        }
        __syncthreads();

        // ---- phase 1: S = Q K^T (3-term split) ----
        float sc[16][4];
#pragma unroll
        for (int nf = 0; nf < 16; nf++)
#pragma unroll
            for (int q = 0; q < 4; q++) sc[nf][q] = 0.f;

#pragma unroll
        for (int ks = 0; ks < 4; ks++) {
            const int kw = ks * 8 + fc;
#pragma unroll
            for (int nf = 0; nf < 16; nf++) {
                int nb = (nf * 8 + fr) * KSTR + kw;
                uint32_t bf[2] = {SW3[KWH_OFF + nb], SW3[KWH_OFF + nb + 4]};
                mma_bf16(sc[nf], Qh[ks], bf);
            }
#pragma unroll
            for (int nf = 0; nf < 16; nf++) {
                int nb = (nf * 8 + fr) * KSTR + kw;
                uint32_t bf[2] = {SW3[KWH_OFF + nb], SW3[KWH_OFF + nb + 4]};
                mma_bf16(sc[nf], Ql[ks], bf);
            }
#pragma unroll
            for (int nf = 0; nf < 16; nf++) {
                int nb = (nf * 8 + fr) * KSTR + kw;
                uint32_t bf[2] = {SW3[KWL_OFF + nb], SW3[KWL_OFF + nb + 4]};
                mma_bf16(sc[nf], Qh[ks], bf);
            }
        }

        // ---- bias add (row b at nf reuses row a's nf-1 values) ----
        float pb0 = Sb[sboff - 8], pb1 = Sb[sboff - 7];
#pragma unroll
        for (int nf = 0; nf < 16; nf++) {
            float b0 = Sb[sboff + 8 * nf];
            float b1 = Sb[sboff + 8 * nf + 1];
            sc[nf][0] += b0;
            sc[nf][1] += b1;
            sc[nf][2] += pb0;
            sc[nf][3] += pb1;
            pb0 = b0; pb1 = b1;
        }

        // ---- online softmax (two rows per thread) ----
        float mxa = -1e30f, mxb = -1e30f;
#pragma unroll
        for (int nf = 0; nf < 16; nf++) {
            mxa = fmaxf(mxa, fmaxf(sc[nf][0], sc[nf][1]));
            mxb = fmaxf(mxb, fmaxf(sc[nf][2], sc[nf][3]));
        }
        mxa = fmaxf(mxa, __shfl_xor_sync(0xffffffffu, mxa, 1));
        mxa = fmaxf(mxa, __shfl_xor_sync(0xffffffffu, mxa, 2));
        mxb = fmaxf(mxb, __shfl_xor_sync(0xffffffffu, mxb, 1));
        mxb = fmaxf(mxb, __shfl_xor_sync(0xffffffffu, mxb, 2));
        float mna = fmaxf(m_a, mxa), mnb = fmaxf(m_b, mxb);
        float ca = __expf(m_a - mna), cb = __expf(m_b - mnb);
        float sa = 0.f, sb2 = 0.f;
#pragma unroll
        for (int nf = 0; nf < 16; nf++) {
            sc[nf][0] = __expf(sc[nf][0] - mna);
            sc[nf][1] = __expf(sc[nf][1] - mna);
            sc[nf][2] = __expf(sc[nf][2] - mnb);
            sc[nf][3] = __expf(sc[nf][3] - mnb);
            sa  += sc[nf][0] + sc[nf][1];
            sb2 += sc[nf][2] + sc[nf][3];
        }
        sa  += __shfl_xor_sync(0xffffffffu, sa, 1);
        sa  += __shfl_xor_sync(0xffffffffu, sa, 2);
        sb2 += __shfl_xor_sync(0xffffffffu, sb2, 1);
        sb2 += __shfl_xor_sync(0xffffffffu, sb2, 2);
        l_a = l_a * ca + sa;
        l_b = l_b * cb + sb2;
        m_a = mna; m_b = mnb;

        // rescale O
#pragma unroll
        for (int i = 0; i < 8; i++) {
            Oa[i][0] *= ca; Oa[i][1] *= ca;
            Oa[i][2] *= cb; Oa[i][3] *= cb;
        }

        // ---- phase 2: O += P V (3-term split, P direct from registers) ----
#pragma unroll
        for (int ks2 = 0; ks2 < 8; ks2++) {
            uint32_t Ph[4], Pl[4];
            pack_hilo(sc[2*ks2][0],   sc[2*ks2][1],   Ph[0], Pl[0]);
            pack_hilo(sc[2*ks2][2],   sc[2*ks2][3],   Ph[1], Pl[1]);
            pack_hilo(sc[2*ks2+1][0], sc[2*ks2+1][1], Ph[2], Pl[2]);
            pack_hilo(sc[2*ks2+1][2], sc[2*ks2+1][3], Ph[3], Pl[3]);
            const int kw2 = ks2 * 8 + fc;
#pragma unroll
            for (int nf2 = 0; nf2 < 8; nf2++) {
                int nb = (nf2 * 8 + fr) * VSTR + kw2;
                uint32_t bf[2] = {SW3[VTH_OFF + nb], SW3[VTH_OFF + nb + 4]};
                mma_bf16(Oa[nf2], Ph, bf);
            }
#pragma unroll
            for (int nf2 = 0; nf2 < 8; nf2++) {
                int nb = (nf2 * 8 + fr) * VSTR + kw2;
                uint32_t bf[2] = {SW3[VTH_OFF + nb], SW3[VTH_OFF + nb + 4]};
                mma_bf16(Oa[nf2], Pl, bf);
            }
#pragma unroll
            for (int nf2 = 0; nf2 < 8; nf2++) {
                int nb = (nf2 * 8 + fr) * VSTR + kw2;
                uint32_t bf[2] = {SW3[VTL_OFF + nb], SW3[VTL_OFF + nb + 4]};
                mma_bf16(Oa[nf2], Ph, bf);
            }
        }
    }

    // ---- epilogue ----
    float inva = 1.0f / l_a, invb = 1.0f / l_b;
    int ra = q0 + 16 * wid + fr;
#pragma unroll
    for (int nf2 = 0; nf2 < 8; nf2++) {
        int d = nf2 * 8 + 2 * fc;
        float* pa = g_attn + (size_t)(b * SEQ + ra) * DM + h * DK + d;
        float* pb = pa + (size_t)8 * DM;
        *(float2*)pa = make_float2(Oa[nf2][0] * inva, Oa[nf2][1] * inva);
        *(float2*)pb = make_float2(Oa[nf2][2] * invb, Oa[nf2][3] * invb);
    }
}

// ---------------- launch ----------------------------------------------------
extern "C" void kernel_launch(void* const* d_in, const int* in_sizes, int n_in,
                              void* d_out, int out_size) {
    const float* X   = (const float*)d_in[0];
    const float* Wq  = (const float*)d_in[1];
    const float* Wk  = (const float*)d_in[2];
    const float* Wv  = (const float*)d_in[3];
    const float* Wo  = (const float*)d_in[4];
    const float* tbl = (const float*)d_in[5];
    float* out = (float*)d_out;

    cudaFuncSetAttribute(attn_mma,
                         cudaFuncAttributeMaxDynamicSharedMemorySize,
                         ATTN3_BYTES);

    bias_kernel<<<(RELN + 255) / 256, 256>>>(tbl);

    xcvt<<<(MROWS * DM / 4 + 255) / 256, 256>>>(X, 0, MROWS * DM / 4);
    dim3 gw(DM / 32, DM / 32, 4);
    wt_cvt<<<gw, dim3(32, 8)>>>(Wq, Wk, Wv, Wo);

    dim3 g1(DM / 128, MROWS / 128, 3);
    gemm_mma<<<g1, 256>>>(0, 0, nullptr);

    dim3 g2(SEQ / 128, BSZ * NH);
    attn_mma<<<g2, 256, ATTN3_BYTES>>>();

    xcvt<<<(MROWS * DM / 4 + 255) / 256, 256>>>(nullptr, 1, MROWS * DM / 4);
    dim3 g3(DM / 128, MROWS / 128, 1);
    gemm_mma<<<g3, 256>>>(3, 1, out);
}

// round 8
// speedup vs baseline: 3.4929x; 1.0945x over previous
#include <cuda_runtime.h>
#include <cuda_bf16.h>
#include <math.h>
#include <stdint.h>

#define BSZ   2
#define SEQ   2048
#define DM    1024
#define NH    16
#define DK    64
#define RELN  (2*SEQ-1)   // 4095
#define MROWS (BSZ*SEQ)   // 4096

// ---------------- scratch (device globals; device-code access only) --------
__device__ float g_q[BSZ*NH*SEQ*DK];     // [b][h][s][d]
__device__ float g_k[BSZ*NH*SEQ*DK];
__device__ float g_v[BSZ*NH*SEQ*DK];
__device__ float g_bias[NH*RELN];        // [h][rel + S-1]

__device__ __nv_bfloat16 g_xhi[MROWS*DM];   // activations hi/lo (X, then attn out)
__device__ __nv_bfloat16 g_xlo[MROWS*DM];
__device__ __nv_bfloat16 g_wth[4*DM*DM];    // W^T hi: [w][n][k]
__device__ __nv_bfloat16 g_wtl[4*DM*DM];    // W^T lo

// ======================= mma.sync / cp.async helpers ========================
__device__ __forceinline__ void mma_bf16(float acc[4], const uint32_t a[4],
                                         const uint32_t b[2]) {
    asm volatile(
        "mma.sync.aligned.m16n8k16.row.col.f32.bf16.bf16.f32 "
        "{%0,%1,%2,%3}, {%4,%5,%6,%7}, {%8,%9}, {%0,%1,%2,%3};"
        : "+f"(acc[0]), "+f"(acc[1]), "+f"(acc[2]), "+f"(acc[3])
        : "r"(a[0]), "r"(a[1]), "r"(a[2]), "r"(a[3]), "r"(b[0]), "r"(b[1]));
}
__device__ __forceinline__ uint32_t smem_u32(const void* p) {
    uint32_t a;
    asm("{ .reg .u64 t; cvta.to.shared.u64 t, %1; cvt.u32.u64 %0, t; }"
        : "=r"(a) : "l"(p));
    return a;
}
#define CP16(dst, src) \
    asm volatile("cp.async.cg.shared.global [%0], [%1], 16;" \
        :: "r"(dst), "l"(src))
#define CP_COMMIT() asm volatile("cp.async.commit_group;")
#define CP_WAIT(n)  asm volatile("cp.async.wait_group %0;" :: "n"(n))

__device__ __forceinline__ uint32_t packbf(float a, float b) {
    __nv_bfloat162 t;
    t.x = __float2bfloat16_rn(a);
    t.y = __float2bfloat16_rn(b);
    return *(uint32_t*)&t;
}
__device__ __forceinline__ void pack_hilo(float a, float b,
                                          uint32_t& hi, uint32_t& lo) {
    __nv_bfloat16 ha = __float2bfloat16_rn(a);
    __nv_bfloat16 hb = __float2bfloat16_rn(b);
    __nv_bfloat162 th; th.x = ha; th.y = hb;
    hi = *(uint32_t*)&th;
    lo = packbf(a - __bfloat162float(ha), b - __bfloat162float(hb));
}

// ---------------- relative-position bias precompute -------------------------
__global__ void bias_kernel(const float* __restrict__ table) {
    int idx = blockIdx.x * blockDim.x + threadIdx.x;
    if (idx >= RELN) return;
    int rel = idx - (SEQ - 1);
    int bucket = (rel > 0) ? 16 : 0;
    int rabs = rel < 0 ? -rel : rel;
    int add;
    if (rabs < 8) {
        add = rabs;
    } else {
        double lf = log((double)rabs / 8.0) / log(16.0) * 8.0;
        add = 8 + (int)lf;
        if (add > 15) add = 15;
    }
    bucket += add;
#pragma unroll
    for (int h = 0; h < NH; h++)
        g_bias[h * RELN + idx] = table[bucket * NH + h];
}

// ---------------- fp32 X -> (hi,lo) bf16 split -------------------------------
__global__ __launch_bounds__(256) void xcvt(const float* __restrict__ in,
                                            int n4) {
    int i = blockIdx.x * blockDim.x + threadIdx.x;
    if (i >= n4) return;
    float4 x = ((const float4*)in)[i];
    float xs[4] = {x.x, x.y, x.z, x.w};
    __nv_bfloat16 hb[4], lb[4];
#pragma unroll
    for (int j = 0; j < 4; j++) {
        hb[j] = __float2bfloat16_rn(xs[j]);
        lb[j] = __float2bfloat16_rn(xs[j] - __bfloat162float(hb[j]));
    }
    *(uint2*)&g_xhi[i * 4] = *(uint2*)hb;
    *(uint2*)&g_xlo[i * 4] = *(uint2*)lb;
}

// ---------------- W [K][N] -> W^T (hi,lo) bf16 [N][K] -----------------------
__global__ __launch_bounds__(256) void wt_cvt(const float* __restrict__ Wq,
                                              const float* __restrict__ Wk,
                                              const float* __restrict__ Wv,
                                              const float* __restrict__ Wo) {
    __shared__ float tile[32][33];
    int w = blockIdx.z;
    const float* W = (w == 0) ? Wq : (w == 1) ? Wk : (w == 2) ? Wv : Wo;
    int kb = blockIdx.y * 32, nb = blockIdx.x * 32;
    int tx = threadIdx.x, ty = threadIdx.y;
    for (int r = ty; r < 32; r += 8)
        tile[r][tx] = W[(size_t)(kb + r) * DM + nb + tx];
    __syncthreads();
    __nv_bfloat16* oh = g_wth + (size_t)w * DM * DM;
    __nv_bfloat16* ol = g_wtl + (size_t)w * DM * DM;
    for (int r = ty; r < 32; r += 8) {
        float x = tile[tx][r];
        __nv_bfloat16 h = __float2bfloat16_rn(x);
        __nv_bfloat16 l = __float2bfloat16_rn(x - __bfloat162float(h));
        size_t o = (size_t)(nb + r) * DM + kb + tx;
        oh[o] = h;
        ol[o] = l;
    }
}

// ---------------- split-bf16 GEMM, cp.async double-buffered -----------------
// C[128 x 128] per block, K=1024 in 32 chunks of 32. 8 warps = 2(m) x 4(n).
// Smem slot = {A hi, A lo, B hi, B lo} each [128][40] bf16 (stride-20 words).
#define A_ELEMS  (128*40)          // bf16 per region
#define AW       2560              // words per region
#define RSTRIDE  20                // words per row
#define SLOT_W   (4*AW)            // 10240 words per slot
#define GEMM_SMEM_BYTES (2*SLOT_W*4)   // 81920

__global__ __launch_bounds__(256) void gemm_mma(
    int wbase, int mode, float* __restrict__ outp)
{
    extern __shared__ __align__(16) uint32_t gsm[];

    const int tid = threadIdx.x;
    const int wid = tid >> 5, lane = tid & 31;
    const int wm = wid & 1;
    const int wn = wid >> 1;
    const int fr = lane >> 2;
    const int fc = lane & 3;

    const int w  = wbase + blockIdx.z;
    const int m0 = blockIdx.y * 128;
    const int n0 = blockIdx.x * 128;
    const __nv_bfloat16* __restrict__ ah = g_xhi;
    const __nv_bfloat16* __restrict__ al = g_xlo;
    const __nv_bfloat16* __restrict__ bh = g_wth + (size_t)w * DM * DM;
    const __nv_bfloat16* __restrict__ bl = g_wtl + (size_t)w * DM * DM;

    // per-thread load descriptors (8 x 16B per chunk)
    const __nv_bfloat16* asrc[4];
    const __nv_bfloat16* bsrc[4];
    uint32_t adst[4], bdst[4];
    const uint32_t sb0 = smem_u32(gsm);
#pragma unroll
    for (int i = 0; i < 4; i++) {
        int idx = tid + i * 256;
        int sel = idx >> 9, r = (idx >> 2) & 127, j = idx & 3;
        asrc[i] = (sel ? al : ah) + (size_t)(m0 + r) * DM + j * 8;
        adst[i] = sb0 + (uint32_t)(sel * A_ELEMS + r * 40 + j * 8) * 2;
        bsrc[i] = (sel ? bl : bh) + (size_t)(n0 + r) * DM + j * 8;
        bdst[i] = sb0 + (uint32_t)(2 * A_ELEMS + sel * A_ELEMS + r * 40 + j * 8) * 2;
    }

    float acc[4][4][4];
#pragma unroll
    for (int i = 0; i < 4; i++)
#pragma unroll
        for (int j = 0; j < 4; j++)
#pragma unroll
            for (int q = 0; q < 4; q++) acc[i][j][q] = 0.f;

    // prologue: prefetch chunk 0 into slot 0
#pragma unroll
    for (int i = 0; i < 4; i++) {
        CP16(adst[i], asrc[i]);
        CP16(bdst[i], bsrc[i]);
    }
    CP_COMMIT();

    for (int c = 0; c < 32; c++) {
        // prefetch next chunk into the other slot
        if (c < 31) {
            const int k1 = (c + 1) * 32;
            const uint32_t so = ((c + 1) & 1) * (SLOT_W * 4);
#pragma unroll
            for (int i = 0; i < 4; i++) {
                CP16(adst[i] + so, asrc[i] + k1);
                CP16(bdst[i] + so, bsrc[i] + k1);
            }
            CP_COMMIT();
            CP_WAIT(1);
        } else {
            CP_WAIT(0);
        }
        __syncthreads();

        const uint32_t* SW = gsm + (c & 1) * SLOT_W;
#pragma unroll
        for (int ks = 0; ks < 2; ks++) {
            const int kw = ks * 8;
            uint32_t Ahf[4][4], Alf[4][4], Bf[4][2];
#pragma unroll
            for (int mf = 0; mf < 4; mf++) {
                int base = (wm * 64 + mf * 16 + fr) * RSTRIDE + kw + fc;
                Ahf[mf][0] = SW[base];
                Ahf[mf][1] = SW[base + 8 * RSTRIDE];
                Ahf[mf][2] = SW[base + 4];
                Ahf[mf][3] = SW[base + 8 * RSTRIDE + 4];
            }
#pragma unroll
            for (int nf = 0; nf < 4; nf++) {
                int nb = (wn * 32 + nf * 8 + fr) * RSTRIDE + kw + fc;
                Bf[nf][0] = SW[2 * AW + nb];
                Bf[nf][1] = SW[2 * AW + nb + 4];
            }
#pragma unroll
            for (int mf = 0; mf < 4; mf++)
#pragma unroll
                for (int nf = 0; nf < 4; nf++)
                    mma_bf16(acc[mf][nf], Ahf[mf], Bf[nf]);   // hi*hi
#pragma unroll
            for (int mf = 0; mf < 4; mf++) {
                int base = AW + (wm * 64 + mf * 16 + fr) * RSTRIDE + kw + fc;
                Alf[mf][0] = SW[base];
                Alf[mf][1] = SW[base + 8 * RSTRIDE];
                Alf[mf][2] = SW[base + 4];
                Alf[mf][3] = SW[base + 8 * RSTRIDE + 4];
            }
#pragma unroll
            for (int mf = 0; mf < 4; mf++)
#pragma unroll
                for (int nf = 0; nf < 4; nf++)
                    mma_bf16(acc[mf][nf], Alf[mf], Bf[nf]);   // lo*hi
#pragma unroll
            for (int nf = 0; nf < 4; nf++) {
                int nb = (wn * 32 + nf * 8 + fr) * RSTRIDE + kw + fc;
                Bf[nf][0] = SW[3 * AW + nb];
                Bf[nf][1] = SW[3 * AW + nb + 4];
            }
#pragma unroll
            for (int mf = 0; mf < 4; mf++)
#pragma unroll
                for (int nf = 0; nf < 4; nf++)
                    mma_bf16(acc[mf][nf], Ahf[mf], Bf[nf]);   // hi*lo
        }
        __syncthreads();   // protect slot being prefetched next iteration
    }

    // ---- epilogue ----
#pragma unroll
    for (int mf = 0; mf < 4; mf++) {
        int row = m0 + wm * 64 + mf * 16 + fr;
#pragma unroll
        for (int nf = 0; nf < 4; nf++) {
            int n = n0 + wn * 32 + nf * 8 + fc * 2;
            float2 v0 = make_float2(acc[mf][nf][0], acc[mf][nf][1]);
            float2 v1 = make_float2(acc[mf][nf][2], acc[mf][nf][3]);
            if (mode == 0) {
                float* dst = (w == 0) ? g_q : (w == 1) ? g_k : g_v;
                int h = n >> 6, d = n & 63;
                int b = row >> 11, s = row & (SEQ - 1);
                size_t base = (((size_t)(b * NH + h) * SEQ + s) * DK) + d;
                *(float2*)(dst + base) = v0;
                *(float2*)(dst + base + 8 * DK) = v1;
            } else {
                *(float2*)(outp + (size_t)row * DM + n) = v0;
                *(float2*)(outp + (size_t)(row + 8) * DM + n) = v1;
            }
        }
    }
}

// ---------------- flash attention via mma.sync ------------------------------
#define KSTR 36
#define VSTR 68
#define KWH_OFF 0
#define KWL_OFF (128*KSTR)
#define VTH_OFF (2*128*KSTR)
#define VTL_OFF (VTH_OFF + 64*VSTR)
#define SB_OFF  (VTH_OFF + 2*64*VSTR)
#define ATTN3_BYTES ((SB_OFF + 256) * 4)

__global__ __launch_bounds__(256, 1) void attn_mma() {
    extern __shared__ __align__(16) uint32_t SW3[];
    float* Sb = (float*)(SW3 + SB_OFF);

    const int bh = blockIdx.y;
    const int h = bh & (NH - 1);
    const int b = bh >> 4;
    const int q0 = blockIdx.x * 128;
    const float* __restrict__ Qg = g_q + (size_t)bh * SEQ * DK;
    const float* __restrict__ Kg = g_k + (size_t)bh * SEQ * DK;
    const float* __restrict__ Vg = g_v + (size_t)bh * SEQ * DK;

    const int tid = threadIdx.x;
    const int wid = tid >> 5, lane = tid & 31;
    const int fr = lane >> 2, fc = lane & 3;

#pragma unroll
    for (int i = 0; i < 8; i++) {
        int idx = tid + i * 256;
        int r = idx >> 4, j = idx & 15;
        float4 v = *(const float4*)(Qg + (size_t)(q0 + r) * DK + j * 4);
        uint32_t h0, l0, h1, l1;
        pack_hilo(v.x, v.y, h0, l0);
        pack_hilo(v.z, v.w, h1, l1);
        SW3[KWH_OFF + r * KSTR + 2 * j]     = h0;
        SW3[KWH_OFF + r * KSTR + 2 * j + 1] = h1;
        SW3[KWL_OFF + r * KSTR + 2 * j]     = l0;
        SW3[KWL_OFF + r * KSTR + 2 * j + 1] = l1;
    }
    __syncthreads();
    uint32_t Qh[4][4], Ql[4][4];
#pragma unroll
    for (int ks = 0; ks < 4; ks++) {
        int base = (16 * wid + fr) * KSTR + ks * 8 + fc;
        Qh[ks][0] = SW3[KWH_OFF + base];
        Qh[ks][1] = SW3[KWH_OFF + base + 8 * KSTR];
        Qh[ks][2] = SW3[KWH_OFF + base + 4];
        Qh[ks][3] = SW3[KWH_OFF + base + 8 * KSTR + 4];
        Ql[ks][0] = SW3[KWL_OFF + base];
        Ql[ks][1] = SW3[KWL_OFF + base + 8 * KSTR];
        Ql[ks][2] = SW3[KWL_OFF + base + 4];
        Ql[ks][3] = SW3[KWL_OFF + base + 8 * KSTR + 4];
    }

    float Oa[8][4];
#pragma unroll
    for (int i = 0; i < 8; i++)
#pragma unroll
        for (int q = 0; q < 4; q++) Oa[i][q] = 0.f;
    float m_a = -1e30f, m_b = -1e30f, l_a = 0.f, l_b = 0.f;

    const int sboff = 2 * fc - 16 * wid - fr + 128;

    for (int k0 = 0; k0 < SEQ; k0 += 128) {
        __syncthreads();

#pragma unroll
        for (int i = 0; i < 8; i++) {
            int idx = tid + i * 256;
            int r = idx >> 4, j = idx & 15;
            float4 v = *(const float4*)(Kg + (size_t)(k0 + r) * DK + j * 4);
            uint32_t h0, l0, h1, l1;
            pack_hilo(v.x, v.y, h0, l0);
            pack_hilo(v.z, v.w, h1, l1);
            SW3[KWH_OFF + r * KSTR + 2 * j]     = h0;
            SW3[KWH_OFF + r * KSTR + 2 * j + 1] = h1;
            SW3[KWL_OFF + r * KSTR + 2 * j]     = l0;
            SW3[KWL_OFF + r * KSTR + 2 * j + 1] = l1;
        }
#pragma unroll
        for (int i = 0; i < 4; i++) {
            int t = tid + i * 256;
            int u = t & 63, jg = t >> 6;
            float4 v0 = *(const float4*)(Vg + (size_t)(k0 + 2 * u) * DK + jg * 4);
            float4 v1 = *(const float4*)(Vg + (size_t)(k0 + 2 * u + 1) * DK + jg * 4);
            float a0[4] = {v0.x, v0.y, v0.z, v0.w};
            float a1[4] = {v1.x, v1.y, v1.z, v1.w};
#pragma unroll
            for (int dd = 0; dd < 4; dd++) {
                uint32_t hw, lw;
                pack_hilo(a0[dd], a1[dd], hw, lw);
                int d = jg * 4 + dd;
                SW3[VTH_OFF + d * VSTR + u] = hw;
                SW3[VTL_OFF + d * VSTR + u] = lw;
            }
        }
        if (tid < 256) {
            int gi = 2047 + k0 - q0 + tid - 128;
            gi = gi < 0 ? 0 : gi;
            Sb[tid] = g_bias[h * RELN + gi];
        }
        __syncthreads();

        float sc[16][4];
#pragma unroll
        for (int nf = 0; nf < 16; nf++)
#pragma unroll
            for (int q = 0; q < 4; q++) sc[nf][q] = 0.f;

#pragma unroll
        for (int ks = 0; ks < 4; ks++) {
            const int kw = ks * 8 + fc;
#pragma unroll
            for (int nf = 0; nf < 16; nf++) {
                int nb = (nf * 8 + fr) * KSTR + kw;
                uint32_t bf[2] = {SW3[KWH_OFF + nb], SW3[KWH_OFF + nb + 4]};
                mma_bf16(sc[nf], Qh[ks], bf);
            }
#pragma unroll
            for (int nf = 0; nf < 16; nf++) {
                int nb = (nf * 8 + fr) * KSTR + kw;
                uint32_t bf[2] = {SW3[KWH_OFF + nb], SW3[KWH_OFF + nb + 4]};
                mma_bf16(sc[nf], Ql[ks], bf);
            }
#pragma unroll
            for (int nf = 0; nf < 16; nf++) {
                int nb = (nf * 8 + fr) * KSTR + kw;
                uint32_t bf[2] = {SW3[KWL_OFF + nb], SW3[KWL_OFF + nb + 4]};
                mma_bf16(sc[nf], Qh[ks], bf);
            }
        }

        float pb0 = Sb[sboff - 8], pb1 = Sb[sboff - 7];
#pragma unroll
        for (int nf = 0; nf < 16; nf++) {
            float b0 = Sb[sboff + 8 * nf];
            float b1 = Sb[sboff + 8 * nf + 1];
            sc[nf][0] += b0;
            sc[nf][1] += b1;
            sc[nf][2] += pb0;
            sc[nf][3] += pb1;
            pb0 = b0; pb1 = b1;
        }

        float mxa = -1e30f, mxb = -1e30f;
#pragma unroll
        for (int nf = 0; nf < 16; nf++) {
            mxa = fmaxf(mxa, fmaxf(sc[nf][0], sc[nf][1]));
            mxb = fmaxf(mxb, fmaxf(sc[nf][2], sc[nf][3]));
        }
        mxa = fmaxf(mxa, __shfl_xor_sync(0xffffffffu, mxa, 1));
        mxa = fmaxf(mxa, __shfl_xor_sync(0xffffffffu, mxa, 2));
        mxb = fmaxf(mxb, __shfl_xor_sync(0xffffffffu, mxb, 1));
        mxb = fmaxf(mxb, __shfl_xor_sync(0xffffffffu, mxb, 2));
        float mna = fmaxf(m_a, mxa), mnb = fmaxf(m_b, mxb);
        float ca = __expf(m_a - mna), cb = __expf(m_b - mnb);
        float sa = 0.f, sb2 = 0.f;
#pragma unroll
        for (int nf = 0; nf < 16; nf++) {
            sc[nf][0] = __expf(sc[nf][0] - mna);
            sc[nf][1] = __expf(sc[nf][1] - mna);
            sc[nf][2] = __expf(sc[nf][2] - mnb);
            sc[nf][3] = __expf(sc[nf][3] - mnb);
            sa  += sc[nf][0] + sc[nf][1];
            sb2 += sc[nf][2] + sc[nf][3];
        }
        sa  += __shfl_xor_sync(0xffffffffu, sa, 1);
        sa  += __shfl_xor_sync(0xffffffffu, sa, 2);
        sb2 += __shfl_xor_sync(0xffffffffu, sb2, 1);
        sb2 += __shfl_xor_sync(0xffffffffu, sb2, 2);
        l_a = l_a * ca + sa;
        l_b = l_b * cb + sb2;
        m_a = mna; m_b = mnb;

#pragma unroll
        for (int i = 0; i < 8; i++) {
            Oa[i][0] *= ca; Oa[i][1] *= ca;
            Oa[i][2] *= cb; Oa[i][3] *= cb;
        }

#pragma unroll
        for (int ks2 = 0; ks2 < 8; ks2++) {
            uint32_t Ph[4], Pl[4];
            pack_hilo(sc[2*ks2][0],   sc[2*ks2][1],   Ph[0], Pl[0]);
            pack_hilo(sc[2*ks2][2],   sc[2*ks2][3],   Ph[1], Pl[1]);
            pack_hilo(sc[2*ks2+1][0], sc[2*ks2+1][1], Ph[2], Pl[2]);
            pack_hilo(sc[2*ks2+1][2], sc[2*ks2+1][3], Ph[3], Pl[3]);
            const int kw2 = ks2 * 8 + fc;
#pragma unroll
            for (int nf2 = 0; nf2 < 8; nf2++) {
                int nb = (nf2 * 8 + fr) * VSTR + kw2;
                uint32_t bf[2] = {SW3[VTH_OFF + nb], SW3[VTH_OFF + nb + 4]};
                mma_bf16(Oa[nf2], Ph, bf);
            }
#pragma unroll
            for (int nf2 = 0; nf2 < 8; nf2++) {
                int nb = (nf2 * 8 + fr) * VSTR + kw2;
                uint32_t bf[2] = {SW3[VTH_OFF + nb], SW3[VTH_OFF + nb + 4]};
                mma_bf16(Oa[nf2], Pl, bf);
            }
#pragma unroll
            for (int nf2 = 0; nf2 < 8; nf2++) {
                int nb = (nf2 * 8 + fr) * VSTR + kw2;
                uint32_t bf[2] = {SW3[VTL_OFF + nb], SW3[VTL_OFF + nb + 4]};
                mma_bf16(Oa[nf2], Ph, bf);
            }
        }
    }

    // ---- epilogue: write hi/lo bf16 straight into g_xhi/g_xlo --------------
    float inva = 1.0f / l_a, invb = 1.0f / l_b;
    int ra = q0 + 16 * wid + fr;
#pragma unroll
    for (int nf2 = 0; nf2 < 8; nf2++) {
        int d = nf2 * 8 + 2 * fc;
        size_t ia = (size_t)(b * SEQ + ra) * DM + h * DK + d;
        size_t ib = ia + (size_t)8 * DM;
        uint32_t hw, lw;
        pack_hilo(Oa[nf2][0] * inva, Oa[nf2][1] * inva, hw, lw);
        *(uint32_t*)&g_xhi[ia] = hw;
        *(uint32_t*)&g_xlo[ia] = lw;
        pack_hilo(Oa[nf2][2] * invb, Oa[nf2][3] * invb, hw, lw);
        *(uint32_t*)&g_xhi[ib] = hw;
        *(uint32_t*)&g_xlo[ib] = lw;
    }
}

// ---------------- launch ----------------------------------------------------
extern "C" void kernel_launch(void* const* d_in, const int* in_sizes, int n_in,
                              void* d_out, int out_size) {
    const float* X   = (const float*)d_in[0];
    const float* Wq  = (const float*)d_in[1];
    const float* Wk  = (const float*)d_in[2];
    const float* Wv  = (const float*)d_in[3];
    const float* Wo  = (const float*)d_in[4];
    const float* tbl = (const float*)d_in[5];
    float* out = (float*)d_out;

    cudaFuncSetAttribute(attn_mma,
                         cudaFuncAttributeMaxDynamicSharedMemorySize,
                         ATTN3_BYTES);
    cudaFuncSetAttribute(gemm_mma,
                         cudaFuncAttributeMaxDynamicSharedMemorySize,
                         GEMM_SMEM_BYTES);

    bias_kernel<<<(RELN + 255) / 256, 256>>>(tbl);

    xcvt<<<(MROWS * DM / 4 + 255) / 256, 256>>>(X, MROWS * DM / 4);
    dim3 gw(DM / 32, DM / 32, 4);
    wt_cvt<<<gw, dim3(32, 8)>>>(Wq, Wk, Wv, Wo);

    dim3 g1(DM / 128, MROWS / 128, 3);
    gemm_mma<<<g1, 256, GEMM_SMEM_BYTES>>>(0, 0, nullptr);

    dim3 g2(SEQ / 128, BSZ * NH);
    attn_mma<<<g2, 256, ATTN3_BYTES>>>();

    // attention epilogue already produced g_xhi/g_xlo for the out projection
    dim3 g3(DM / 128, MROWS / 128, 1);
    gemm_mma<<<g3, 256, GEMM_SMEM_BYTES>>>(3, 1, out);
}

// round 9
// speedup vs baseline: 4.0739x; 1.1663x over previous
#include <cuda_runtime.h>
#include <cuda_bf16.h>
#include <math.h>
#include <stdint.h>

#define BSZ   2
#define SEQ   2048
#define DM    1024
#define NH    16
#define DK    64
#define RELN  (2*SEQ-1)   // 4095
#define MROWS (BSZ*SEQ)   // 4096

// ---------------- scratch (device globals; device-code access only) --------
__device__ float g_v[BSZ*NH*SEQ*DK];         // V fp32 [b][h][s][d] (vcvt input)
__device__ float g_bias[NH*RELN];            // [h][rel + S-1]

__device__ uint32_t g_qhi_w[BSZ*NH*SEQ*(DK/2)];   // Q packed hi words [bh][s][dw]
__device__ uint32_t g_qlo_w[BSZ*NH*SEQ*(DK/2)];
__device__ uint32_t g_khi_w[BSZ*NH*SEQ*(DK/2)];   // K packed words
__device__ uint32_t g_klo_w[BSZ*NH*SEQ*(DK/2)];
__device__ uint32_t g_vthi[BSZ*NH*DK*(SEQ/2)];    // V^T words [bh][d][u]
__device__ uint32_t g_vtlo[BSZ*NH*DK*(SEQ/2)];

__device__ __nv_bfloat16 g_xhi[MROWS*DM];   // activations hi/lo (X, then attn out)
__device__ __nv_bfloat16 g_xlo[MROWS*DM];
__device__ __nv_bfloat16 g_wth[4*DM*DM];    // W^T hi: [w][n][k]
__device__ __nv_bfloat16 g_wtl[4*DM*DM];    // W^T lo

// ======================= mma.sync / cp.async helpers ========================
__device__ __forceinline__ void mma_bf16(float acc[4], const uint32_t a[4],
                                         const uint32_t b[2]) {
    asm volatile(
        "mma.sync.aligned.m16n8k16.row.col.f32.bf16.bf16.f32 "
        "{%0,%1,%2,%3}, {%4,%5,%6,%7}, {%8,%9}, {%0,%1,%2,%3};"
        : "+f"(acc[0]), "+f"(acc[1]), "+f"(acc[2]), "+f"(acc[3])
        : "r"(a[0]), "r"(a[1]), "r"(a[2]), "r"(a[3]), "r"(b[0]), "r"(b[1]));
}
__device__ __forceinline__ uint32_t smem_u32(const void* p) {
    uint32_t a;
    asm("{ .reg .u64 t; cvta.to.shared.u64 t, %1; cvt.u32.u64 %0, t; }"
        : "=r"(a) : "l"(p));
    return a;
}
#define CP16(dst, src) \
    asm volatile("cp.async.cg.shared.global [%0], [%1], 16;" \
        :: "r"(dst), "l"(src))
#define CP_COMMIT() asm volatile("cp.async.commit_group;")
#define CP_WAIT(n)  asm volatile("cp.async.wait_group %0;" :: "n"(n))

__device__ __forceinline__ uint32_t packbf(float a, float b) {
    __nv_bfloat162 t;
    t.x = __float2bfloat16_rn(a);
    t.y = __float2bfloat16_rn(b);
    return *(uint32_t*)&t;
}
__device__ __forceinline__ void pack_hilo(float a, float b,
                                          uint32_t& hi, uint32_t& lo) {
    __nv_bfloat16 ha = __float2bfloat16_rn(a);
    __nv_bfloat16 hb = __float2bfloat16_rn(b);
    __nv_bfloat162 th; th.x = ha; th.y = hb;
    hi = *(uint32_t*)&th;
    lo = packbf(a - __bfloat162float(ha), b - __bfloat162float(hb));
}

// ---------------- relative-position bias precompute -------------------------
__global__ void bias_kernel(const float* __restrict__ table) {
    int idx = blockIdx.x * blockDim.x + threadIdx.x;
    if (idx >= RELN) return;
    int rel = idx - (SEQ - 1);
    int bucket = (rel > 0) ? 16 : 0;
    int rabs = rel < 0 ? -rel : rel;
    int add;
    if (rabs < 8) {
        add = rabs;
    } else {
        double lf = log((double)rabs / 8.0) / log(16.0) * 8.0;
        add = 8 + (int)lf;
        if (add > 15) add = 15;
    }
    bucket += add;
#pragma unroll
    for (int h = 0; h < NH; h++)
        g_bias[h * RELN + idx] = table[bucket * NH + h];
}

// ---------------- fp32 X -> (hi,lo) bf16 split -------------------------------
__global__ __launch_bounds__(256) void xcvt(const float* __restrict__ in,
                                            int n4) {
    int i = blockIdx.x * blockDim.x + threadIdx.x;
    if (i >= n4) return;
    float4 x = ((const float4*)in)[i];
    float xs[4] = {x.x, x.y, x.z, x.w};
    __nv_bfloat16 hb[4], lb[4];
#pragma unroll
    for (int j = 0; j < 4; j++) {
        hb[j] = __float2bfloat16_rn(xs[j]);
        lb[j] = __float2bfloat16_rn(xs[j] - __bfloat162float(hb[j]));
    }
    *(uint2*)&g_xhi[i * 4] = *(uint2*)hb;
    *(uint2*)&g_xlo[i * 4] = *(uint2*)lb;
}

// ---------------- W [K][N] -> W^T (hi,lo) bf16 [N][K] -----------------------
__global__ __launch_bounds__(256) void wt_cvt(const float* __restrict__ Wq,
                                              const float* __restrict__ Wk,
                                              const float* __restrict__ Wv,
                                              const float* __restrict__ Wo) {
    __shared__ float tile[32][33];
    int w = blockIdx.z;
    const float* W = (w == 0) ? Wq : (w == 1) ? Wk : (w == 2) ? Wv : Wo;
    int kb = blockIdx.y * 32, nb = blockIdx.x * 32;
    int tx = threadIdx.x, ty = threadIdx.y;
    for (int r = ty; r < 32; r += 8)
        tile[r][tx] = W[(size_t)(kb + r) * DM + nb + tx];
    __syncthreads();
    __nv_bfloat16* oh = g_wth + (size_t)w * DM * DM;
    __nv_bfloat16* ol = g_wtl + (size_t)w * DM * DM;
    for (int r = ty; r < 32; r += 8) {
        float x = tile[tx][r];
        __nv_bfloat16 h = __float2bfloat16_rn(x);
        __nv_bfloat16 l = __float2bfloat16_rn(x - __bfloat162float(h));
        size_t o = (size_t)(nb + r) * DM + kb + tx;
        oh[o] = h;
        ol[o] = l;
    }
}

// ---------------- V fp32 [s][d] -> V^T packed words [d][u] ------------------
__global__ __launch_bounds__(256) void vcvt() {
    __shared__ float sm[64][65];
    const int bh = blockIdx.y;
    const int s0 = blockIdx.x * 64;
    const int tid = threadIdx.x;
    const float* V = g_v + ((size_t)bh * SEQ + s0) * DK;
#pragma unroll
    for (int i = 0; i < 4; i++) {
        int idx = tid + i * 256;           // [0,1024)
        int r = idx >> 4, j = idx & 15;
        float4 v = *(const float4*)(V + r * DK + j * 4);
        sm[r][j * 4 + 0] = v.x;
        sm[r][j * 4 + 1] = v.y;
        sm[r][j * 4 + 2] = v.z;
        sm[r][j * 4 + 3] = v.w;
    }
    __syncthreads();
#pragma unroll
    for (int i = 0; i < 8; i++) {
        int idx = tid + i * 256;           // [0,2048)
        int d = idx >> 5, u = idx & 31;
        uint32_t hw, lw;
        pack_hilo(sm[2 * u][d], sm[2 * u + 1][d], hw, lw);
        size_t o = ((size_t)bh * DK + d) * (SEQ / 2) + (s0 >> 1) + u;
        g_vthi[o] = hw;
        g_vtlo[o] = lw;
    }
}

// ---------------- split-bf16 GEMM, cp.async double-buffered, occ 2 ----------
#define A_ELEMS  (128*40)
#define AW       2560
#define RSTRIDE  20
#define SLOT_W   (4*AW)
#define GEMM_SMEM_BYTES (2*SLOT_W*4)   // 81920

__global__ __launch_bounds__(256, 2) void gemm_mma(
    int wbase, int mode, float* __restrict__ outp)
{
    extern __shared__ __align__(16) uint32_t gsm[];

    const int tid = threadIdx.x;
    const int wid = tid >> 5, lane = tid & 31;
    const int wm = wid & 1;
    const int wn = wid >> 1;
    const int fr = lane >> 2;
    const int fc = lane & 3;

    const int w  = wbase + blockIdx.z;
    const int m0 = blockIdx.y * 128;
    const int n0 = blockIdx.x * 128;
    const __nv_bfloat16* __restrict__ ah = g_xhi;
    const __nv_bfloat16* __restrict__ al = g_xlo;
    const __nv_bfloat16* __restrict__ bh = g_wth + (size_t)w * DM * DM;
    const __nv_bfloat16* __restrict__ bl = g_wtl + (size_t)w * DM * DM;

    const __nv_bfloat16* asrc[4];
    const __nv_bfloat16* bsrc[4];
    uint32_t adst[4], bdst[4];
    const uint32_t sb0 = smem_u32(gsm);
#pragma unroll
    for (int i = 0; i < 4; i++) {
        int idx = tid + i * 256;
        int sel = idx >> 9, r = (idx >> 2) & 127, j = idx & 3;
        asrc[i] = (sel ? al : ah) + (size_t)(m0 + r) * DM + j * 8;
        adst[i] = sb0 + (uint32_t)(sel * AW + r * RSTRIDE + j * 4) * 4;
        bsrc[i] = (sel ? bl : bh) + (size_t)(n0 + r) * DM + j * 8;
        bdst[i] = sb0 + (uint32_t)(2 * AW + sel * AW + r * RSTRIDE + j * 4) * 4;
    }

    float acc[4][4][4];
#pragma unroll
    for (int i = 0; i < 4; i++)
#pragma unroll
        for (int j = 0; j < 4; j++)
#pragma unroll
            for (int q = 0; q < 4; q++) acc[i][j][q] = 0.f;

#pragma unroll
    for (int i = 0; i < 4; i++) {
        CP16(adst[i], asrc[i]);
        CP16(bdst[i], bsrc[i]);
    }
    CP_COMMIT();

    for (int c = 0; c < 32; c++) {
        if (c < 31) {
            const int k1 = (c + 1) * 32;
            const uint32_t so = ((c + 1) & 1) * (SLOT_W * 4);
#pragma unroll
            for (int i = 0; i < 4; i++) {
                CP16(adst[i] + so, asrc[i] + k1);
                CP16(bdst[i] + so, bsrc[i] + k1);
            }
            CP_COMMIT();
            CP_WAIT(1);
        } else {
            CP_WAIT(0);
        }
        __syncthreads();

        const uint32_t* SW = gsm + (c & 1) * SLOT_W;
#pragma unroll
        for (int ks = 0; ks < 2; ks++) {
            const int kw = ks * 8;
            uint32_t Af[4][4], Bhf[4][2], Blf[4][2];
            // A hi fragments
#pragma unroll
            for (int mf = 0; mf < 4; mf++) {
                int base = (wm * 64 + mf * 16 + fr) * RSTRIDE + kw + fc;
                Af[mf][0] = SW[base];
                Af[mf][1] = SW[base + 8 * RSTRIDE];
                Af[mf][2] = SW[base + 4];
                Af[mf][3] = SW[base + 8 * RSTRIDE + 4];
            }
            // B hi + B lo fragments
#pragma unroll
            for (int nf = 0; nf < 4; nf++) {
                int nb = (wn * 32 + nf * 8 + fr) * RSTRIDE + kw + fc;
                Bhf[nf][0] = SW[2 * AW + nb];
                Bhf[nf][1] = SW[2 * AW + nb + 4];
                Blf[nf][0] = SW[3 * AW + nb];
                Blf[nf][1] = SW[3 * AW + nb + 4];
            }
#pragma unroll
            for (int mf = 0; mf < 4; mf++)
#pragma unroll
                for (int nf = 0; nf < 4; nf++)
                    mma_bf16(acc[mf][nf], Af[mf], Bhf[nf]);   // hi*hi
#pragma unroll
            for (int mf = 0; mf < 4; mf++)
#pragma unroll
                for (int nf = 0; nf < 4; nf++)
                    mma_bf16(acc[mf][nf], Af[mf], Blf[nf]);   // hi*lo
            // A lo fragments (reuse Af registers)
#pragma unroll
            for (int mf = 0; mf < 4; mf++) {
                int base = AW + (wm * 64 + mf * 16 + fr) * RSTRIDE + kw + fc;
                Af[mf][0] = SW[base];
                Af[mf][1] = SW[base + 8 * RSTRIDE];
                Af[mf][2] = SW[base + 4];
                Af[mf][3] = SW[base + 8 * RSTRIDE + 4];
            }
#pragma unroll
            for (int mf = 0; mf < 4; mf++)
#pragma unroll
                for (int nf = 0; nf < 4; nf++)
                    mma_bf16(acc[mf][nf], Af[mf], Bhf[nf]);   // lo*hi
        }
        __syncthreads();
    }

    // ---- epilogue ----
#pragma unroll
    for (int mf = 0; mf < 4; mf++) {
        int row = m0 + wm * 64 + mf * 16 + fr;
#pragma unroll
        for (int nf = 0; nf < 4; nf++) {
            int n = n0 + wn * 32 + nf * 8 + fc * 2;
            if (mode == 0) {
                int h = n >> 6, d = n & 63;
                int b = row >> 11, s = row & (SEQ - 1);
                size_t wi = ((size_t)(b * NH + h) * SEQ + s) * (DK / 2) + (d >> 1);
                if (w < 2) {
                    uint32_t* dsth = (w == 0) ? g_qhi_w : g_khi_w;
                    uint32_t* dstl = (w == 0) ? g_qlo_w : g_klo_w;
                    uint32_t hw, lw;
                    pack_hilo(acc[mf][nf][0], acc[mf][nf][1], hw, lw);
                    dsth[wi] = hw; dstl[wi] = lw;
                    pack_hilo(acc[mf][nf][2], acc[mf][nf][3], hw, lw);
                    dsth[wi + 8 * (DK / 2)] = hw;   // row+8 -> s+8
                    dstl[wi + 8 * (DK / 2)] = lw;
                } else {
                    size_t base = ((size_t)(b * NH + h) * SEQ + s) * DK + d;
                    *(float2*)(g_v + base) =
                        make_float2(acc[mf][nf][0], acc[mf][nf][1]);
                    *(float2*)(g_v + base + 8 * DK) =
                        make_float2(acc[mf][nf][2], acc[mf][nf][3]);
                }
            } else {
                *(float2*)(outp + (size_t)row * DM + n) =
                    make_float2(acc[mf][nf][0], acc[mf][nf][1]);
                *(float2*)(outp + (size_t)(row + 8) * DM + n) =
                    make_float2(acc[mf][nf][2], acc[mf][nf][3]);
            }
        }
    }
}

// ---------------- flash attention via mma.sync, cp.async double-buffered ----
#define KSTR 36
#define VSTR 68
#define S_KH 0
#define S_KL (128*KSTR)             // 4608
#define S_VH (2*128*KSTR)           // 9216
#define S_VL (S_VH + 64*VSTR)       // 13568
#define S_SB (S_VH + 2*64*VSTR)     // 17920
#define SLOT3_W (S_SB + 256)        // 18176
#define ATTN3_BYTES (2*SLOT3_W*4)   // 145408

__global__ __launch_bounds__(256, 1) void attn_mma() {
    extern __shared__ __align__(16) uint32_t SW3[];

    const int bh = blockIdx.y;
    const int h = bh & (NH - 1);
    const int b = bh >> 4;
    const int q0 = blockIdx.x * 128;
    const int tid = threadIdx.x;
    const int wid = tid >> 5, lane = tid & 31;
    const int fr = lane >> 2, fc = lane & 3;

    const size_t kwbase = (size_t)bh * SEQ * (DK / 2);
    const size_t vwbase = (size_t)bh * DK * (SEQ / 2);
    const uint32_t sb0 = smem_u32(SW3);

    // ---- Q fragments: direct LDG from packed words ----
    uint32_t Qh[4][4], Ql[4][4];
    {
        const size_t qb = kwbase + (size_t)(q0 + 16 * wid + fr) * (DK / 2);
#pragma unroll
        for (int ks = 0; ks < 4; ks++) {
            size_t i0 = qb + ks * 8 + fc;
            Qh[ks][0] = g_qhi_w[i0];
            Qh[ks][1] = g_qhi_w[i0 + 8 * (DK / 2)];
            Qh[ks][2] = g_qhi_w[i0 + 4];
            Qh[ks][3] = g_qhi_w[i0 + 8 * (DK / 2) + 4];
            Ql[ks][0] = g_qlo_w[i0];
            Ql[ks][1] = g_qlo_w[i0 + 8 * (DK / 2)];
            Ql[ks][2] = g_qlo_w[i0 + 4];
            Ql[ks][3] = g_qlo_w[i0 + 8 * (DK / 2) + 4];
        }
    }

    float Oa[8][4];
#pragma unroll
    for (int i = 0; i < 8; i++)
#pragma unroll
        for (int q = 0; q < 4; q++) Oa[i][q] = 0.f;
    float m_a = -1e30f, m_b = -1e30f, l_a = 0.f, l_b = 0.f;

    const int sboff = 2 * fc - 16 * wid - fr + 128;

    // ---- prefetch helper (macro-ish lambda) ----
    auto prefetch = [&](int t) {
        const int slot = t & 1;
        const uint32_t sbase = sb0 + slot * SLOT3_W * 4;
        const int k0 = t * 128;
        // K: 1024 chunks of 16B per half
#pragma unroll
        for (int i = 0; i < 4; i++) {
            int idx = tid + i * 256;            // [0,1024)
            int r = idx >> 3, jc = idx & 7;
            size_t src = kwbase + (size_t)(k0 + r) * (DK / 2) + jc * 4;
            uint32_t doff = (uint32_t)(r * KSTR + jc * 4) * 4;
            CP16(sbase + S_KH * 4 + doff, g_khi_w + src);
            CP16(sbase + S_KL * 4 + doff, g_klo_w + src);
        }
        // V^T: 1024 chunks per half
#pragma unroll
        for (int i = 0; i < 4; i++) {
            int idx = tid + i * 256;            // [0,1024)
            int d = idx >> 4, jc = idx & 15;
            size_t src = vwbase + (size_t)d * (SEQ / 2) + (k0 >> 1) + jc * 4;
            uint32_t doff = (uint32_t)(d * VSTR + jc * 4) * 4;
            CP16(sbase + S_VH * 4 + doff, g_vthi + src);
            CP16(sbase + S_VL * 4 + doff, g_vtlo + src);
        }
        // bias window (plain load/store; protected by slot alternation)
        {
            int gi = 2047 + k0 - q0 + tid - 128;
            gi = gi < 0 ? 0 : (gi > RELN - 1 ? RELN - 1 : gi);
            float bv = g_bias[h * RELN + gi];
            SW3[slot * SLOT3_W + S_SB + tid] = __float_as_uint(bv);
        }
    };

    prefetch(0);
    CP_COMMIT();

    for (int t = 0; t < SEQ / 128; t++) {
        if (t < SEQ / 128 - 1) {
            prefetch(t + 1);
            CP_COMMIT();
            CP_WAIT(1);
        } else {
            CP_WAIT(0);
        }
        __syncthreads();

        const uint32_t* SWs = SW3 + (t & 1) * SLOT3_W;
        const float* Sb = (const float*)(SWs + S_SB);

        // ---- phase 1: S = Q K^T (3-term split) ----
        float sc[16][4];
#pragma unroll
        for (int nf = 0; nf < 16; nf++)
#pragma unroll
            for (int q = 0; q < 4; q++) sc[nf][q] = 0.f;

#pragma unroll
        for (int ks = 0; ks < 4; ks++) {
            const int kw = ks * 8 + fc;
#pragma unroll
            for (int nf = 0; nf < 16; nf++) {
                int nb = (nf * 8 + fr) * KSTR + kw;
                uint32_t bf[2] = {SWs[S_KH + nb], SWs[S_KH + nb + 4]};
                mma_bf16(sc[nf], Qh[ks], bf);
            }
#pragma unroll
            for (int nf = 0; nf < 16; nf++) {
                int nb = (nf * 8 + fr) * KSTR + kw;
                uint32_t bf[2] = {SWs[S_KH + nb], SWs[S_KH + nb + 4]};
                mma_bf16(sc[nf], Ql[ks], bf);
            }
#pragma unroll
            for (int nf = 0; nf < 16; nf++) {
                int nb = (nf * 8 + fr) * KSTR + kw;
                uint32_t bf[2] = {SWs[S_KL + nb], SWs[S_KL + nb + 4]};
                mma_bf16(sc[nf], Qh[ks], bf);
            }
        }

        // ---- bias add ----
        float pb0 = Sb[sboff - 8], pb1 = Sb[sboff - 7];
#pragma unroll
        for (int nf = 0; nf < 16; nf++) {
            float b0 = Sb[sboff + 8 * nf];
            float b1 = Sb[sboff + 8 * nf + 1];
            sc[nf][0] += b0;
            sc[nf][1] += b1;
            sc[nf][2] += pb0;
            sc[nf][3] += pb1;
            pb0 = b0; pb1 = b1;
        }

        // ---- online softmax ----
        float mxa = -1e30f, mxb = -1e30f;
#pragma unroll
        for (int nf = 0; nf < 16; nf++) {
            mxa = fmaxf(mxa, fmaxf(sc[nf][0], sc[nf][1]));
            mxb = fmaxf(mxb, fmaxf(sc[nf][2], sc[nf][3]));
        }
        mxa = fmaxf(mxa, __shfl_xor_sync(0xffffffffu, mxa, 1));
        mxa = fmaxf(mxa, __shfl_xor_sync(0xffffffffu, mxa, 2));
        mxb = fmaxf(mxb, __shfl_xor_sync(0xffffffffu, mxb, 1));
        mxb = fmaxf(mxb, __shfl_xor_sync(0xffffffffu, mxb, 2));
        float mna = fmaxf(m_a, mxa), mnb = fmaxf(m_b, mxb);
        float ca = __expf(m_a - mna), cb = __expf(m_b - mnb);
        float sa = 0.f, sb2 = 0.f;
#pragma unroll
        for (int nf = 0; nf < 16; nf++) {
            sc[nf][0] = __expf(sc[nf][0] - mna);
            sc[nf][1] = __expf(sc[nf][1] - mna);
            sc[nf][2] = __expf(sc[nf][2] - mnb);
            sc[nf][3] = __expf(sc[nf][3] - mnb);
            sa  += sc[nf][0] + sc[nf][1];
            sb2 += sc[nf][2] + sc[nf][3];
        }
        sa  += __shfl_xor_sync(0xffffffffu, sa, 1);
        sa  += __shfl_xor_sync(0xffffffffu, sa, 2);
        sb2 += __shfl_xor_sync(0xffffffffu, sb2, 1);
        sb2 += __shfl_xor_sync(0xffffffffu, sb2, 2);
        l_a = l_a * ca + sa;
        l_b = l_b * cb + sb2;
        m_a = mna; m_b = mnb;

#pragma unroll
        for (int i = 0; i < 8; i++) {
            Oa[i][0] *= ca; Oa[i][1] *= ca;
            Oa[i][2] *= cb; Oa[i][3] *= cb;
        }

        // ---- phase 2: O += P V ----
#pragma unroll
        for (int ks2 = 0; ks2 < 8; ks2++) {
            uint32_t Ph[4], Pl[4];
            pack_hilo(sc[2*ks2][0],   sc[2*ks2][1],   Ph[0], Pl[0]);
            pack_hilo(sc[2*ks2][2],   sc[2*ks2][3],   Ph[1], Pl[1]);
            pack_hilo(sc[2*ks2+1][0], sc[2*ks2+1][1], Ph[2], Pl[2]);
            pack_hilo(sc[2*ks2+1][2], sc[2*ks2+1][3], Ph[3], Pl[3]);
            const int kw2 = ks2 * 8 + fc;
#pragma unroll
            for (int nf2 = 0; nf2 < 8; nf2++) {
                int nb = (nf2 * 8 + fr) * VSTR + kw2;
                uint32_t bf[2] = {SWs[S_VH + nb], SWs[S_VH + nb + 4]};
                mma_bf16(Oa[nf2], Ph, bf);
            }
#pragma unroll
            for (int nf2 = 0; nf2 < 8; nf2++) {
                int nb = (nf2 * 8 + fr) * VSTR + kw2;
                uint32_t bf[2] = {SWs[S_VH + nb], SWs[S_VH + nb + 4]};
                mma_bf16(Oa[nf2], Pl, bf);
            }
#pragma unroll
            for (int nf2 = 0; nf2 < 8; nf2++) {
                int nb = (nf2 * 8 + fr) * VSTR + kw2;
                uint32_t bf[2] = {SWs[S_VL + nb], SWs[S_VL + nb + 4]};
                mma_bf16(Oa[nf2], Ph, bf);
            }
        }
        __syncthreads();   // compute done before next prefetch overwrites slot
    }

    // ---- epilogue: write hi/lo bf16 straight into g_xhi/g_xlo --------------
    float inva = 1.0f / l_a, invb = 1.0f / l_b;
    int ra = q0 + 16 * wid + fr;
#pragma unroll
    for (int nf2 = 0; nf2 < 8; nf2++) {
        int d = nf2 * 8 + 2 * fc;
        size_t ia = (size_t)(b * SEQ + ra) * DM + h * DK + d;
        size_t ib = ia + (size_t)8 * DM;
        uint32_t hw, lw;
        pack_hilo(Oa[nf2][0] * inva, Oa[nf2][1] * inva, hw, lw);
        *(uint32_t*)&g_xhi[ia] = hw;
        *(uint32_t*)&g_xlo[ia] = lw;
        pack_hilo(Oa[nf2][2] * invb, Oa[nf2][3] * invb, hw, lw);
        *(uint32_t*)&g_xhi[ib] = hw;
        *(uint32_t*)&g_xlo[ib] = lw;
    }
}

// ---------------- launch ----------------------------------------------------
extern "C" void kernel_launch(void* const* d_in, const int* in_sizes, int n_in,
                              void* d_out, int out_size) {
    const float* X   = (const float*)d_in[0];
    const float* Wq  = (const float*)d_in[1];
    const float* Wk  = (const float*)d_in[2];
    const float* Wv  = (const float*)d_in[3];
    const float* Wo  = (const float*)d_in[4];
    const float* tbl = (const float*)d_in[5];
    float* out = (float*)d_out;

    cudaFuncSetAttribute(attn_mma,
                         cudaFuncAttributeMaxDynamicSharedMemorySize,
                         ATTN3_BYTES);
    cudaFuncSetAttribute(gemm_mma,
                         cudaFuncAttributeMaxDynamicSharedMemorySize,
                         GEMM_SMEM_BYTES);

    bias_kernel<<<(RELN + 255) / 256, 256>>>(tbl);

    xcvt<<<(MROWS * DM / 4 + 255) / 256, 256>>>(X, MROWS * DM / 4);
    dim3 gw(DM / 32, DM / 32, 4);
    wt_cvt<<<gw, dim3(32, 8)>>>(Wq, Wk, Wv, Wo);

    dim3 g1(DM / 128, MROWS / 128, 3);
    gemm_mma<<<g1, 256, GEMM_SMEM_BYTES>>>(0, 0, nullptr);

    dim3 gv(SEQ / 64, BSZ * NH);
    vcvt<<<gv, 256>>>();

    dim3 g2(SEQ / 128, BSZ * NH);
    attn_mma<<<g2, 256, ATTN3_BYTES>>>();

    dim3 g3(DM / 128, MROWS / 128, 1);
    gemm_mma<<<g3, 256, GEMM_SMEM_BYTES>>>(3, 1, out);
}

// round 10
// speedup vs baseline: 4.3123x; 1.0585x over previous
#include <cuda_runtime.h>
#include <cuda_bf16.h>
#include <math.h>
#include <stdint.h>

#define BSZ   2
#define SEQ   2048
#define DM    1024
#define NH    16
#define DK    64
#define RELN  (2*SEQ-1)   // 4095
#define MROWS (BSZ*SEQ)   // 4096

// ---------------- scratch (device globals; device-code access only) --------
__device__ float g_v[BSZ*NH*SEQ*DK];         // V fp32 [b][h][s][d] (vcvt input)
__device__ float g_bias[NH*RELN];            // [h][rel + S-1]

__device__ uint32_t g_qhi_w[BSZ*NH*SEQ*(DK/2)];   // Q packed hi words [bh][s][dw]
__device__ uint32_t g_qlo_w[BSZ*NH*SEQ*(DK/2)];
__device__ uint32_t g_khi_w[BSZ*NH*SEQ*(DK/2)];   // K packed words
__device__ uint32_t g_klo_w[BSZ*NH*SEQ*(DK/2)];
__device__ uint32_t g_vthi[BSZ*NH*DK*(SEQ/2)];    // V^T words [bh][d][u]
__device__ uint32_t g_vtlo[BSZ*NH*DK*(SEQ/2)];

__device__ __nv_bfloat16 g_xhi[MROWS*DM];   // activations hi/lo
__device__ __nv_bfloat16 g_xlo[MROWS*DM];
__device__ __nv_bfloat16 g_wth[4*DM*DM];    // W^T hi: [w][n][k]
__device__ __nv_bfloat16 g_wtl[4*DM*DM];    // W^T lo

// ======================= mma / ldmatrix / cp.async helpers ==================
__device__ __forceinline__ void mma_bf16(float acc[4], const uint32_t a[4],
                                         const uint32_t b[2]) {
    asm volatile(
        "mma.sync.aligned.m16n8k16.row.col.f32.bf16.bf16.f32 "
        "{%0,%1,%2,%3}, {%4,%5,%6,%7}, {%8,%9}, {%0,%1,%2,%3};"
        : "+f"(acc[0]), "+f"(acc[1]), "+f"(acc[2]), "+f"(acc[3])
        : "r"(a[0]), "r"(a[1]), "r"(a[2]), "r"(a[3]), "r"(b[0]), "r"(b[1]));
}
#define LDSM_X4(R0, R1, R2, R3, A) \
    asm volatile("ldmatrix.sync.aligned.m8n8.x4.shared.b16 {%0,%1,%2,%3}, [%4];" \
        : "=r"(R0), "=r"(R1), "=r"(R2), "=r"(R3) : "r"(A))
__device__ __forceinline__ uint32_t smem_u32(const void* p) {
    uint32_t a;
    asm("{ .reg .u64 t; cvta.to.shared.u64 t, %1; cvt.u32.u64 %0, t; }"
        : "=r"(a) : "l"(p));
    return a;
}
#define CP16(dst, src) \
    asm volatile("cp.async.cg.shared.global [%0], [%1], 16;" \
        :: "r"(dst), "l"(src))
#define CP_COMMIT() asm volatile("cp.async.commit_group;")
#define CP_WAIT(n)  asm volatile("cp.async.wait_group %0;" :: "n"(n))

__device__ __forceinline__ uint32_t packbf(float a, float b) {
    __nv_bfloat162 t;
    t.x = __float2bfloat16_rn(a);
    t.y = __float2bfloat16_rn(b);
    return *(uint32_t*)&t;
}
__device__ __forceinline__ void pack_hilo(float a, float b,
                                          uint32_t& hi, uint32_t& lo) {
    __nv_bfloat16 ha = __float2bfloat16_rn(a);
    __nv_bfloat16 hb = __float2bfloat16_rn(b);
    __nv_bfloat162 th; th.x = ha; th.y = hb;
    hi = *(uint32_t*)&th;
    lo = packbf(a - __bfloat162float(ha), b - __bfloat162float(hb));
}

// ---------------- relative-position bias precompute -------------------------
__global__ void bias_kernel(const float* __restrict__ table) {
    int idx = blockIdx.x * blockDim.x + threadIdx.x;
    if (idx >= RELN) return;
    int rel = idx - (SEQ - 1);
    int bucket = (rel > 0) ? 16 : 0;
    int rabs = rel < 0 ? -rel : rel;
    int add;
    if (rabs < 8) {
        add = rabs;
    } else {
        double lf = log((double)rabs / 8.0) / log(16.0) * 8.0;
        add = 8 + (int)lf;
        if (add > 15) add = 15;
    }
    bucket += add;
#pragma unroll
    for (int h = 0; h < NH; h++)
        g_bias[h * RELN + idx] = table[bucket * NH + h];
}

// ---------------- fp32 X -> (hi,lo) bf16 split -------------------------------
__global__ __launch_bounds__(256) void xcvt(const float* __restrict__ in,
                                            int n4) {
    int i = blockIdx.x * blockDim.x + threadIdx.x;
    if (i >= n4) return;
    float4 x = ((const float4*)in)[i];
    float xs[4] = {x.x, x.y, x.z, x.w};
    __nv_bfloat16 hb[4], lb[4];
#pragma unroll
    for (int j = 0; j < 4; j++) {
        hb[j] = __float2bfloat16_rn(xs[j]);
        lb[j] = __float2bfloat16_rn(xs[j] - __bfloat162float(hb[j]));
    }
    *(uint2*)&g_xhi[i * 4] = *(uint2*)hb;
    *(uint2*)&g_xlo[i * 4] = *(uint2*)lb;
}

// ---------------- W [K][N] -> W^T (hi,lo) bf16 [N][K] -----------------------
__global__ __launch_bounds__(256) void wt_cvt(const float* __restrict__ Wq,
                                              const float* __restrict__ Wk,
                                              const float* __restrict__ Wv,
                                              const float* __restrict__ Wo) {
    __shared__ float tile[32][33];
    int w = blockIdx.z;
    const float* W = (w == 0) ? Wq : (w == 1) ? Wk : (w == 2) ? Wv : Wo;
    int kb = blockIdx.y * 32, nb = blockIdx.x * 32;
    int tx = threadIdx.x, ty = threadIdx.y;
    for (int r = ty; r < 32; r += 8)
        tile[r][tx] = W[(size_t)(kb + r) * DM + nb + tx];
    __syncthreads();
    __nv_bfloat16* oh = g_wth + (size_t)w * DM * DM;
    __nv_bfloat16* ol = g_wtl + (size_t)w * DM * DM;
    for (int r = ty; r < 32; r += 8) {
        float x = tile[tx][r];
        __nv_bfloat16 h = __float2bfloat16_rn(x);
        __nv_bfloat16 l = __float2bfloat16_rn(x - __bfloat162float(h));
        size_t o = (size_t)(nb + r) * DM + kb + tx;
        oh[o] = h;
        ol[o] = l;
    }
}

// ---------------- V fp32 [s][d] -> V^T packed words [d][u] ------------------
__global__ __launch_bounds__(256) void vcvt() {
    __shared__ float sm[64][65];
    const int bh = blockIdx.y;
    const int s0 = blockIdx.x * 64;
    const int tid = threadIdx.x;
    const float* V = g_v + ((size_t)bh * SEQ + s0) * DK;
#pragma unroll
    for (int i = 0; i < 4; i++) {
        int idx = tid + i * 256;
        int r = idx >> 4, j = idx & 15;
        float4 v = *(const float4*)(V + r * DK + j * 4);
        sm[r][j * 4 + 0] = v.x;
        sm[r][j * 4 + 1] = v.y;
        sm[r][j * 4 + 2] = v.z;
        sm[r][j * 4 + 3] = v.w;
    }
    __syncthreads();
#pragma unroll
    for (int i = 0; i < 8; i++) {
        int idx = tid + i * 256;
        int d = idx >> 5, u = idx & 31;
        uint32_t hw, lw;
        pack_hilo(sm[2 * u][d], sm[2 * u + 1][d], hw, lw);
        size_t o = ((size_t)bh * DK + d) * (SEQ / 2) + (s0 >> 1) + u;
        g_vthi[o] = hw;
        g_vtlo[o] = lw;
    }
}

// ---------------- split-bf16 GEMM, cp.async + ldmatrix, occ 2 ----------------
#define AW       2560
#define RSTRIDE  20
#define SLOT_W   (4*AW)
#define GEMM_SMEM_BYTES (2*SLOT_W*4)   // 81920

__global__ __launch_bounds__(256, 2) void gemm_mma(
    int wbase, int mode, float* __restrict__ outp)
{
    extern __shared__ __align__(16) uint32_t gsm[];

    const int tid = threadIdx.x;
    const int wid = tid >> 5, lane = tid & 31;
    const int wm = wid & 1;
    const int wn = wid >> 1;
    const int fr = lane >> 2;
    const int fc = lane & 3;
    // ldmatrix lane-address components
    const int arow_l = (lane & 7) + ((lane >> 3) & 1) * 8;
    const int acol_l = (lane >> 4) * 4;
    const int brow_l = (lane & 7) + (lane >> 4) * 8;
    const int bcol_l = ((lane >> 3) & 1) * 4;

    const int w  = wbase + blockIdx.z;
    const int m0 = blockIdx.y * 128;
    const int n0 = blockIdx.x * 128;
    const __nv_bfloat16* __restrict__ ah = g_xhi;
    const __nv_bfloat16* __restrict__ al = g_xlo;
    const __nv_bfloat16* __restrict__ bh = g_wth + (size_t)w * DM * DM;
    const __nv_bfloat16* __restrict__ bl = g_wtl + (size_t)w * DM * DM;

    const __nv_bfloat16* asrc[4];
    const __nv_bfloat16* bsrc[4];
    uint32_t adst[4], bdst[4];
    const uint32_t sb0 = smem_u32(gsm);
#pragma unroll
    for (int i = 0; i < 4; i++) {
        int idx = tid + i * 256;
        int sel = idx >> 9, r = (idx >> 2) & 127, j = idx & 3;
        asrc[i] = (sel ? al : ah) + (size_t)(m0 + r) * DM + j * 8;
        adst[i] = sb0 + (uint32_t)(sel * AW + r * RSTRIDE + j * 4) * 4;
        bsrc[i] = (sel ? bl : bh) + (size_t)(n0 + r) * DM + j * 8;
        bdst[i] = sb0 + (uint32_t)(2 * AW + sel * AW + r * RSTRIDE + j * 4) * 4;
    }

    // per-thread ldmatrix base words
    const int a_base_w = (wm * 64 + arow_l) * RSTRIDE + acol_l;
    const int b_base_w = (wn * 32 + brow_l) * RSTRIDE + bcol_l;

    float acc[4][4][4];
#pragma unroll
    for (int i = 0; i < 4; i++)
#pragma unroll
        for (int j = 0; j < 4; j++)
#pragma unroll
            for (int q = 0; q < 4; q++) acc[i][j][q] = 0.f;

#pragma unroll
    for (int i = 0; i < 4; i++) {
        CP16(adst[i], asrc[i]);
        CP16(bdst[i], bsrc[i]);
    }
    CP_COMMIT();

    for (int c = 0; c < 32; c++) {
        if (c < 31) {
            const int k1 = (c + 1) * 32;
            const uint32_t so = ((c + 1) & 1) * (SLOT_W * 4);
#pragma unroll
            for (int i = 0; i < 4; i++) {
                CP16(adst[i] + so, asrc[i] + k1);
                CP16(bdst[i] + so, bsrc[i] + k1);
            }
            CP_COMMIT();
            CP_WAIT(1);
        } else {
            CP_WAIT(0);
        }
        __syncthreads();

        const uint32_t sws = sb0 + (c & 1) * (SLOT_W * 4);
#pragma unroll
        for (int ks = 0; ks < 2; ks++) {
            const int kw = ks * 8;
            uint32_t Af[4][4], Bhf[4][2], Blf[4][2];
            // A hi fragments via ldmatrix.x4
#pragma unroll
            for (int mf = 0; mf < 4; mf++) {
                uint32_t ad = sws + (uint32_t)(a_base_w + mf * 16 * RSTRIDE + kw) * 4;
                LDSM_X4(Af[mf][0], Af[mf][1], Af[mf][2], Af[mf][3], ad);
            }
            // B hi + lo pairs via ldmatrix.x4
#pragma unroll
            for (int j = 0; j < 2; j++) {
                uint32_t bd = sws + (uint32_t)(2 * AW + b_base_w + j * 16 * RSTRIDE + kw) * 4;
                LDSM_X4(Bhf[2 * j][0], Bhf[2 * j][1],
                        Bhf[2 * j + 1][0], Bhf[2 * j + 1][1], bd);
                LDSM_X4(Blf[2 * j][0], Blf[2 * j][1],
                        Blf[2 * j + 1][0], Blf[2 * j + 1][1], bd + AW * 4);
            }
#pragma unroll
            for (int mf = 0; mf < 4; mf++)
#pragma unroll
                for (int nf = 0; nf < 4; nf++)
                    mma_bf16(acc[mf][nf], Af[mf], Bhf[nf]);   // hi*hi
#pragma unroll
            for (int mf = 0; mf < 4; mf++)
#pragma unroll
                for (int nf = 0; nf < 4; nf++)
                    mma_bf16(acc[mf][nf], Af[mf], Blf[nf]);   // hi*lo
            // A lo fragments (reuse Af regs)
#pragma unroll
            for (int mf = 0; mf < 4; mf++) {
                uint32_t ad = sws + (uint32_t)(AW + a_base_w + mf * 16 * RSTRIDE + kw) * 4;
                LDSM_X4(Af[mf][0], Af[mf][1], Af[mf][2], Af[mf][3], ad);
            }
#pragma unroll
            for (int mf = 0; mf < 4; mf++)
#pragma unroll
                for (int nf = 0; nf < 4; nf++)
                    mma_bf16(acc[mf][nf], Af[mf], Bhf[nf]);   // lo*hi
        }
        __syncthreads();
    }

    // ---- epilogue ----
#pragma unroll
    for (int mf = 0; mf < 4; mf++) {
        int row = m0 + wm * 64 + mf * 16 + fr;
#pragma unroll
        for (int nf = 0; nf < 4; nf++) {
            int n = n0 + wn * 32 + nf * 8 + fc * 2;
            if (mode == 0) {
                int h = n >> 6, d = n & 63;
                int b = row >> 11, s = row & (SEQ - 1);
                size_t wi = ((size_t)(b * NH + h) * SEQ + s) * (DK / 2) + (d >> 1);
                if (w < 2) {
                    uint32_t* dsth = (w == 0) ? g_qhi_w : g_khi_w;
                    uint32_t* dstl = (w == 0) ? g_qlo_w : g_klo_w;
                    uint32_t hw, lw;
                    pack_hilo(acc[mf][nf][0], acc[mf][nf][1], hw, lw);
                    dsth[wi] = hw; dstl[wi] = lw;
                    pack_hilo(acc[mf][nf][2], acc[mf][nf][3], hw, lw);
                    dsth[wi + 8 * (DK / 2)] = hw;
                    dstl[wi + 8 * (DK / 2)] = lw;
                } else {
                    size_t base = ((size_t)(b * NH + h) * SEQ + s) * DK + d;
                    *(float2*)(g_v + base) =
                        make_float2(acc[mf][nf][0], acc[mf][nf][1]);
                    *(float2*)(g_v + base + 8 * DK) =
                        make_float2(acc[mf][nf][2], acc[mf][nf][3]);
                }
            } else {
                *(float2*)(outp + (size_t)row * DM + n) =
                    make_float2(acc[mf][nf][0], acc[mf][nf][1]);
                *(float2*)(outp + (size_t)(row + 8) * DM + n) =
                    make_float2(acc[mf][nf][2], acc[mf][nf][3]);
            }
        }
    }
}

// ---------------- flash attention via mma.sync + ldmatrix -------------------
#define KSTR 36
#define VSTR 68
#define S_KH 0
#define S_KL (128*KSTR)
#define S_VH (2*128*KSTR)
#define S_VL (S_VH + 64*VSTR)
#define S_SB (S_VH + 2*64*VSTR)
#define SLOT3_W (S_SB + 256)
#define ATTN3_BYTES (2*SLOT3_W*4)   // 145408

__global__ __launch_bounds__(256, 1) void attn_mma() {
    extern __shared__ __align__(16) uint32_t SW3[];

    const int bh = blockIdx.y;
    const int h = bh & (NH - 1);
    const int b = bh >> 4;
    const int q0 = blockIdx.x * 128;
    const int tid = threadIdx.x;
    const int wid = tid >> 5, lane = tid & 31;
    const int fr = lane >> 2, fc = lane & 3;
    const int brow_l = (lane & 7) + (lane >> 4) * 8;
    const int bcol_l = ((lane >> 3) & 1) * 4;

    const size_t kwbase = (size_t)bh * SEQ * (DK / 2);
    const size_t vwbase = (size_t)bh * DK * (SEQ / 2);
    const uint32_t sb0 = smem_u32(SW3);

    uint32_t Qh[4][4], Ql[4][4];
    {
        const size_t qb = kwbase + (size_t)(q0 + 16 * wid + fr) * (DK / 2);
#pragma unroll
        for (int ks = 0; ks < 4; ks++) {
            size_t i0 = qb + ks * 8 + fc;
            Qh[ks][0] = g_qhi_w[i0];
            Qh[ks][1] = g_qhi_w[i0 + 8 * (DK / 2)];
            Qh[ks][2] = g_qhi_w[i0 + 4];
            Qh[ks][3] = g_qhi_w[i0 + 8 * (DK / 2) + 4];
            Ql[ks][0] = g_qlo_w[i0];
            Ql[ks][1] = g_qlo_w[i0 + 8 * (DK / 2)];
            Ql[ks][2] = g_qlo_w[i0 + 4];
            Ql[ks][3] = g_qlo_w[i0 + 8 * (DK / 2) + 4];
        }
    }

    float Oa[8][4];
#pragma unroll
    for (int i = 0; i < 8; i++)
#pragma unroll
        for (int q = 0; q < 4; q++) Oa[i][q] = 0.f;
    float m_a = -1e30f, m_b = -1e30f, l_a = 0.f, l_b = 0.f;

    const int sboff = 2 * fc - 16 * wid - fr + 128;

    auto prefetch = [&](int t) {
        const int slot = t & 1;
        const uint32_t sbase = sb0 + slot * SLOT3_W * 4;
        const int k0 = t * 128;
#pragma unroll
        for (int i = 0; i < 4; i++) {
            int idx = tid + i * 256;
            int r = idx >> 3, jc = idx & 7;
            size_t src = kwbase + (size_t)(k0 + r) * (DK / 2) + jc * 4;
            uint32_t doff = (uint32_t)(r * KSTR + jc * 4) * 4;
            CP16(sbase + S_KH * 4 + doff, g_khi_w + src);
            CP16(sbase + S_KL * 4 + doff, g_klo_w + src);
        }
#pragma unroll
        for (int i = 0; i < 4; i++) {
            int idx = tid + i * 256;
            int d = idx >> 4, jc = idx & 15;
            size_t src = vwbase + (size_t)d * (SEQ / 2) + (k0 >> 1) + jc * 4;
            uint32_t doff = (uint32_t)(d * VSTR + jc * 4) * 4;
            CP16(sbase + S_VH * 4 + doff, g_vthi + src);
            CP16(sbase + S_VL * 4 + doff, g_vtlo + src);
        }
        {
            int gi = 2047 + k0 - q0 + tid - 128;
            gi = gi < 0 ? 0 : (gi > RELN - 1 ? RELN - 1 : gi);
            float bv = g_bias[h * RELN + gi];
            SW3[slot * SLOT3_W + S_SB + tid] = __float_as_uint(bv);
        }
    };

    prefetch(0);
    CP_COMMIT();

    for (int t = 0; t < SEQ / 128; t++) {
        if (t < SEQ / 128 - 1) {
            prefetch(t + 1);
            CP_COMMIT();
            CP_WAIT(1);
        } else {
            CP_WAIT(0);
        }
        __syncthreads();

        const uint32_t sws = sb0 + (t & 1) * SLOT3_W * 4;
        const float* Sb = (const float*)(SW3 + (t & 1) * SLOT3_W + S_SB);

        // ---- phase 1: S = Q K^T (ldmatrix pairs, 3-term split) ----
        float sc[16][4];
#pragma unroll
        for (int nf = 0; nf < 16; nf++)
#pragma unroll
            for (int q = 0; q < 4; q++) sc[nf][q] = 0.f;

#pragma unroll
        for (int ks = 0; ks < 4; ks++) {
            const int kw = ks * 8 + bcol_l;
#pragma unroll
            for (int j = 0; j < 8; j++) {
                uint32_t kd = sws + (uint32_t)(S_KH + (j * 16 + brow_l) * KSTR + kw) * 4;
                uint32_t bf0[2], bf1[2];
                LDSM_X4(bf0[0], bf0[1], bf1[0], bf1[1], kd);
                mma_bf16(sc[2 * j],     Qh[ks], bf0);
                mma_bf16(sc[2 * j + 1], Qh[ks], bf1);
                mma_bf16(sc[2 * j],     Ql[ks], bf0);
                mma_bf16(sc[2 * j + 1], Ql[ks], bf1);
                LDSM_X4(bf0[0], bf0[1], bf1[0], bf1[1],
                        kd + (S_KL - S_KH) * 4);
                mma_bf16(sc[2 * j],     Qh[ks], bf0);
                mma_bf16(sc[2 * j + 1], Qh[ks], bf1);
            }
        }

        // ---- bias add ----
        float pb0 = Sb[sboff - 8], pb1 = Sb[sboff - 7];
#pragma unroll
        for (int nf = 0; nf < 16; nf++) {
            float b0 = Sb[sboff + 8 * nf];
            float b1 = Sb[sboff + 8 * nf + 1];
            sc[nf][0] += b0;
            sc[nf][1] += b1;
            sc[nf][2] += pb0;
            sc[nf][3] += pb1;
            pb0 = b0; pb1 = b1;
        }

        // ---- online softmax ----
        float mxa = -1e30f, mxb = -1e30f;
#pragma unroll
        for (int nf = 0; nf < 16; nf++) {
            mxa = fmaxf(mxa, fmaxf(sc[nf][0], sc[nf][1]));
            mxb = fmaxf(mxb, fmaxf(sc[nf][2], sc[nf][3]));
        }
        mxa = fmaxf(mxa, __shfl_xor_sync(0xffffffffu, mxa, 1));
        mxa = fmaxf(mxa, __shfl_xor_sync(0xffffffffu, mxa, 2));
        mxb = fmaxf(mxb, __shfl_xor_sync(0xffffffffu, mxb, 1));
        mxb = fmaxf(mxb, __shfl_xor_sync(0xffffffffu, mxb, 2));
        float mna = fmaxf(m_a, mxa), mnb = fmaxf(m_b, mxb);
        float ca = __expf(m_a - mna), cb = __expf(m_b - mnb);
        float sa = 0.f, sb2 = 0.f;
#pragma unroll
        for (int nf = 0; nf < 16; nf++) {
            sc[nf][0] = __expf(sc[nf][0] - mna);
            sc[nf][1] = __expf(sc[nf][1] - mna);
            sc[nf][2] = __expf(sc[nf][2] - mnb);
            sc[nf][3] = __expf(sc[nf][3] - mnb);
            sa  += sc[nf][0] + sc[nf][1];
            sb2 += sc[nf][2] + sc[nf][3];
        }
        sa  += __shfl_xor_sync(0xffffffffu, sa, 1);
        sa  += __shfl_xor_sync(0xffffffffu, sa, 2);
        sb2 += __shfl_xor_sync(0xffffffffu, sb2, 1);
        sb2 += __shfl_xor_sync(0xffffffffu, sb2, 2);
        l_a = l_a * ca + sa;
        l_b = l_b * cb + sb2;
        m_a = mna; m_b = mnb;

#pragma unroll
        for (int i = 0; i < 8; i++) {
            Oa[i][0] *= ca; Oa[i][1] *= ca;
            Oa[i][2] *= cb; Oa[i][3] *= cb;
        }

        // ---- phase 2: O += P V (ldmatrix V pairs) ----
#pragma unroll
        for (int ks2 = 0; ks2 < 8; ks2++) {
            uint32_t Ph[4], Pl[4];
            pack_hilo(sc[2*ks2][0],   sc[2*ks2][1],   Ph[0], Pl[0]);
            pack_hilo(sc[2*ks2][2],   sc[2*ks2][3],   Ph[1], Pl[1]);
            pack_hilo(sc[2*ks2+1][0], sc[2*ks2+1][1], Ph[2], Pl[2]);
            pack_hilo(sc[2*ks2+1][2], sc[2*ks2+1][3], Ph[3], Pl[3]);
            const int kw2 = ks2 * 8 + bcol_l;
#pragma unroll
            for (int j = 0; j < 4; j++) {
                uint32_t vd = sws + (uint32_t)(S_VH + (j * 16 + brow_l) * VSTR + kw2) * 4;
                uint32_t bf0[2], bf1[2];
                LDSM_X4(bf0[0], bf0[1], bf1[0], bf1[1], vd);
                mma_bf16(Oa[2 * j],     Ph, bf0);
                mma_bf16(Oa[2 * j + 1], Ph, bf1);
                mma_bf16(Oa[2 * j],     Pl, bf0);
                mma_bf16(Oa[2 * j + 1], Pl, bf1);
                LDSM_X4(bf0[0], bf0[1], bf1[0], bf1[1],
                        vd + (S_VL - S_VH) * 4);
                mma_bf16(Oa[2 * j],     Ph, bf0);
                mma_bf16(Oa[2 * j + 1], Ph, bf1);
            }
        }
        __syncthreads();
    }

    // ---- epilogue: write hi/lo bf16 straight into g_xhi/g_xlo --------------
    float inva = 1.0f / l_a, invb = 1.0f / l_b;
    int ra = q0 + 16 * wid + fr;
#pragma unroll
    for (int nf2 = 0; nf2 < 8; nf2++) {
        int d = nf2 * 8 + 2 * fc;
        size_t ia = (size_t)(b * SEQ + ra) * DM + h * DK + d;
        size_t ib = ia + (size_t)8 * DM;
        uint32_t hw, lw;
        pack_hilo(Oa[nf2][0] * inva, Oa[nf2][1] * inva, hw, lw);
        *(uint32_t*)&g_xhi[ia] = hw;
        *(uint32_t*)&g_xlo[ia] = lw;
        pack_hilo(Oa[nf2][2] * invb, Oa[nf2][3] * invb, hw, lw);
        *(uint32_t*)&g_xhi[ib] = hw;
        *(uint32_t*)&g_xlo[ib] = lw;
    }
}

// ---------------- launch ----------------------------------------------------
extern "C" void kernel_launch(void* const* d_in, const int* in_sizes, int n_in,
                              void* d_out, int out_size) {
    const float* X   = (const float*)d_in[0];
    const float* Wq  = (const float*)d_in[1];
    const float* Wk  = (const float*)d_in[2];
    const float* Wv  = (const float*)d_in[3];
    const float* Wo  = (const float*)d_in[4];
    const float* tbl = (const float*)d_in[5];
    float* out = (float*)d_out;

    cudaFuncSetAttribute(attn_mma,
                         cudaFuncAttributeMaxDynamicSharedMemorySize,
                         ATTN3_BYTES);
    cudaFuncSetAttribute(gemm_mma,
                         cudaFuncAttributeMaxDynamicSharedMemorySize,
                         GEMM_SMEM_BYTES);

    bias_kernel<<<(RELN + 255) / 256, 256>>>(tbl);

    xcvt<<<(MROWS * DM / 4 + 255) / 256, 256>>>(X, MROWS * DM / 4);
    dim3 gw(DM / 32, DM / 32, 4);
    wt_cvt<<<gw, dim3(32, 8)>>>(Wq, Wk, Wv, Wo);

    dim3 g1(DM / 128, MROWS / 128, 3);
    gemm_mma<<<g1, 256, GEMM_SMEM_BYTES>>>(0, 0, nullptr);

    dim3 gv(SEQ / 64, BSZ * NH);
    vcvt<<<gv, 256>>>();

    dim3 g2(SEQ / 128, BSZ * NH);
    attn_mma<<<g2, 256, ATTN3_BYTES>>>();

    dim3 g3(DM / 128, MROWS / 128, 1);
    gemm_mma<<<g3, 256, GEMM_SMEM_BYTES>>>(3, 1, out);
}

// round 11
// speedup vs baseline: 4.3640x; 1.0120x over previous
#include <cuda_runtime.h>
#include <cuda_bf16.h>
#include <math.h>
#include <stdint.h>

#define BSZ   2
#define SEQ   2048
#define DM    1024
#define NH    16
#define DK    64
#define RELN  (2*SEQ-1)   // 4095
#define MROWS (BSZ*SEQ)   // 4096

// ---------------- scratch (device globals; device-code access only) --------
__device__ float g_v[BSZ*NH*SEQ*DK];         // V fp32 [b][h][s][d] (vcvt input)
__device__ float g_bias[NH*RELN];            // [h][rel + S-1]

__device__ uint32_t g_qhi_w[BSZ*NH*SEQ*(DK/2)];   // Q packed hi words [bh][s][dw]
__device__ uint32_t g_qlo_w[BSZ*NH*SEQ*(DK/2)];
__device__ uint32_t g_khi_w[BSZ*NH*SEQ*(DK/2)];   // K packed words
__device__ uint32_t g_klo_w[BSZ*NH*SEQ*(DK/2)];
__device__ uint32_t g_vthi[BSZ*NH*DK*(SEQ/2)];    // V^T words [bh][d][u]
__device__ uint32_t g_vtlo[BSZ*NH*DK*(SEQ/2)];

__device__ __nv_bfloat16 g_xhi[MROWS*DM];   // activations hi/lo
__device__ __nv_bfloat16 g_xlo[MROWS*DM];
__device__ __nv_bfloat16 g_wth[4*DM*DM];    // W^T hi: [w][n][k]
__device__ __nv_bfloat16 g_wtl[4*DM*DM];    // W^T lo

// ======================= mma / ldmatrix / cp.async helpers ==================
__device__ __forceinline__ void mma_bf16(float acc[4], const uint32_t a[4],
                                         const uint32_t b[2]) {
    asm volatile(
        "mma.sync.aligned.m16n8k16.row.col.f32.bf16.bf16.f32 "
        "{%0,%1,%2,%3}, {%4,%5,%6,%7}, {%8,%9}, {%0,%1,%2,%3};"
        : "+f"(acc[0]), "+f"(acc[1]), "+f"(acc[2]), "+f"(acc[3])
        : "r"(a[0]), "r"(a[1]), "r"(a[2]), "r"(a[3]), "r"(b[0]), "r"(b[1]));
}
#define LDSM_X4(R0, R1, R2, R3, A) \
    asm volatile("ldmatrix.sync.aligned.m8n8.x4.shared.b16 {%0,%1,%2,%3}, [%4];" \
        : "=r"(R0), "=r"(R1), "=r"(R2), "=r"(R3) : "r"(A))
__device__ __forceinline__ uint32_t smem_u32(const void* p) {
    uint32_t a;
    asm("{ .reg .u64 t; cvta.to.shared.u64 t, %1; cvt.u32.u64 %0, t; }"
        : "=r"(a) : "l"(p));
    return a;
}
#define CP16(dst, src) \
    asm volatile("cp.async.cg.shared.global [%0], [%1], 16;" \
        :: "r"(dst), "l"(src))
#define CP_COMMIT() asm volatile("cp.async.commit_group;")
#define CP_WAIT(n)  asm volatile("cp.async.wait_group %0;" :: "n"(n))

__device__ __forceinline__ uint32_t packbf(float a, float b) {
    __nv_bfloat162 t;
    t.x = __float2bfloat16_rn(a);
    t.y = __float2bfloat16_rn(b);
    return *(uint32_t*)&t;
}
__device__ __forceinline__ void pack_hilo(float a, float b,
                                          uint32_t& hi, uint32_t& lo) {
    __nv_bfloat16 ha = __float2bfloat16_rn(a);
    __nv_bfloat16 hb = __float2bfloat16_rn(b);
    __nv_bfloat162 th; th.x = ha; th.y = hb;
    hi = *(uint32_t*)&th;
    lo = packbf(a - __bfloat162float(ha), b - __bfloat162float(hb));
}

// ---------------- relative-position bias precompute -------------------------
__global__ void bias_kernel(const float* __restrict__ table) {
    int idx = blockIdx.x * blockDim.x + threadIdx.x;
    if (idx >= RELN) return;
    int rel = idx - (SEQ - 1);
    int bucket = (rel > 0) ? 16 : 0;
    int rabs = rel < 0 ? -rel : rel;
    int add;
    if (rabs < 8) {
        add = rabs;
    } else {
        double lf = log((double)rabs / 8.0) / log(16.0) * 8.0;
        add = 8 + (int)lf;
        if (add > 15) add = 15;
    }
    bucket += add;
#pragma unroll
    for (int h = 0; h < NH; h++)
        g_bias[h * RELN + idx] = table[bucket * NH + h];
}

// ---------------- fp32 X -> (hi,lo) bf16 split -------------------------------
__global__ __launch_bounds__(256) void xcvt(const float* __restrict__ in,
                                            int n4) {
    int i = blockIdx.x * blockDim.x + threadIdx.x;
    if (i >= n4) return;
    float4 x = ((const float4*)in)[i];
    float xs[4] = {x.x, x.y, x.z, x.w};
    __nv_bfloat16 hb[4], lb[4];
#pragma unroll
    for (int j = 0; j < 4; j++) {
        hb[j] = __float2bfloat16_rn(xs[j]);
        lb[j] = __float2bfloat16_rn(xs[j] - __bfloat162float(hb[j]));
    }
    *(uint2*)&g_xhi[i * 4] = *(uint2*)hb;
    *(uint2*)&g_xlo[i * 4] = *(uint2*)lb;
}

// ---------------- W [K][N] -> W^T (hi,lo) bf16 [N][K] -----------------------
__global__ __launch_bounds__(256) void wt_cvt(const float* __restrict__ Wq,
                                              const float* __restrict__ Wk,
                                              const float* __restrict__ Wv,
                                              const float* __restrict__ Wo) {
    __shared__ float tile[32][33];
    int w = blockIdx.z;
    const float* W = (w == 0) ? Wq : (w == 1) ? Wk : (w == 2) ? Wv : Wo;
    int kb = blockIdx.y * 32, nb = blockIdx.x * 32;
    int tx = threadIdx.x, ty = threadIdx.y;
    for (int r = ty; r < 32; r += 8)
        tile[r][tx] = W[(size_t)(kb + r) * DM + nb + tx];
    __syncthreads();
    __nv_bfloat16* oh = g_wth + (size_t)w * DM * DM;
    __nv_bfloat16* ol = g_wtl + (size_t)w * DM * DM;
    for (int r = ty; r < 32; r += 8) {
        float x = tile[tx][r];
        __nv_bfloat16 h = __float2bfloat16_rn(x);
        __nv_bfloat16 l = __float2bfloat16_rn(x - __bfloat162float(h));
        size_t o = (size_t)(nb + r) * DM + kb + tx;
        oh[o] = h;
        ol[o] = l;
    }
}

// ---------------- V fp32 [s][d] -> V^T packed words [d][u] ------------------
__global__ __launch_bounds__(256) void vcvt() {
    __shared__ float sm[64][65];
    const int bh = blockIdx.y;
    const int s0 = blockIdx.x * 64;
    const int tid = threadIdx.x;
    const float* V = g_v + ((size_t)bh * SEQ + s0) * DK;
#pragma unroll
    for (int i = 0; i < 4; i++) {
        int idx = tid + i * 256;
        int r = idx >> 4, j = idx & 15;
        float4 v = *(const float4*)(V + r * DK + j * 4);
        sm[r][j * 4 + 0] = v.x;
        sm[r][j * 4 + 1] = v.y;
        sm[r][j * 4 + 2] = v.z;
        sm[r][j * 4 + 3] = v.w;
    }
    __syncthreads();
#pragma unroll
    for (int i = 0; i < 8; i++) {
        int idx = tid + i * 256;
        int d = idx >> 5, u = idx & 31;
        uint32_t hw, lw;
        pack_hilo(sm[2 * u][d], sm[2 * u + 1][d], hw, lw);
        size_t o = ((size_t)bh * DK + d) * (SEQ / 2) + (s0 >> 1) + u;
        g_vthi[o] = hw;
        g_vtlo[o] = lw;
    }
}

// ---------------- split-bf16 GEMM, one-barrier cp.async pipeline ------------
#define AW       2560
#define RSTRIDE  20
#define SLOT_W   (4*AW)
#define GEMM_SMEM_BYTES (2*SLOT_W*4)   // 81920

__global__ __launch_bounds__(256, 2) void gemm_mma(
    int wbase, int mode, float* __restrict__ outp)
{
    extern __shared__ __align__(16) uint32_t gsm[];

    const int tid = threadIdx.x;
    const int wid = tid >> 5, lane = tid & 31;
    const int wm = wid & 1;
    const int wn = wid >> 1;
    const int fr = lane >> 2;
    const int fc = lane & 3;
    const int arow_l = (lane & 7) + ((lane >> 3) & 1) * 8;
    const int acol_l = (lane >> 4) * 4;
    const int brow_l = (lane & 7) + (lane >> 4) * 8;
    const int bcol_l = ((lane >> 3) & 1) * 4;

    const int w  = wbase + blockIdx.z;
    const int m0 = blockIdx.y * 128;
    const int n0 = blockIdx.x * 128;
    const __nv_bfloat16* __restrict__ ah = g_xhi;
    const __nv_bfloat16* __restrict__ al = g_xlo;
    const __nv_bfloat16* __restrict__ bh = g_wth + (size_t)w * DM * DM;
    const __nv_bfloat16* __restrict__ bl = g_wtl + (size_t)w * DM * DM;

    const __nv_bfloat16* asrc[4];
    const __nv_bfloat16* bsrc[4];
    uint32_t adst[4], bdst[4];
    const uint32_t sb0 = smem_u32(gsm);
#pragma unroll
    for (int i = 0; i < 4; i++) {
        int idx = tid + i * 256;
        int sel = idx >> 9, r = (idx >> 2) & 127, j = idx & 3;
        asrc[i] = (sel ? al : ah) + (size_t)(m0 + r) * DM + j * 8;
        adst[i] = sb0 + (uint32_t)(sel * AW + r * RSTRIDE + j * 4) * 4;
        bsrc[i] = (sel ? bl : bh) + (size_t)(n0 + r) * DM + j * 8;
        bdst[i] = sb0 + (uint32_t)(2 * AW + sel * AW + r * RSTRIDE + j * 4) * 4;
    }

    const int a_base_w = (wm * 64 + arow_l) * RSTRIDE + acol_l;
    const int b_base_w = (wn * 32 + brow_l) * RSTRIDE + bcol_l;

    float acc[4][4][4];
#pragma unroll
    for (int i = 0; i < 4; i++)
#pragma unroll
        for (int j = 0; j < 4; j++)
#pragma unroll
            for (int q = 0; q < 4; q++) acc[i][j][q] = 0.f;

    // prologue: prefetch chunk 0 into slot 0
#pragma unroll
    for (int i = 0; i < 4; i++) {
        CP16(adst[i], asrc[i]);
        CP16(bdst[i], bsrc[i]);
    }
    CP_COMMIT();

    for (int c = 0; c < 32; c++) {
        CP_WAIT(0);          // chunk c landed (sole pending group)
        __syncthreads();     // all warps: chunk c visible AND other slot free
        if (c < 31) {        // prefetch chunk c+1 into the other slot
            const int k1 = (c + 1) * 32;
            const uint32_t so = ((c + 1) & 1) * (SLOT_W * 4);
#pragma unroll
            for (int i = 0; i < 4; i++) {
                CP16(adst[i] + so, asrc[i] + k1);
                CP16(bdst[i] + so, bsrc[i] + k1);
            }
            CP_COMMIT();
        }

        const uint32_t sws = sb0 + (c & 1) * (SLOT_W * 4);
#pragma unroll
        for (int ks = 0; ks < 2; ks++) {
            const int kw = ks * 8;
            uint32_t Af[4][4], Bhf[4][2], Blf[4][2];
#pragma unroll
            for (int mf = 0; mf < 4; mf++) {
                uint32_t ad = sws + (uint32_t)(a_base_w + mf * 16 * RSTRIDE + kw) * 4;
                LDSM_X4(Af[mf][0], Af[mf][1], Af[mf][2], Af[mf][3], ad);
            }
#pragma unroll
            for (int j = 0; j < 2; j++) {
                uint32_t bd = sws + (uint32_t)(2 * AW + b_base_w + j * 16 * RSTRIDE + kw) * 4;
                LDSM_X4(Bhf[2 * j][0], Bhf[2 * j][1],
                        Bhf[2 * j + 1][0], Bhf[2 * j + 1][1], bd);
                LDSM_X4(Blf[2 * j][0], Blf[2 * j][1],
                        Blf[2 * j + 1][0], Blf[2 * j + 1][1], bd + AW * 4);
            }
#pragma unroll
            for (int mf = 0; mf < 4; mf++)
#pragma unroll
                for (int nf = 0; nf < 4; nf++)
                    mma_bf16(acc[mf][nf], Af[mf], Bhf[nf]);   // hi*hi
#pragma unroll
            for (int mf = 0; mf < 4; mf++)
#pragma unroll
                for (int nf = 0; nf < 4; nf++)
                    mma_bf16(acc[mf][nf], Af[mf], Blf[nf]);   // hi*lo
#pragma unroll
            for (int mf = 0; mf < 4; mf++) {
                uint32_t ad = sws + (uint32_t)(AW + a_base_w + mf * 16 * RSTRIDE + kw) * 4;
                LDSM_X4(Af[mf][0], Af[mf][1], Af[mf][2], Af[mf][3], ad);
            }
#pragma unroll
            for (int mf = 0; mf < 4; mf++)
#pragma unroll
                for (int nf = 0; nf < 4; nf++)
                    mma_bf16(acc[mf][nf], Af[mf], Bhf[nf]);   // lo*hi
        }
    }

    // ---- epilogue ----
#pragma unroll
    for (int mf = 0; mf < 4; mf++) {
        int row = m0 + wm * 64 + mf * 16 + fr;
#pragma unroll
        for (int nf = 0; nf < 4; nf++) {
            int n = n0 + wn * 32 + nf * 8 + fc * 2;
            if (mode == 0) {
                int h = n >> 6, d = n & 63;
                int b = row >> 11, s = row & (SEQ - 1);
                size_t wi = ((size_t)(b * NH + h) * SEQ + s) * (DK / 2) + (d >> 1);
                if (w < 2) {
                    uint32_t* dsth = (w == 0) ? g_qhi_w : g_khi_w;
                    uint32_t* dstl = (w == 0) ? g_qlo_w : g_klo_w;
                    uint32_t hw, lw;
                    pack_hilo(acc[mf][nf][0], acc[mf][nf][1], hw, lw);
                    dsth[wi] = hw; dstl[wi] = lw;
                    pack_hilo(acc[mf][nf][2], acc[mf][nf][3], hw, lw);
                    dsth[wi + 8 * (DK / 2)] = hw;
                    dstl[wi + 8 * (DK / 2)] = lw;
                } else {
                    size_t base = ((size_t)(b * NH + h) * SEQ + s) * DK + d;
                    *(float2*)(g_v + base) =
                        make_float2(acc[mf][nf][0], acc[mf][nf][1]);
                    *(float2*)(g_v + base + 8 * DK) =
                        make_float2(acc[mf][nf][2], acc[mf][nf][3]);
                }
            } else {
                *(float2*)(outp + (size_t)row * DM + n) =
                    make_float2(acc[mf][nf][0], acc[mf][nf][1]);
                *(float2*)(outp + (size_t)(row + 8) * DM + n) =
                    make_float2(acc[mf][nf][2], acc[mf][nf][3]);
            }
        }
    }
}

// ---------------- flash attention, one-barrier cp.async pipeline ------------
#define KSTR 36
#define VSTR 68
#define S_KH 0
#define S_KL (128*KSTR)
#define S_VH (2*128*KSTR)
#define S_VL (S_VH + 64*VSTR)
#define S_SB (S_VH + 2*64*VSTR)
#define SLOT3_W (S_SB + 256)
#define ATTN3_BYTES (2*SLOT3_W*4)   // 145408

__global__ __launch_bounds__(256, 1) void attn_mma() {
    extern __shared__ __align__(16) uint32_t SW3[];

    const int bh = blockIdx.y;
    const int h = bh & (NH - 1);
    const int b = bh >> 4;
    const int q0 = blockIdx.x * 128;
    const int tid = threadIdx.x;
    const int wid = tid >> 5, lane = tid & 31;
    const int fr = lane >> 2, fc = lane & 3;
    const int brow_l = (lane & 7) + (lane >> 4) * 8;
    const int bcol_l = ((lane >> 3) & 1) * 4;

    const size_t kwbase = (size_t)bh * SEQ * (DK / 2);
    const size_t vwbase = (size_t)bh * DK * (SEQ / 2);
    const uint32_t sb0 = smem_u32(SW3);

    uint32_t Qh[4][4], Ql[4][4];
    {
        const size_t qb = kwbase + (size_t)(q0 + 16 * wid + fr) * (DK / 2);
#pragma unroll
        for (int ks = 0; ks < 4; ks++) {
            size_t i0 = qb + ks * 8 + fc;
            Qh[ks][0] = g_qhi_w[i0];
            Qh[ks][1] = g_qhi_w[i0 + 8 * (DK / 2)];
            Qh[ks][2] = g_qhi_w[i0 + 4];
            Qh[ks][3] = g_qhi_w[i0 + 8 * (DK / 2) + 4];
            Ql[ks][0] = g_qlo_w[i0];
            Ql[ks][1] = g_qlo_w[i0 + 8 * (DK / 2)];
            Ql[ks][2] = g_qlo_w[i0 + 4];
            Ql[ks][3] = g_qlo_w[i0 + 8 * (DK / 2) + 4];
        }
    }

    float Oa[8][4];
#pragma unroll
    for (int i = 0; i < 8; i++)
#pragma unroll
        for (int q = 0; q < 4; q++) Oa[i][q] = 0.f;
    float m_a = -1e30f, m_b = -1e30f, l_a = 0.f, l_b = 0.f;

    const int sboff = 2 * fc - 16 * wid - fr + 128;

    auto prefetch = [&](int t) {
        const int slot = t & 1;
        const uint32_t sbase = sb0 + slot * SLOT3_W * 4;
        const int k0 = t * 128;
#pragma unroll
        for (int i = 0; i < 4; i++) {
            int idx = tid + i * 256;
            int r = idx >> 3, jc = idx & 7;
            size_t src = kwbase + (size_t)(k0 + r) * (DK / 2) + jc * 4;
            uint32_t doff = (uint32_t)(r * KSTR + jc * 4) * 4;
            CP16(sbase + S_KH * 4 + doff, g_khi_w + src);
            CP16(sbase + S_KL * 4 + doff, g_klo_w + src);
        }
#pragma unroll
        for (int i = 0; i < 4; i++) {
            int idx = tid + i * 256;
            int d = idx >> 4, jc = idx & 15;
            size_t src = vwbase + (size_t)d * (SEQ / 2) + (k0 >> 1) + jc * 4;
            uint32_t doff = (uint32_t)(d * VSTR + jc * 4) * 4;
            CP16(sbase + S_VH * 4 + doff, g_vthi + src);
            CP16(sbase + S_VL * 4 + doff, g_vtlo + src);
        }
        {
            int gi = 2047 + k0 - q0 + tid - 128;
            gi = gi < 0 ? 0 : (gi > RELN - 1 ? RELN - 1 : gi);
            float bv = g_bias[h * RELN + gi];
            SW3[slot * SLOT3_W + S_SB + tid] = __float_as_uint(bv);
        }
    };

    prefetch(0);
    CP_COMMIT();

    for (int t = 0; t < SEQ / 128; t++) {
        CP_WAIT(0);          // tile t landed
        __syncthreads();     // visible to all; other slot fully consumed
        if (t < SEQ / 128 - 1) {
            prefetch(t + 1);
            CP_COMMIT();
        }

        const uint32_t sws = sb0 + (t & 1) * SLOT3_W * 4;
        const float* Sb = (const float*)(SW3 + (t & 1) * SLOT3_W + S_SB);

        // ---- phase 1: S = Q K^T (ldmatrix pairs, 3-term split) ----
        float sc[16][4];
#pragma unroll
        for (int nf = 0; nf < 16; nf++)
#pragma unroll
            for (int q = 0; q < 4; q++) sc[nf][q] = 0.f;

#pragma unroll
        for (int ks = 0; ks < 4; ks++) {
            const int kw = ks * 8 + bcol_l;
#pragma unroll
            for (int j = 0; j < 8; j++) {
                uint32_t kd = sws + (uint32_t)(S_KH + (j * 16 + brow_l) * KSTR + kw) * 4;
                uint32_t bf0[2], bf1[2];
                LDSM_X4(bf0[0], bf0[1], bf1[0], bf1[1], kd);
                mma_bf16(sc[2 * j],     Qh[ks], bf0);
                mma_bf16(sc[2 * j + 1], Qh[ks], bf1);
                mma_bf16(sc[2 * j],     Ql[ks], bf0);
                mma_bf16(sc[2 * j + 1], Ql[ks], bf1);
                LDSM_X4(bf0[0], bf0[1], bf1[0], bf1[1],
                        kd + (S_KL - S_KH) * 4);
                mma_bf16(sc[2 * j],     Qh[ks], bf0);
                mma_bf16(sc[2 * j + 1], Qh[ks], bf1);
            }
        }

        // ---- bias add ----
        float pb0 = Sb[sboff - 8], pb1 = Sb[sboff - 7];
#pragma unroll
        for (int nf = 0; nf < 16; nf++) {
            float b0 = Sb[sboff + 8 * nf];
            float b1 = Sb[sboff + 8 * nf + 1];
            sc[nf][0] += b0;
            sc[nf][1] += b1;
            sc[nf][2] += pb0;
            sc[nf][3] += pb1;
            pb0 = b0; pb1 = b1;
        }

        // ---- online softmax ----
        float mxa = -1e30f, mxb = -1e30f;
#pragma unroll
        for (int nf = 0; nf < 16; nf++) {
            mxa = fmaxf(mxa, fmaxf(sc[nf][0], sc[nf][1]));
            mxb = fmaxf(mxb, fmaxf(sc[nf][2], sc[nf][3]));
        }
        mxa = fmaxf(mxa, __shfl_xor_sync(0xffffffffu, mxa, 1));
        mxa = fmaxf(mxa, __shfl_xor_sync(0xffffffffu, mxa, 2));
        mxb = fmaxf(mxb, __shfl_xor_sync(0xffffffffu, mxb, 1));
        mxb = fmaxf(mxb, __shfl_xor_sync(0xffffffffu, mxb, 2));
        float mna = fmaxf(m_a, mxa), mnb = fmaxf(m_b, mxb);
        float ca = __expf(m_a - mna), cb = __expf(m_b - mnb);
        float sa = 0.f, sb2 = 0.f;
#pragma unroll
        for (int nf = 0; nf < 16; nf++) {
            sc[nf][0] = __expf(sc[nf][0] - mna);
            sc[nf][1] = __expf(sc[nf][1] - mna);
            sc[nf][2] = __expf(sc[nf][2] - mnb);
            sc[nf][3] = __expf(sc[nf][3] - mnb);
            sa  += sc[nf][0] + sc[nf][1];
            sb2 += sc[nf][2] + sc[nf][3];
        }
        sa  += __shfl_xor_sync(0xffffffffu, sa, 1);
        sa  += __shfl_xor_sync(0xffffffffu, sa, 2);
        sb2 += __shfl_xor_sync(0xffffffffu, sb2, 1);
        sb2 += __shfl_xor_sync(0xffffffffu, sb2, 2);
        l_a = l_a * ca + sa;
        l_b = l_b * cb + sb2;
        m_a = mna; m_b = mnb;

#pragma unroll
        for (int i = 0; i < 8; i++) {
            Oa[i][0] *= ca; Oa[i][1] *= ca;
            Oa[i][2] *= cb; Oa[i][3] *= cb;
        }

        // ---- phase 2: O += P V (ldmatrix V pairs) ----
#pragma unroll
        for (int ks2 = 0; ks2 < 8; ks2++) {
            uint32_t Ph[4], Pl[4];
            pack_hilo(sc[2*ks2][0],   sc[2*ks2][1],   Ph[0], Pl[0]);
            pack_hilo(sc[2*ks2][2],   sc[2*ks2][3],   Ph[1], Pl[1]);
            pack_hilo(sc[2*ks2+1][0], sc[2*ks2+1][1], Ph[2], Pl[2]);
            pack_hilo(sc[2*ks2+1][2], sc[2*ks2+1][3], Ph[3], Pl[3]);
            const int kw2 = ks2 * 8 + bcol_l;
#pragma unroll
            for (int j = 0; j < 4; j++) {
                uint32_t vd = sws + (uint32_t)(S_VH + (j * 16 + brow_l) * VSTR + kw2) * 4;
                uint32_t bf0[2], bf1[2];
                LDSM_X4(bf0[0], bf0[1], bf1[0], bf1[1], vd);
                mma_bf16(Oa[2 * j],     Ph, bf0);
                mma_bf16(Oa[2 * j + 1], Ph, bf1);
                mma_bf16(Oa[2 * j],     Pl, bf0);
                mma_bf16(Oa[2 * j + 1], Pl, bf1);
                LDSM_X4(bf0[0], bf0[1], bf1[0], bf1[1],
                        vd + (S_VL - S_VH) * 4);
                mma_bf16(Oa[2 * j],     Ph, bf0);
                mma_bf16(Oa[2 * j + 1], Ph, bf1);
            }
        }
    }

    // ---- epilogue: write hi/lo bf16 straight into g_xhi/g_xlo --------------
    float inva = 1.0f / l_a, invb = 1.0f / l_b;
    int ra = q0 + 16 * wid + fr;
#pragma unroll
    for (int nf2 = 0; nf2 < 8; nf2++) {
        int d = nf2 * 8 + 2 * fc;
        size_t ia = (size_t)(b * SEQ + ra) * DM + h * DK + d;
        size_t ib = ia + (size_t)8 * DM;
        uint32_t hw, lw;
        pack_hilo(Oa[nf2][0] * inva, Oa[nf2][1] * inva, hw, lw);
        *(uint32_t*)&g_xhi[ia] = hw;
        *(uint32_t*)&g_xlo[ia] = lw;
        pack_hilo(Oa[nf2][2] * invb, Oa[nf2][3] * invb, hw, lw);
        *(uint32_t*)&g_xhi[ib] = hw;
        *(uint32_t*)&g_xlo[ib] = lw;
    }
}

// ---------------- launch ----------------------------------------------------
extern "C" void kernel_launch(void* const* d_in, const int* in_sizes, int n_in,
                              void* d_out, int out_size) {
    const float* X   = (const float*)d_in[0];
    const float* Wq  = (const float*)d_in[1];
    const float* Wk  = (const float*)d_in[2];
    const float* Wv  = (const float*)d_in[3];
    const float* Wo  = (const float*)d_in[4];
    const float* tbl = (const float*)d_in[5];
    float* out = (float*)d_out;

    cudaFuncSetAttribute(attn_mma,
                         cudaFuncAttributeMaxDynamicSharedMemorySize,
                         ATTN3_BYTES);
    cudaFuncSetAttribute(gemm_mma,
                         cudaFuncAttributeMaxDynamicSharedMemorySize,
                         GEMM_SMEM_BYTES);

    bias_kernel<<<(RELN + 255) / 256, 256>>>(tbl);

    xcvt<<<(MROWS * DM / 4 + 255) / 256, 256>>>(X, MROWS * DM / 4);
    dim3 gw(DM / 32, DM / 32, 4);
    wt_cvt<<<gw, dim3(32, 8)>>>(Wq, Wk, Wv, Wo);

    dim3 g1(DM / 128, MROWS / 128, 3);
    gemm_mma<<<g1, 256, GEMM_SMEM_BYTES>>>(0, 0, nullptr);

    dim3 gv(SEQ / 64, BSZ * NH);
    vcvt<<<gv, 256>>>();

    dim3 g2(SEQ / 128, BSZ * NH);
    attn_mma<<<g2, 256, ATTN3_BYTES>>>();

    dim3 g3(DM / 128, MROWS / 128, 1);
    gemm_mma<<<g3, 256, GEMM_SMEM_BYTES>>>(3, 1, out);
}

// round 12
// speedup vs baseline: 4.4823x; 1.0271x over previous
#include <cuda_runtime.h>
#include <cuda_bf16.h>
#include <math.h>
#include <stdint.h>

#define BSZ   2
#define SEQ   2048
#define DM    1024
#define NH    16
#define DK    64
#define RELN  (2*SEQ-1)   // 4095
#define MROWS (BSZ*SEQ)   // 4096

// ---------------- scratch (device globals; device-code access only) --------
__device__ float g_bias[NH*RELN];            // [h][rel + S-1]

__device__ uint32_t g_qhi_w[BSZ*NH*SEQ*(DK/2)];   // Q packed hi words [bh][s][dw]
__device__ uint32_t g_qlo_w[BSZ*NH*SEQ*(DK/2)];
__device__ uint32_t g_khi_w[BSZ*NH*SEQ*(DK/2)];   // K packed words
__device__ uint32_t g_klo_w[BSZ*NH*SEQ*(DK/2)];
__device__ uint32_t g_vthi[BSZ*NH*DK*(SEQ/2)];    // V^T words [bh][d][u]
__device__ uint32_t g_vtlo[BSZ*NH*DK*(SEQ/2)];

__device__ __nv_bfloat16 g_xhi[MROWS*DM];   // activations hi/lo
__device__ __nv_bfloat16 g_xlo[MROWS*DM];
__device__ __nv_bfloat16 g_wth[4*DM*DM];    // W^T hi: [w][n][k]
__device__ __nv_bfloat16 g_wtl[4*DM*DM];    // W^T lo

// ======================= mma / ldmatrix / cp.async helpers ==================
__device__ __forceinline__ void mma_bf16(float acc[4], const uint32_t a[4],
                                         const uint32_t b[2]) {
    asm volatile(
        "mma.sync.aligned.m16n8k16.row.col.f32.bf16.bf16.f32 "
        "{%0,%1,%2,%3}, {%4,%5,%6,%7}, {%8,%9}, {%0,%1,%2,%3};"
        : "+f"(acc[0]), "+f"(acc[1]), "+f"(acc[2]), "+f"(acc[3])
        : "r"(a[0]), "r"(a[1]), "r"(a[2]), "r"(a[3]), "r"(b[0]), "r"(b[1]));
}
#define LDSM_X4(R0, R1, R2, R3, A) \
    asm volatile("ldmatrix.sync.aligned.m8n8.x4.shared.b16 {%0,%1,%2,%3}, [%4];" \
        : "=r"(R0), "=r"(R1), "=r"(R2), "=r"(R3) : "r"(A))
__device__ __forceinline__ uint32_t smem_u32(const void* p) {
    uint32_t a;
    asm("{ .reg .u64 t; cvta.to.shared.u64 t, %1; cvt.u32.u64 %0, t; }"
        : "=r"(a) : "l"(p));
    return a;
}
#define CP16(dst, src) \
    asm volatile("cp.async.cg.shared.global [%0], [%1], 16;" \
        :: "r"(dst), "l"(src))
#define CP_COMMIT() asm volatile("cp.async.commit_group;")
#define CP_WAIT(n)  asm volatile("cp.async.wait_group %0;" :: "n"(n))

__device__ __forceinline__ uint32_t packbf(float a, float b) {
    __nv_bfloat162 t;
    t.x = __float2bfloat16_rn(a);
    t.y = __float2bfloat16_rn(b);
    return *(uint32_t*)&t;
}
__device__ __forceinline__ void pack_hilo(float a, float b,
                                          uint32_t& hi, uint32_t& lo) {
    __nv_bfloat16 ha = __float2bfloat16_rn(a);
    __nv_bfloat16 hb = __float2bfloat16_rn(b);
    __nv_bfloat162 th; th.x = ha; th.y = hb;
    hi = *(uint32_t*)&th;
    lo = packbf(a - __bfloat162float(ha), b - __bfloat162float(hb));
}

// ---------------- relative-position bias precompute -------------------------
__global__ void bias_kernel(const float* __restrict__ table) {
    int idx = blockIdx.x * blockDim.x + threadIdx.x;
    if (idx >= RELN) return;
    int rel = idx - (SEQ - 1);
    int bucket = (rel > 0) ? 16 : 0;
    int rabs = rel < 0 ? -rel : rel;
    int add;
    if (rabs < 8) {
        add = rabs;
    } else {
        double lf = log((double)rabs / 8.0) / log(16.0) * 8.0;
        add = 8 + (int)lf;
        if (add > 15) add = 15;
    }
    bucket += add;
#pragma unroll
    for (int h = 0; h < NH; h++)
        g_bias[h * RELN + idx] = table[bucket * NH + h];
}

// ---------------- fp32 X -> (hi,lo) bf16 split -------------------------------
__global__ __launch_bounds__(256) void xcvt(const float* __restrict__ in,
                                            int n4) {
    int i = blockIdx.x * blockDim.x + threadIdx.x;
    if (i >= n4) return;
    float4 x = ((const float4*)in)[i];
    float xs[4] = {x.x, x.y, x.z, x.w};
    __nv_bfloat16 hb[4], lb[4];
#pragma unroll
    for (int j = 0; j < 4; j++) {
        hb[j] = __float2bfloat16_rn(xs[j]);
        lb[j] = __float2bfloat16_rn(xs[j] - __bfloat162float(hb[j]));
    }
    *(uint2*)&g_xhi[i * 4] = *(uint2*)hb;
    *(uint2*)&g_xlo[i * 4] = *(uint2*)lb;
}

// ---------------- W [K][N] -> W^T (hi,lo) bf16 [N][K] -----------------------
__global__ __launch_bounds__(256) void wt_cvt(const float* __restrict__ Wq,
                                              const float* __restrict__ Wk,
                                              const float* __restrict__ Wv,
                                              const float* __restrict__ Wo) {
    __shared__ float tile[32][33];
    int w = blockIdx.z;
    const float* W = (w == 0) ? Wq : (w == 1) ? Wk : (w == 2) ? Wv : Wo;
    int kb = blockIdx.y * 32, nb = blockIdx.x * 32;
    int tx = threadIdx.x, ty = threadIdx.y;
    for (int r = ty; r < 32; r += 8)
        tile[r][tx] = W[(size_t)(kb + r) * DM + nb + tx];
    __syncthreads();
    __nv_bfloat16* oh = g_wth + (size_t)w * DM * DM;
    __nv_bfloat16* ol = g_wtl + (size_t)w * DM * DM;
    for (int r = ty; r < 32; r += 8) {
        float x = tile[tx][r];
        __nv_bfloat16 h = __float2bfloat16_rn(x);
        __nv_bfloat16 l = __float2bfloat16_rn(x - __bfloat162float(h));
        size_t o = (size_t)(nb + r) * DM + kb + tx;
        oh[o] = h;
        ol[o] = l;
    }
}

// ---------------- split-bf16 GEMM, one-barrier cp.async pipeline ------------
#define AW       2560
#define RSTRIDE  20
#define SLOT_W   (4*AW)
#define GEMM_SMEM_BYTES (2*SLOT_W*4)   // 81920
#define VPAD 133

__global__ __launch_bounds__(256, 2) void gemm_mma(
    int wbase, int mode, float* __restrict__ outp)
{
    extern __shared__ __align__(16) uint32_t gsm[];

    const int tid = threadIdx.x;
    const int wid = tid >> 5, lane = tid & 31;
    const int wm = wid & 1;
    const int wn = wid >> 1;
    const int fr = lane >> 2;
    const int fc = lane & 3;
    const int arow_l = (lane & 7) + ((lane >> 3) & 1) * 8;
    const int acol_l = (lane >> 4) * 4;
    const int brow_l = (lane & 7) + (lane >> 4) * 8;
    const int bcol_l = ((lane >> 3) & 1) * 4;

    const int w  = wbase + blockIdx.z;
    const int m0 = blockIdx.y * 128;
    const int n0 = blockIdx.x * 128;
    const __nv_bfloat16* __restrict__ ah = g_xhi;
    const __nv_bfloat16* __restrict__ al = g_xlo;
    const __nv_bfloat16* __restrict__ bh = g_wth + (size_t)w * DM * DM;
    const __nv_bfloat16* __restrict__ bl = g_wtl + (size_t)w * DM * DM;

    const __nv_bfloat16* asrc[4];
    const __nv_bfloat16* bsrc[4];
    uint32_t adst[4], bdst[4];
    const uint32_t sb0 = smem_u32(gsm);
#pragma unroll
    for (int i = 0; i < 4; i++) {
        int idx = tid + i * 256;
        int sel = idx >> 9, r = (idx >> 2) & 127, j = idx & 3;
        asrc[i] = (sel ? al : ah) + (size_t)(m0 + r) * DM + j * 8;
        adst[i] = sb0 + (uint32_t)(sel * AW + r * RSTRIDE + j * 4) * 4;
        bsrc[i] = (sel ? bl : bh) + (size_t)(n0 + r) * DM + j * 8;
        bdst[i] = sb0 + (uint32_t)(2 * AW + sel * AW + r * RSTRIDE + j * 4) * 4;
    }

    const int a_base_w = (wm * 64 + arow_l) * RSTRIDE + acol_l;
    const int b_base_w = (wn * 32 + brow_l) * RSTRIDE + bcol_l;

    float acc[4][4][4];
#pragma unroll
    for (int i = 0; i < 4; i++)
#pragma unroll
        for (int j = 0; j < 4; j++)
#pragma unroll
            for (int q = 0; q < 4; q++) acc[i][j][q] = 0.f;

    // prologue: prefetch chunk 0 into slot 0
#pragma unroll
    for (int i = 0; i < 4; i++) {
        CP16(adst[i], asrc[i]);
        CP16(bdst[i], bsrc[i]);
    }
    CP_COMMIT();

    for (int c = 0; c < 32; c++) {
        CP_WAIT(0);          // chunk c landed
        __syncthreads();     // visible to all; other slot fully consumed

        const uint32_t sws = sb0 + (c & 1) * (SLOT_W * 4);
#pragma unroll
        for (int ks = 0; ks < 2; ks++) {
            const int kw = ks * 8;
            uint32_t Af[4][4], Bhf[4][2], Blf[4][2];
            // LDSM first: get tensor food queued before anything else
#pragma unroll
            for (int mf = 0; mf < 4; mf++) {
                uint32_t ad = sws + (uint32_t)(a_base_w + mf * 16 * RSTRIDE + kw) * 4;
                LDSM_X4(Af[mf][0], Af[mf][1], Af[mf][2], Af[mf][3], ad);
            }
#pragma unroll
            for (int j = 0; j < 2; j++) {
                uint32_t bd = sws + (uint32_t)(2 * AW + b_base_w + j * 16 * RSTRIDE + kw) * 4;
                LDSM_X4(Bhf[2 * j][0], Bhf[2 * j][1],
                        Bhf[2 * j + 1][0], Bhf[2 * j + 1][1], bd);
                LDSM_X4(Blf[2 * j][0], Blf[2 * j][1],
                        Blf[2 * j + 1][0], Blf[2 * j + 1][1], bd + AW * 4);
            }
            // prefetch next chunk AFTER the ks0 fragments are in flight
            if (ks == 0 && c < 31) {
                const int k1 = (c + 1) * 32;
                const uint32_t so = ((c + 1) & 1) * (SLOT_W * 4);
#pragma unroll
                for (int i = 0; i < 4; i++) {
                    CP16(adst[i] + so, asrc[i] + k1);
                    CP16(bdst[i] + so, bsrc[i] + k1);
                }
                CP_COMMIT();
            }
#pragma unroll
            for (int mf = 0; mf < 4; mf++)
#pragma unroll
                for (int nf = 0; nf < 4; nf++)
                    mma_bf16(acc[mf][nf], Af[mf], Bhf[nf]);   // hi*hi
#pragma unroll
            for (int mf = 0; mf < 4; mf++)
#pragma unroll
                for (int nf = 0; nf < 4; nf++)
                    mma_bf16(acc[mf][nf], Af[mf], Blf[nf]);   // hi*lo
#pragma unroll
            for (int mf = 0; mf < 4; mf++) {
                uint32_t ad = sws + (uint32_t)(AW + a_base_w + mf * 16 * RSTRIDE + kw) * 4;
                LDSM_X4(Af[mf][0], Af[mf][1], Af[mf][2], Af[mf][3], ad);
            }
#pragma unroll
            for (int mf = 0; mf < 4; mf++)
#pragma unroll
                for (int nf = 0; nf < 4; nf++)
                    mma_bf16(acc[mf][nf], Af[mf], Bhf[nf]);   // lo*hi
        }
    }

    // ---- epilogue ----
    if (mode == 0 && w == 2) {
        // V: transpose + pack straight into g_vthi/g_vtlo via smem staging
        __syncthreads();                       // all warps done with slots
        float* SMF = (float*)gsm;              // [128][VPAD]
#pragma unroll
        for (int mf = 0; mf < 4; mf++) {
            int rl = wm * 64 + mf * 16 + fr;
#pragma unroll
            for (int nf = 0; nf < 4; nf++) {
                int nl = wn * 32 + nf * 8 + fc * 2;
                SMF[rl * VPAD + nl]           = acc[mf][nf][0];
                SMF[rl * VPAD + nl + 1]       = acc[mf][nf][1];
                SMF[(rl + 8) * VPAD + nl]     = acc[mf][nf][2];
                SMF[(rl + 8) * VPAD + nl + 1] = acc[mf][nf][3];
            }
        }
        __syncthreads();
        const int b = m0 >> 11, s0 = m0 & (SEQ - 1);
#pragma unroll
        for (int i = 0; i < 32; i++) {
            int idx = tid + i * 256;           // 0..8191
            int hh = idx >> 12, rem = idx & 4095;
            int d = rem >> 6, u = rem & 63;
            float v0 = SMF[(2 * u) * VPAD + hh * 64 + d];
            float v1 = SMF[(2 * u + 1) * VPAD + hh * 64 + d];
            uint32_t hw, lw;
            pack_hilo(v0, v1, hw, lw);
            int h = blockIdx.x * 2 + hh;
            size_t o = ((size_t)(b * NH + h) * DK + d) * (SEQ / 2) + (s0 >> 1) + u;
            g_vthi[o] = hw;
            g_vtlo[o] = lw;
        }
        return;
    }
#pragma unroll
    for (int mf = 0; mf < 4; mf++) {
        int row = m0 + wm * 64 + mf * 16 + fr;
#pragma unroll
        for (int nf = 0; nf < 4; nf++) {
            int n = n0 + wn * 32 + nf * 8 + fc * 2;
            if (mode == 0) {
                int h = n >> 6, d = n & 63;
                int b = row >> 11, s = row & (SEQ - 1);
                size_t wi = ((size_t)(b * NH + h) * SEQ + s) * (DK / 2) + (d >> 1);
                uint32_t* dsth = (w == 0) ? g_qhi_w : g_khi_w;
                uint32_t* dstl = (w == 0) ? g_qlo_w : g_klo_w;
                uint32_t hw, lw;
                pack_hilo(acc[mf][nf][0], acc[mf][nf][1], hw, lw);
                dsth[wi] = hw; dstl[wi] = lw;
                pack_hilo(acc[mf][nf][2], acc[mf][nf][3], hw, lw);
                dsth[wi + 8 * (DK / 2)] = hw;
                dstl[wi + 8 * (DK / 2)] = lw;
            } else {
                *(float2*)(outp + (size_t)row * DM + n) =
                    make_float2(acc[mf][nf][0], acc[mf][nf][1]);
                *(float2*)(outp + (size_t)(row + 8) * DM + n) =
                    make_float2(acc[mf][nf][2], acc[mf][nf][3]);
            }
        }
    }
}

// ---------------- flash attention, one-barrier cp.async pipeline ------------
#define KSTR 36
#define VSTR 68
#define S_KH 0
#define S_KL (128*KSTR)
#define S_VH (2*128*KSTR)
#define S_VL (S_VH + 64*VSTR)
#define S_SB (S_VH + 2*64*VSTR)
#define SLOT3_W (S_SB + 256)
#define ATTN3_BYTES (2*SLOT3_W*4)   // 145408

__global__ __launch_bounds__(256, 1) void attn_mma() {
    extern __shared__ __align__(16) uint32_t SW3[];

    const int bh = blockIdx.y;
    const int h = bh & (NH - 1);
    const int b = bh >> 4;
    const int q0 = blockIdx.x * 128;
    const int tid = threadIdx.x;
    const int wid = tid >> 5, lane = tid & 31;
    const int fr = lane >> 2, fc = lane & 3;
    const int brow_l = (lane & 7) + (lane >> 4) * 8;
    const int bcol_l = ((lane >> 3) & 1) * 4;

    const size_t kwbase = (size_t)bh * SEQ * (DK / 2);
    const size_t vwbase = (size_t)bh * DK * (SEQ / 2);
    const uint32_t sb0 = smem_u32(SW3);

    uint32_t Qh[4][4], Ql[4][4];
    {
        const size_t qb = kwbase + (size_t)(q0 + 16 * wid + fr) * (DK / 2);
#pragma unroll
        for (int ks = 0; ks < 4; ks++) {
            size_t i0 = qb + ks * 8 + fc;
            Qh[ks][0] = g_qhi_w[i0];
            Qh[ks][1] = g_qhi_w[i0 + 8 * (DK / 2)];
            Qh[ks][2] = g_qhi_w[i0 + 4];
            Qh[ks][3] = g_qhi_w[i0 + 8 * (DK / 2) + 4];
            Ql[ks][0] = g_qlo_w[i0];
            Ql[ks][1] = g_qlo_w[i0 + 8 * (DK / 2)];
            Ql[ks][2] = g_qlo_w[i0 + 4];
            Ql[ks][3] = g_qlo_w[i0 + 8 * (DK / 2) + 4];
        }
    }

    float Oa[8][4];
#pragma unroll
    for (int i = 0; i < 8; i++)
#pragma unroll
        for (int q = 0; q < 4; q++) Oa[i][q] = 0.f;
    float m_a = -1e30f, m_b = -1e30f, l_a = 0.f, l_b = 0.f;

    const int sboff = 2 * fc - 16 * wid - fr + 128;

    auto prefetch = [&](int t) {
        const int slot = t & 1;
        const uint32_t sbase = sb0 + slot * SLOT3_W * 4;
        const int k0 = t * 128;
#pragma unroll
        for (int i = 0; i < 4; i++) {
            int idx = tid + i * 256;
            int r = idx >> 3, jc = idx & 7;
            size_t src = kwbase + (size_t)(k0 + r) * (DK / 2) + jc * 4;
            uint32_t doff = (uint32_t)(r * KSTR + jc * 4) * 4;
            CP16(sbase + S_KH * 4 + doff, g_khi_w + src);
            CP16(sbase + S_KL * 4 + doff, g_klo_w + src);
        }
#pragma unroll
        for (int i = 0; i < 4; i++) {
            int idx = tid + i * 256;
            int d = idx >> 4, jc = idx & 15;
            size_t src = vwbase + (size_t)d * (SEQ / 2) + (k0 >> 1) + jc * 4;
            uint32_t doff = (uint32_t)(d * VSTR + jc * 4) * 4;
            CP16(sbase + S_VH * 4 + doff, g_vthi + src);
            CP16(sbase + S_VL * 4 + doff, g_vtlo + src);
        }
        {
            int gi = 2047 + k0 - q0 + tid - 128;
            gi = gi < 0 ? 0 : (gi > RELN - 1 ? RELN - 1 : gi);
            float bv = g_bias[h * RELN + gi];
            SW3[slot * SLOT3_W + S_SB + tid] = __float_as_uint(bv);
        }
    };

    prefetch(0);
    CP_COMMIT();

    for (int t = 0; t < SEQ / 128; t++) {
        CP_WAIT(0);
        __syncthreads();
        if (t < SEQ / 128 - 1) {
            prefetch(t + 1);
            CP_COMMIT();
        }

        const uint32_t sws = sb0 + (t & 1) * SLOT3_W * 4;
        const float* Sb = (const float*)(SW3 + (t & 1) * SLOT3_W + S_SB);

        // ---- phase 1: S = Q K^T (ldmatrix pairs, 3-term split) ----
        float sc[16][4];
#pragma unroll
        for (int nf = 0; nf < 16; nf++)
#pragma unroll
            for (int q = 0; q < 4; q++) sc[nf][q] = 0.f;

#pragma unroll
        for (int ks = 0; ks < 4; ks++) {
            const int kw = ks * 8 + bcol_l;
#pragma unroll
            for (int j = 0; j < 8; j++) {
                uint32_t kd = sws + (uint32_t)(S_KH + (j * 16 + brow_l) * KSTR + kw) * 4;
                uint32_t bf0[2], bf1[2];
                LDSM_X4(bf0[0], bf0[1], bf1[0], bf1[1], kd);
                mma_bf16(sc[2 * j],     Qh[ks], bf0);
                mma_bf16(sc[2 * j + 1], Qh[ks], bf1);
                mma_bf16(sc[2 * j],     Ql[ks], bf0);
                mma_bf16(sc[2 * j + 1], Ql[ks], bf1);
                LDSM_X4(bf0[0], bf0[1], bf1[0], bf1[1],
                        kd + (S_KL - S_KH) * 4);
                mma_bf16(sc[2 * j],     Qh[ks], bf0);
                mma_bf16(sc[2 * j + 1], Qh[ks], bf1);
            }
        }

        // ---- bias add ----
        float pb0 = Sb[sboff - 8], pb1 = Sb[sboff - 7];
#pragma unroll
        for (int nf = 0; nf < 16; nf++) {
            float b0 = Sb[sboff + 8 * nf];
            float b1 = Sb[sboff + 8 * nf + 1];
            sc[nf][0] += b0;
            sc[nf][1] += b1;
            sc[nf][2] += pb0;
            sc[nf][3] += pb1;
            pb0 = b0; pb1 = b1;
        }

        // ---- online softmax ----
        float mxa = -1e30f, mxb = -1e30f;
#pragma unroll
        for (int nf = 0; nf < 16; nf++) {
            mxa = fmaxf(mxa, fmaxf(sc[nf][0], sc[nf][1]));
            mxb = fmaxf(mxb, fmaxf(sc[nf][2], sc[nf][3]));
        }
        mxa = fmaxf(mxa, __shfl_xor_sync(0xffffffffu, mxa, 1));
        mxa = fmaxf(mxa, __shfl_xor_sync(0xffffffffu, mxa, 2));
        mxb = fmaxf(mxb, __shfl_xor_sync(0xffffffffu, mxb, 1));
        mxb = fmaxf(mxb, __shfl_xor_sync(0xffffffffu, mxb, 2));
        float mna = fmaxf(m_a, mxa), mnb = fmaxf(m_b, mxb);
        float ca = __expf(m_a - mna), cb = __expf(m_b - mnb);
        float sa = 0.f, sb2 = 0.f;
#pragma unroll
        for (int nf = 0; nf < 16; nf++) {
            sc[nf][0] = __expf(sc[nf][0] - mna);
            sc[nf][1] = __expf(sc[nf][1] - mna);
            sc[nf][2] = __expf(sc[nf][2] - mnb);
            sc[nf][3] = __expf(sc[nf][3] - mnb);
            sa  += sc[nf][0] + sc[nf][1];
            sb2 += sc[nf][2] + sc[nf][3];
        }
        sa  += __shfl_xor_sync(0xffffffffu, sa, 1);
        sa  += __shfl_xor_sync(0xffffffffu, sa, 2);
        sb2 += __shfl_xor_sync(0xffffffffu, sb2, 1);
        sb2 += __shfl_xor_sync(0xffffffffu, sb2, 2);
        l_a = l_a * ca + sa;
        l_b = l_b * cb + sb2;
        m_a = mna; m_b = mnb;

#pragma unroll
        for (int i = 0; i < 8; i++) {
            Oa[i][0] *= ca; Oa[i][1] *= ca;
            Oa[i][2] *= cb; Oa[i][3] *= cb;
        }

        // ---- phase 2: O += P V (ldmatrix V pairs) ----
#pragma unroll
        for (int ks2 = 0; ks2 < 8; ks2++) {
            uint32_t Ph[4], Pl[4];
            pack_hilo(sc[2*ks2][0],   sc[2*ks2][1],   Ph[0], Pl[0]);
            pack_hilo(sc[2*ks2][2],   sc[2*ks2][3],   Ph[1], Pl[1]);
            pack_hilo(sc[2*ks2+1][0], sc[2*ks2+1][1], Ph[2], Pl[2]);
            pack_hilo(sc[2*ks2+1][2], sc[2*ks2+1][3], Ph[3], Pl[3]);
            const int kw2 = ks2 * 8 + bcol_l;
#pragma unroll
            for (int j = 0; j < 4; j++) {
                uint32_t vd = sws + (uint32_t)(S_VH + (j * 16 + brow_l) * VSTR + kw2) * 4;
                uint32_t bf0[2], bf1[2];
                LDSM_X4(bf0[0], bf0[1], bf1[0], bf1[1], vd);
                mma_bf16(Oa[2 * j],     Ph, bf0);
                mma_bf16(Oa[2 * j + 1], Ph, bf1);
                mma_bf16(Oa[2 * j],     Pl, bf0);
                mma_bf16(Oa[2 * j + 1], Pl, bf1);
                LDSM_X4(bf0[0], bf0[1], bf1[0], bf1[1],
                        vd + (S_VL - S_VH) * 4);
                mma_bf16(Oa[2 * j],     Ph, bf0);
                mma_bf16(Oa[2 * j + 1], Ph, bf1);
            }
        }
    }

    // ---- epilogue: write hi/lo bf16 straight into g_xhi/g_xlo --------------
    float inva = 1.0f / l_a, invb = 1.0f / l_b;
    int ra = q0 + 16 * wid + fr;
#pragma unroll
    for (int nf2 = 0; nf2 < 8; nf2++) {
        int d = nf2 * 8 + 2 * fc;
        size_t ia = (size_t)(b * SEQ + ra) * DM + h * DK + d;
        size_t ib = ia + (size_t)8 * DM;
        uint32_t hw, lw;
        pack_hilo(Oa[nf2][0] * inva, Oa[nf2][1] * inva, hw, lw);
        *(uint32_t*)&g_xhi[ia] = hw;
        *(uint32_t*)&g_xlo[ia] = lw;
        pack_hilo(Oa[nf2][2] * invb, Oa[nf2][3] * invb, hw, lw);
        *(uint32_t*)&g_xhi[ib] = hw;
        *(uint32_t*)&g_xlo[ib] = lw;
    }
}

// ---------------- launch ----------------------------------------------------
extern "C" void kernel_launch(void* const* d_in, const int* in_sizes, int n_in,
                              void* d_out, int out_size) {
    const float* X   = (const float*)d_in[0];
    const float* Wq  = (const float*)d_in[1];
    const float* Wk  = (const float*)d_in[2];
    const float* Wv  = (const float*)d_in[3];
    const float* Wo  = (const float*)d_in[4];
    const float* tbl = (const float*)d_in[5];
    float* out = (float*)d_out;

    cudaFuncSetAttribute(attn_mma,
                         cudaFuncAttributeMaxDynamicSharedMemorySize,
                         ATTN3_BYTES);
    cudaFuncSetAttribute(gemm_mma,
                         cudaFuncAttributeMaxDynamicSharedMemorySize,
                         GEMM_SMEM_BYTES);

    bias_kernel<<<(RELN + 255) / 256, 256>>>(tbl);

    xcvt<<<(MROWS * DM / 4 + 255) / 256, 256>>>(X, MROWS * DM / 4);
    dim3 gw(DM / 32, DM / 32, 4);
    wt_cvt<<<gw, dim3(32, 8)>>>(Wq, Wk, Wv, Wo);

    dim3 g1(DM / 128, MROWS / 128, 3);
    gemm_mma<<<g1, 256, GEMM_SMEM_BYTES>>>(0, 0, nullptr);

    dim3 g2(SEQ / 128, BSZ * NH);
    attn_mma<<<g2, 256, ATTN3_BYTES>>>();

    dim3 g3(DM / 128, MROWS / 128, 1);
    gemm_mma<<<g3, 256, GEMM_SMEM_BYTES>>>(3, 1, out);
}